// round 1
// baseline (speedup 1.0000x reference)
#include <cuda_runtime.h>
#include <cstddef>

// ---------------------------------------------------------------------------
// Problem constants
// ---------------------------------------------------------------------------
#define NROWS   100352            // 32 * 56 * 56 tokens
#define DIMC    256
#define NWIN    2048              // 32 * 64 windows
#define NTOK    49
#define SCALE_Q 0.17677669529663689f   // 32^-0.5

// ---------------------------------------------------------------------------
// Scratch (static __device__ arrays; allocation is forbidden)
// ---------------------------------------------------------------------------
__device__ float g_ywin[100352 * 256];   // LN1(x), window-partitioned order
__device__ float g_qkv [100352 * 768];   // qkv projection
__device__ float g_attn[100352 * 256];   // attention output (window order)
__device__ float g_x1  [100352 * 256];   // shortcut + proj (x-order)
__device__ float g_h2  [100352 * 256];   // LN2(x1)
__device__ float g_act [100352 * 1024];  // gelu(mlp1)

// ---------------------------------------------------------------------------
// window-order row  <->  x-order row mapping (shift = 3, 8x8 windows of 7x7)
// Same map is used for the forward gather (LN1) and the reverse scatter (proj).
// ---------------------------------------------------------------------------
__device__ __forceinline__ int win_to_x_row(int m) {
    int w  = m / 49;
    int t  = m - w * 49;
    int b  = w >> 6;
    int wi = w & 63;
    int tr = t / 7;
    int tc = t - tr * 7;
    int gr = ((wi >> 3) * 7) + tr;
    int gc = ((wi & 7) * 7) + tc;
    int r = gr + 3; if (r >= 56) r -= 56;
    int c = gc + 3; if (c >= 56) c -= 56;
    return b * 3136 + r * 56 + c;
}

__device__ __forceinline__ float gelu_tanh(float x) {
    float x3 = x * x * x;
    return 0.5f * x * (1.0f + tanhf(0.7978845608028654f * (x + 0.044715f * x3)));
}

// ---------------------------------------------------------------------------
// LayerNorm: one warp per 256-wide row, float4 + shuffle reductions.
// GATHER=true : out[m] = LN(in[win_to_x_row(m)])   (LN1 + shift + partition)
// GATHER=false: out[m] = LN(in[m])                 (LN2)
// ---------------------------------------------------------------------------
template <bool GATHER>
__global__ void __launch_bounds__(256) ln_kernel(const float* __restrict__ in,
                                                 const float* __restrict__ gamma,
                                                 const float* __restrict__ beta,
                                                 float* __restrict__ out) {
    int gw   = (blockIdx.x * blockDim.x + threadIdx.x) >> 5;
    int lane = threadIdx.x & 31;
    if (gw >= NROWS) return;
    int src = GATHER ? win_to_x_row(gw) : gw;

    const float4* row = (const float4*)(in + (size_t)src * DIMC);
    float4 v0 = row[lane];
    float4 v1 = row[lane + 32];

    float s  = v0.x + v0.y + v0.z + v0.w + v1.x + v1.y + v1.z + v1.w;
    float ss = v0.x*v0.x + v0.y*v0.y + v0.z*v0.z + v0.w*v0.w
             + v1.x*v1.x + v1.y*v1.y + v1.z*v1.z + v1.w*v1.w;
#pragma unroll
    for (int o = 16; o; o >>= 1) {
        s  += __shfl_xor_sync(0xffffffffu, s,  o);
        ss += __shfl_xor_sync(0xffffffffu, ss, o);
    }
    float mu  = s * (1.0f / 256.0f);
    float inv = rsqrtf(ss * (1.0f / 256.0f) - mu * mu + 1e-5f);

    float4 g0 = ((const float4*)gamma)[lane];
    float4 g1 = ((const float4*)gamma)[lane + 32];
    float4 b0 = ((const float4*)beta)[lane];
    float4 b1 = ((const float4*)beta)[lane + 32];

    float4 o0, o1;
    o0.x = (v0.x - mu) * inv * g0.x + b0.x;
    o0.y = (v0.y - mu) * inv * g0.y + b0.y;
    o0.z = (v0.z - mu) * inv * g0.z + b0.z;
    o0.w = (v0.w - mu) * inv * g0.w + b0.w;
    o1.x = (v1.x - mu) * inv * g1.x + b1.x;
    o1.y = (v1.y - mu) * inv * g1.y + b1.y;
    o1.z = (v1.z - mu) * inv * g1.z + b1.z;
    o1.w = (v1.w - mu) * inv * g1.w + b1.w;

    float4* orow = (float4*)(out + (size_t)gw * DIMC);
    orow[lane]      = o0;
    orow[lane + 32] = o1;
}

// ---------------------------------------------------------------------------
// Tiled SGEMM: C[M,N] = A[M,K] @ B[K,N] (+ epilogues)
// BM=BN=128, BK=16, 256 threads, 8x8 per-thread tile.
// All M/N/K are exact tile multiples here -> no bounds checks.
// ---------------------------------------------------------------------------
#define EPI_BIAS 0   // C = acc + bias
#define EPI_GELU 1   // C = gelu(acc + bias)
#define EPI_PROJ 2   // C[remap(row)] = acc + bias + res[remap(row)]   (N==256)
#define EPI_MLP2 3   // C[row] = acc + bias + res[row]

template <int EPI>
__global__ void __launch_bounds__(256) gemm_kernel(const float* __restrict__ A,
                                                   const float* __restrict__ B,
                                                   const float* __restrict__ bias,
                                                   float* __restrict__ C,
                                                   const float* __restrict__ res,
                                                   int N, int K) {
    __shared__ float As[16][129];   // +1 pad: conflict-free transposed stores
    __shared__ float Bs[16][128];

    const int tid = threadIdx.x;
    const int bm  = blockIdx.x * 128;
    const int bn  = blockIdx.y * 128;
    const int tx  = tid & 15;
    const int ty  = tid >> 4;

    float acc[8][8] = {};

    for (int k0 = 0; k0 < K; k0 += 16) {
#pragma unroll
        for (int it = 0; it < 2; it++) {
            int s = tid + it * 256;
            int r = s >> 2, c = (s & 3) << 2;
            float4 a = *(const float4*)(A + (size_t)(bm + r) * K + k0 + c);
            As[c + 0][r] = a.x;
            As[c + 1][r] = a.y;
            As[c + 2][r] = a.z;
            As[c + 3][r] = a.w;
        }
#pragma unroll
        for (int it = 0; it < 2; it++) {
            int s = tid + it * 256;
            int kk = s >> 5, c = (s & 31) << 2;
            *(float4*)(&Bs[kk][c]) = *(const float4*)(B + (size_t)(k0 + kk) * N + bn + c);
        }
        __syncthreads();
#pragma unroll
        for (int kk = 0; kk < 16; kk++) {
            float ra[8], rb[8];
#pragma unroll
            for (int i = 0; i < 8; i++) ra[i] = As[kk][ty * 8 + i];
#pragma unroll
            for (int j = 0; j < 8; j++) rb[j] = Bs[kk][tx * 8 + j];
#pragma unroll
            for (int i = 0; i < 8; i++)
#pragma unroll
                for (int j = 0; j < 8; j++) acc[i][j] = fmaf(ra[i], rb[j], acc[i][j]);
        }
        __syncthreads();
    }

    float bv[8];
#pragma unroll
    for (int j = 0; j < 8; j++) bv[j] = bias[bn + tx * 8 + j];

#pragma unroll
    for (int i = 0; i < 8; i++) {
        int row = bm + ty * 8 + i;
        int col = bn + tx * 8;
        float v[8];
#pragma unroll
        for (int j = 0; j < 8; j++) v[j] = acc[i][j] + bv[j];

        if (EPI == EPI_GELU) {
#pragma unroll
            for (int j = 0; j < 8; j++) v[j] = gelu_tanh(v[j]);
        }

        size_t off;
        if (EPI == EPI_PROJ) {
            int r = win_to_x_row(row);
            off = (size_t)r * N + col;
#pragma unroll
            for (int j = 0; j < 8; j++) v[j] += res[off + j];
        } else {
            off = (size_t)row * N + col;
            if (EPI == EPI_MLP2) {
#pragma unroll
                for (int j = 0; j < 8; j++) v[j] += res[off + j];
            }
        }
        float4 w0 = {v[0], v[1], v[2], v[3]};
        float4 w1 = {v[4], v[5], v[6], v[7]};
        *(float4*)(C + off)     = w0;
        *(float4*)(C + off + 4) = w1;
    }
}

// ---------------------------------------------------------------------------
// Windowed attention: one block per (window, head). 64 threads.
// Thread i < 49 owns query row i. K/V/Q staged through smem (reads are
// warp-broadcast). Relative-position bias gathered per-head into smem; the
// shift mask is computed analytically from region labels (no mask tensor).
// ---------------------------------------------------------------------------
__global__ void __launch_bounds__(64) attn_kernel(const float* __restrict__ qkv,
                                                  const float* __restrict__ bias_table,
                                                  float* __restrict__ out) {
    const int w     = blockIdx.x >> 3;
    const int h     = blockIdx.x & 7;
    const int wbase = w * 49;
    const int wi    = w & 63;
    const int wr0   = (wi >> 3) * 7;
    const int wc0   = (wi & 7) * 7;

    __shared__ float ks[49][32];
    __shared__ float vs[49][32];
    __shared__ float qs[49][33];   // pad: per-thread row reads conflict-free
    __shared__ float bias_s[169];
    __shared__ int   reg_s[49];

    const int tid = threadIdx.x;

    for (int idx = tid; idx < 49 * 32; idx += 64) {
        int j = idx >> 5, d = idx & 31;
        size_t base = (size_t)(wbase + j) * 768 + h * 32 + d;
        qs[j][d] = qkv[base] * SCALE_Q;
        ks[j][d] = qkv[base + 256];
        vs[j][d] = qkv[base + 512];
    }
    for (int idx = tid; idx < 169; idx += 64) bias_s[idx] = bias_table[idx * 8 + h];
    for (int idx = tid; idx < 49; idx += 64) {
        int tr = idx / 7, tc = idx - tr * 7;
        int gr = wr0 + tr, gc = wc0 + tc;
        int rh = (gr < 49) ? 0 : ((gr < 53) ? 1 : 2);
        int rc = (gc < 49) ? 0 : ((gc < 53) ? 1 : 2);
        reg_s[idx] = rh * 3 + rc;
    }
    __syncthreads();

    if (tid < 49) {
        const int i  = tid;
        const int ri = i / 7, ci = i - (i / 7) * 7;
        const int regi = reg_s[i];

        float q[32];
#pragma unroll
        for (int d = 0; d < 32; d++) q[d] = qs[i][d];

        float sarr[49];
        float mx = -1e30f;
#pragma unroll
        for (int j = 0; j < 49; j++) {
            float a = 0.0f;
#pragma unroll
            for (int d = 0; d < 32; d++) a = fmaf(q[d], ks[j][d], a);
            int rj = j / 7, cj = j - (j / 7) * 7;
            a += bias_s[(ri - rj + 6) + 13 * (ci - cj + 6)];
            if (reg_s[j] != regi) a -= 100.0f;
            sarr[j] = a;
            mx = fmaxf(mx, a);
        }
        float denom = 0.0f;
#pragma unroll
        for (int j = 0; j < 49; j++) {
            sarr[j] = __expf(sarr[j] - mx);
            denom += sarr[j];
        }
        float dinv = 1.0f / denom;

        float o[32] = {};
#pragma unroll
        for (int j = 0; j < 49; j++) {
            float p = sarr[j] * dinv;
#pragma unroll
            for (int d = 0; d < 32; d++) o[d] = fmaf(p, vs[j][d], o[d]);
        }

        float* op = out + (size_t)(wbase + i) * 256 + h * 32;
#pragma unroll
        for (int d = 0; d < 32; d += 4) {
            float4 t = {o[d], o[d + 1], o[d + 2], o[d + 3]};
            *(float4*)(op + d) = t;
        }
    }
}

// ---------------------------------------------------------------------------
// Host launcher (graph-capturable: kernel launches only)
// ---------------------------------------------------------------------------
extern "C" void kernel_launch(void* const* d_in, const int* in_sizes, int n_in,
                              void* d_out, int out_size) {
    (void)in_sizes; (void)n_in; (void)out_size;

    const float* x          = (const float*)d_in[0];
    const float* n1g        = (const float*)d_in[1];
    const float* n1b        = (const float*)d_in[2];
    const float* qkv_w      = (const float*)d_in[3];
    const float* qkv_b      = (const float*)d_in[4];
    const float* proj_w     = (const float*)d_in[5];
    const float* proj_b     = (const float*)d_in[6];
    const float* bias_table = (const float*)d_in[7];
    const float* n2g        = (const float*)d_in[8];
    const float* n2b        = (const float*)d_in[9];
    const float* w1         = (const float*)d_in[10];
    const float* b1         = (const float*)d_in[11];
    const float* w2         = (const float*)d_in[12];
    const float* b2         = (const float*)d_in[13];
    float* out = (float*)d_out;

    float *ywin, *qkvb, *attn, *x1, *h2, *act;
    cudaGetSymbolAddress((void**)&ywin, g_ywin);
    cudaGetSymbolAddress((void**)&qkvb, g_qkv);
    cudaGetSymbolAddress((void**)&attn, g_attn);
    cudaGetSymbolAddress((void**)&x1,   g_x1);
    cudaGetSymbolAddress((void**)&h2,   g_h2);
    cudaGetSymbolAddress((void**)&act,  g_act);

    const int lnBlocks = NROWS / 8;   // 8 warps (rows) per 256-thread block

    // 1) LN1 + cyclic shift + window partition
    ln_kernel<true><<<lnBlocks, 256>>>(x, n1g, n1b, ywin);
    // 2) QKV projection: [100352,256] @ [256,768]
    gemm_kernel<EPI_BIAS><<<dim3(784, 6), 256>>>(ywin, qkv_w, qkv_b, qkvb, nullptr, 768, 256);
    // 3) windowed attention (bias + shift mask + softmax + @V)
    attn_kernel<<<NWIN * 8, 64>>>(qkvb, bias_table, attn);
    // 4) proj + window-reverse + un-shift + residual -> x1
    gemm_kernel<EPI_PROJ><<<dim3(784, 2), 256>>>(attn, proj_w, proj_b, x1, x, 256, 256);
    // 5) LN2
    ln_kernel<false><<<lnBlocks, 256>>>(x1, n2g, n2b, h2);
    // 6) MLP up + GELU: [100352,256] @ [256,1024]
    gemm_kernel<EPI_GELU><<<dim3(784, 8), 256>>>(h2, w1, b1, act, nullptr, 1024, 256);
    // 7) MLP down + residual -> d_out: [100352,1024] @ [1024,256]
    gemm_kernel<EPI_MLP2><<<dim3(784, 2), 256>>>(act, w2, b2, out, x1, 256, 1024);
}

// round 2
// speedup vs baseline: 2.2976x; 2.2976x over previous
#include <cuda_runtime.h>
#include <cstddef>
#include <cstdint>

// ---------------------------------------------------------------------------
// Problem constants
// ---------------------------------------------------------------------------
#define NROWS   100352            // 32 * 56 * 56 tokens
#define DIMC    256
#define NWIN    2048              // 32 * 64 windows
#define SCALE_Q 0.17677669529663689f   // 32^-0.5

// ---------------------------------------------------------------------------
// Scratch (static __device__ arrays; allocation is forbidden)
// ---------------------------------------------------------------------------
__device__ float g_ywin[100352 * 256];   // LN1(x), window-partitioned order
__device__ float g_qkv [100352 * 768];   // qkv projection
__device__ float g_attn[100352 * 256];   // attention output (window order)
__device__ float g_x1  [100352 * 256];   // shortcut + proj (x-order)
__device__ float g_h2  [100352 * 256];   // LN2(x1)
__device__ float g_act [100352 * 1024];  // gelu(mlp1)

// ---------------------------------------------------------------------------
// window-order row <-> x-order row mapping (shift = 3, 8x8 windows of 7x7)
// ---------------------------------------------------------------------------
__device__ __forceinline__ int win_to_x_row(int m) {
    int w  = m / 49;
    int t  = m - w * 49;
    int b  = w >> 6;
    int wi = w & 63;
    int tr = t / 7;
    int tc = t - tr * 7;
    int gr = ((wi >> 3) * 7) + tr;
    int gc = ((wi & 7) * 7) + tc;
    int r = gr + 3; if (r >= 56) r -= 56;
    int c = gc + 3; if (c >= 56) c -= 56;
    return b * 3136 + r * 56 + c;
}

__device__ __forceinline__ float gelu_tanh(float x) {
    float x3 = x * x * x;
    return 0.5f * x * (1.0f + tanhf(0.7978845608028654f * (x + 0.044715f * x3)));
}

// fp32 -> tf32 (round-to-nearest), result as fp32 bit pattern
__device__ __forceinline__ float f2tf(float x) {
    uint32_t r;
    asm("cvt.rna.tf32.f32 %0, %1;" : "=r"(r) : "f"(x));
    return __uint_as_float(r);
}

// ---------------------------------------------------------------------------
// LayerNorm: one warp per 256-wide row.
// GATHER=true : out[m] = LN(in[win_to_x_row(m)])   (LN1 + shift + partition)
// GATHER=false: out[m] = LN(in[m])                 (LN2)
// ---------------------------------------------------------------------------
template <bool GATHER>
__global__ void __launch_bounds__(256) ln_kernel(const float* __restrict__ in,
                                                 const float* __restrict__ gamma,
                                                 const float* __restrict__ beta,
                                                 float* __restrict__ out) {
    int gw   = (blockIdx.x * blockDim.x + threadIdx.x) >> 5;
    int lane = threadIdx.x & 31;
    if (gw >= NROWS) return;
    int src = GATHER ? win_to_x_row(gw) : gw;

    const float4* row = (const float4*)(in + (size_t)src * DIMC);
    float4 v0 = row[lane];
    float4 v1 = row[lane + 32];

    float s  = v0.x + v0.y + v0.z + v0.w + v1.x + v1.y + v1.z + v1.w;
    float ss = v0.x*v0.x + v0.y*v0.y + v0.z*v0.z + v0.w*v0.w
             + v1.x*v1.x + v1.y*v1.y + v1.z*v1.z + v1.w*v1.w;
#pragma unroll
    for (int o = 16; o; o >>= 1) {
        s  += __shfl_xor_sync(0xffffffffu, s,  o);
        ss += __shfl_xor_sync(0xffffffffu, ss, o);
    }
    float mu  = s * (1.0f / 256.0f);
    float inv = rsqrtf(ss * (1.0f / 256.0f) - mu * mu + 1e-5f);

    float4 g0 = ((const float4*)gamma)[lane];
    float4 g1 = ((const float4*)gamma)[lane + 32];
    float4 b0 = ((const float4*)beta)[lane];
    float4 b1 = ((const float4*)beta)[lane + 32];

    float4 o0, o1;
    o0.x = (v0.x - mu) * inv * g0.x + b0.x;
    o0.y = (v0.y - mu) * inv * g0.y + b0.y;
    o0.z = (v0.z - mu) * inv * g0.z + b0.z;
    o0.w = (v0.w - mu) * inv * g0.w + b0.w;
    o1.x = (v1.x - mu) * inv * g1.x + b1.x;
    o1.y = (v1.y - mu) * inv * g1.y + b1.y;
    o1.z = (v1.z - mu) * inv * g1.z + b1.z;
    o1.w = (v1.w - mu) * inv * g1.w + b1.w;

    float4* orow = (float4*)(out + (size_t)gw * DIMC);
    orow[lane]      = o0;
    orow[lane + 32] = o1;
}

// ---------------------------------------------------------------------------
// Tensor-core GEMM (tf32 mma.sync, fp32 accumulate):
//   C[M,N] = A[M,K] @ B[K,N] (+ epilogues)
// BM=BN=128, BK=16, 256 threads = 8 warps (4 x 2), warp tile 32x64.
// Double-buffered smem; A stored [m][k] stride 20, B stored [k][n] stride 136
// (both pads make the mma fragment loads hit 32 distinct banks).
// All M/N/K are exact tile multiples -> no bounds checks.
// ---------------------------------------------------------------------------
#define EPI_BIAS 0   // C = acc + bias
#define EPI_GELU 1   // C = gelu(acc + bias)
#define EPI_PROJ 2   // C[remap(row)] = acc + bias + res[remap(row)]
#define EPI_MLP2 3   // C[row] = acc + bias + res[row]

#define A_STRIDE 20
#define B_STRIDE 136

__device__ __forceinline__ void mma_tf32(float c[4],
                                         const uint32_t a[4],
                                         uint32_t b0, uint32_t b1) {
    asm volatile(
        "mma.sync.aligned.m16n8k8.row.col.f32.tf32.tf32.f32 "
        "{%0,%1,%2,%3}, {%4,%5,%6,%7}, {%8,%9}, {%0,%1,%2,%3};"
        : "+f"(c[0]), "+f"(c[1]), "+f"(c[2]), "+f"(c[3])
        : "r"(a[0]), "r"(a[1]), "r"(a[2]), "r"(a[3]), "r"(b0), "r"(b1));
}

template <int EPI>
__global__ void __launch_bounds__(256) gemm_tc(const float* __restrict__ A,
                                               const float* __restrict__ B,
                                               const float* __restrict__ bias,
                                               float* __restrict__ C,
                                               const float* __restrict__ res,
                                               int N, int K) {
    __shared__ float As[2][128 * A_STRIDE];
    __shared__ float Bs[2][16 * B_STRIDE];

    const int tid  = threadIdx.x;
    const int lane = tid & 31;
    const int wid  = tid >> 5;
    const int bm   = blockIdx.x * 128;
    const int bn   = blockIdx.y * 128;
    const int wm   = (wid & 3) * 32;    // warp m offset within block tile
    const int wn   = (wid >> 2) * 64;   // warp n offset within block tile

    // global-load assignments
    const int a_r0 = tid >> 2;          // 0..63
    const int a_r1 = a_r0 + 64;
    const int a_c  = (tid & 3) << 2;    // 0,4,8,12
    const int b_k0 = tid >> 5;          // 0..7
    const int b_k1 = b_k0 + 8;
    const int b_c  = (tid & 31) << 2;   // 0..124

    const float* Ab = A + (size_t)bm * K;
    const float* Bb = B + bn;

    float acc[2][8][4] = {};

    float4 va0 = *(const float4*)(Ab + (size_t)a_r0 * K + a_c);
    float4 va1 = *(const float4*)(Ab + (size_t)a_r1 * K + a_c);
    float4 vb0 = *(const float4*)(Bb + (size_t)b_k0 * N + b_c);
    float4 vb1 = *(const float4*)(Bb + (size_t)b_k1 * N + b_c);

    // store tile 0
    {
        float* as = As[0];
        as[a_r0 * A_STRIDE + a_c + 0] = f2tf(va0.x);
        as[a_r0 * A_STRIDE + a_c + 1] = f2tf(va0.y);
        as[a_r0 * A_STRIDE + a_c + 2] = f2tf(va0.z);
        as[a_r0 * A_STRIDE + a_c + 3] = f2tf(va0.w);
        as[a_r1 * A_STRIDE + a_c + 0] = f2tf(va1.x);
        as[a_r1 * A_STRIDE + a_c + 1] = f2tf(va1.y);
        as[a_r1 * A_STRIDE + a_c + 2] = f2tf(va1.z);
        as[a_r1 * A_STRIDE + a_c + 3] = f2tf(va1.w);
        float4 t0 = {f2tf(vb0.x), f2tf(vb0.y), f2tf(vb0.z), f2tf(vb0.w)};
        float4 t1 = {f2tf(vb1.x), f2tf(vb1.y), f2tf(vb1.z), f2tf(vb1.w)};
        *(float4*)(Bs[0] + b_k0 * B_STRIDE + b_c) = t0;
        *(float4*)(Bs[0] + b_k1 * B_STRIDE + b_c) = t1;
    }
    __syncthreads();

    int buf = 0;
    for (int k0 = 0; k0 < K; k0 += 16) {
        const bool more = (k0 + 16) < K;
        if (more) {
            const float* Ak = Ab + k0 + 16;
            const float* Bk = Bb + (size_t)(k0 + 16) * N;
            va0 = *(const float4*)(Ak + (size_t)a_r0 * K + a_c);
            va1 = *(const float4*)(Ak + (size_t)a_r1 * K + a_c);
            vb0 = *(const float4*)(Bk + (size_t)b_k0 * N + b_c);
            vb1 = *(const float4*)(Bk + (size_t)b_k1 * N + b_c);
        }

        const float* as = As[buf];
        const float* bs = Bs[buf];
#pragma unroll
        for (int ks = 0; ks < 16; ks += 8) {
            uint32_t af[2][4];
#pragma unroll
            for (int mi = 0; mi < 2; mi++) {
                const float* ap = as + (wm + mi * 16 + (lane >> 2)) * A_STRIDE
                                     + ks + (lane & 3);
                af[mi][0] = __float_as_uint(ap[0]);
                af[mi][1] = __float_as_uint(ap[8 * A_STRIDE]);
                af[mi][2] = __float_as_uint(ap[4]);
                af[mi][3] = __float_as_uint(ap[8 * A_STRIDE + 4]);
            }
#pragma unroll
            for (int ni = 0; ni < 8; ni++) {
                const float* bp = bs + (ks + (lane & 3)) * B_STRIDE
                                     + wn + ni * 8 + (lane >> 2);
                uint32_t b0 = __float_as_uint(bp[0]);
                uint32_t b1 = __float_as_uint(bp[4 * B_STRIDE]);
                mma_tf32(acc[0][ni], af[0], b0, b1);
                mma_tf32(acc[1][ni], af[1], b0, b1);
            }
        }

        if (more) {
            float* asn = As[buf ^ 1];
            float* bsn = Bs[buf ^ 1];
            asn[a_r0 * A_STRIDE + a_c + 0] = f2tf(va0.x);
            asn[a_r0 * A_STRIDE + a_c + 1] = f2tf(va0.y);
            asn[a_r0 * A_STRIDE + a_c + 2] = f2tf(va0.z);
            asn[a_r0 * A_STRIDE + a_c + 3] = f2tf(va0.w);
            asn[a_r1 * A_STRIDE + a_c + 0] = f2tf(va1.x);
            asn[a_r1 * A_STRIDE + a_c + 1] = f2tf(va1.y);
            asn[a_r1 * A_STRIDE + a_c + 2] = f2tf(va1.z);
            asn[a_r1 * A_STRIDE + a_c + 3] = f2tf(va1.w);
            float4 t0 = {f2tf(vb0.x), f2tf(vb0.y), f2tf(vb0.z), f2tf(vb0.w)};
            float4 t1 = {f2tf(vb1.x), f2tf(vb1.y), f2tf(vb1.z), f2tf(vb1.w)};
            *(float4*)(bsn + b_k0 * B_STRIDE + b_c) = t0;
            *(float4*)(bsn + b_k1 * B_STRIDE + b_c) = t1;
        }
        __syncthreads();
        buf ^= 1;
    }

    // ---------------- epilogue ----------------
    float bv0[8], bv1[8];
#pragma unroll
    for (int ni = 0; ni < 8; ni++) {
        int c = bn + wn + ni * 8 + 2 * (lane & 3);
        bv0[ni] = bias[c];
        bv1[ni] = bias[c + 1];
    }

#pragma unroll
    for (int mi = 0; mi < 2; mi++) {
#pragma unroll
        for (int half = 0; half < 2; half++) {
            int r = bm + wm + mi * 16 + (lane >> 2) + half * 8;
            size_t rowoff;
            if (EPI == EPI_PROJ) rowoff = (size_t)win_to_x_row(r) * N;
            else                 rowoff = (size_t)r * N;
#pragma unroll
            for (int ni = 0; ni < 8; ni++) {
                int c = bn + wn + ni * 8 + 2 * (lane & 3);
                float v0 = acc[mi][ni][half * 2 + 0] + bv0[ni];
                float v1 = acc[mi][ni][half * 2 + 1] + bv1[ni];
                if (EPI == EPI_GELU) { v0 = gelu_tanh(v0); v1 = gelu_tanh(v1); }
                if (EPI == EPI_PROJ || EPI == EPI_MLP2) {
                    float2 rr = *(const float2*)(res + rowoff + c);
                    v0 += rr.x; v1 += rr.y;
                }
                float2 w = {v0, v1};
                *(float2*)(C + rowoff + c) = w;
            }
        }
    }
}

// ---------------------------------------------------------------------------
// Windowed attention: one block per (window, head). 64 threads.
// ---------------------------------------------------------------------------
__global__ void __launch_bounds__(64) attn_kernel(const float* __restrict__ qkv,
                                                  const float* __restrict__ bias_table,
                                                  float* __restrict__ out) {
    const int w     = blockIdx.x >> 3;
    const int h     = blockIdx.x & 7;
    const int wbase = w * 49;
    const int wi    = w & 63;
    const int wr0   = (wi >> 3) * 7;
    const int wc0   = (wi & 7) * 7;

    __shared__ float ks[49][32];
    __shared__ float vs[49][32];
    __shared__ float qs[49][33];
    __shared__ float bias_s[169];
    __shared__ int   reg_s[49];

    const int tid = threadIdx.x;

    for (int idx = tid; idx < 49 * 32; idx += 64) {
        int j = idx >> 5, d = idx & 31;
        size_t base = (size_t)(wbase + j) * 768 + h * 32 + d;
        qs[j][d] = qkv[base] * SCALE_Q;
        ks[j][d] = qkv[base + 256];
        vs[j][d] = qkv[base + 512];
    }
    for (int idx = tid; idx < 169; idx += 64) bias_s[idx] = bias_table[idx * 8 + h];
    for (int idx = tid; idx < 49; idx += 64) {
        int tr = idx / 7, tc = idx - tr * 7;
        int gr = wr0 + tr, gc = wc0 + tc;
        int rh = (gr < 49) ? 0 : ((gr < 53) ? 1 : 2);
        int rc = (gc < 49) ? 0 : ((gc < 53) ? 1 : 2);
        reg_s[idx] = rh * 3 + rc;
    }
    __syncthreads();

    if (tid < 49) {
        const int i  = tid;
        const int ri = i / 7, ci = i - (i / 7) * 7;
        const int regi = reg_s[i];

        float q[32];
#pragma unroll
        for (int d = 0; d < 32; d++) q[d] = qs[i][d];

        float sarr[49];
        float mx = -1e30f;
#pragma unroll
        for (int j = 0; j < 49; j++) {
            float a = 0.0f;
#pragma unroll
            for (int d = 0; d < 32; d++) a = fmaf(q[d], ks[j][d], a);
            int rj = j / 7, cj = j - (j / 7) * 7;
            a += bias_s[(ri - rj + 6) + 13 * (ci - cj + 6)];
            if (reg_s[j] != regi) a -= 100.0f;
            sarr[j] = a;
            mx = fmaxf(mx, a);
        }
        float denom = 0.0f;
#pragma unroll
        for (int j = 0; j < 49; j++) {
            sarr[j] = __expf(sarr[j] - mx);
            denom += sarr[j];
        }
        float dinv = 1.0f / denom;

        float o[32] = {};
#pragma unroll
        for (int j = 0; j < 49; j++) {
            float p = sarr[j] * dinv;
#pragma unroll
            for (int d = 0; d < 32; d++) o[d] = fmaf(p, vs[j][d], o[d]);
        }

        float* op = out + (size_t)(wbase + i) * 256 + h * 32;
#pragma unroll
        for (int d = 0; d < 32; d += 4) {
            float4 t = {o[d], o[d + 1], o[d + 2], o[d + 3]};
            *(float4*)(op + d) = t;
        }
    }
}

// ---------------------------------------------------------------------------
// Host launcher (graph-capturable: kernel launches only)
// ---------------------------------------------------------------------------
extern "C" void kernel_launch(void* const* d_in, const int* in_sizes, int n_in,
                              void* d_out, int out_size) {
    (void)in_sizes; (void)n_in; (void)out_size;

    const float* x          = (const float*)d_in[0];
    const float* n1g        = (const float*)d_in[1];
    const float* n1b        = (const float*)d_in[2];
    const float* qkv_w      = (const float*)d_in[3];
    const float* qkv_b      = (const float*)d_in[4];
    const float* proj_w     = (const float*)d_in[5];
    const float* proj_b     = (const float*)d_in[6];
    const float* bias_table = (const float*)d_in[7];
    const float* n2g        = (const float*)d_in[8];
    const float* n2b        = (const float*)d_in[9];
    const float* w1         = (const float*)d_in[10];
    const float* b1         = (const float*)d_in[11];
    const float* w2         = (const float*)d_in[12];
    const float* b2         = (const float*)d_in[13];
    float* out = (float*)d_out;

    float *ywin, *qkvb, *attn, *x1, *h2, *act;
    cudaGetSymbolAddress((void**)&ywin, g_ywin);
    cudaGetSymbolAddress((void**)&qkvb, g_qkv);
    cudaGetSymbolAddress((void**)&attn, g_attn);
    cudaGetSymbolAddress((void**)&x1,   g_x1);
    cudaGetSymbolAddress((void**)&h2,   g_h2);
    cudaGetSymbolAddress((void**)&act,  g_act);

    const int lnBlocks = NROWS / 8;

    // 1) LN1 + cyclic shift + window partition
    ln_kernel<true><<<lnBlocks, 256>>>(x, n1g, n1b, ywin);
    // 2) QKV projection: [100352,256] @ [256,768]
    gemm_tc<EPI_BIAS><<<dim3(784, 6), 256>>>(ywin, qkv_w, qkv_b, qkvb, nullptr, 768, 256);
    // 3) windowed attention (bias + shift mask + softmax + @V)
    attn_kernel<<<NWIN * 8, 64>>>(qkvb, bias_table, attn);
    // 4) proj + window-reverse + un-shift + residual -> x1
    gemm_tc<EPI_PROJ><<<dim3(784, 2), 256>>>(attn, proj_w, proj_b, x1, x, 256, 256);
    // 5) LN2
    ln_kernel<false><<<lnBlocks, 256>>>(x1, n2g, n2b, h2);
    // 6) MLP up + GELU: [100352,256] @ [256,1024]
    gemm_tc<EPI_GELU><<<dim3(784, 8), 256>>>(h2, w1, b1, act, nullptr, 1024, 256);
    // 7) MLP down + residual -> d_out: [100352,1024] @ [1024,256]
    gemm_tc<EPI_MLP2><<<dim3(784, 2), 256>>>(act, w2, b2, out, x1, 256, 1024);
}

// round 3
// speedup vs baseline: 4.0068x; 1.7439x over previous
#include <cuda_runtime.h>
#include <cuda_bf16.h>
#include <cstddef>
#include <cstdint>

// ---------------------------------------------------------------------------
// Problem constants
// ---------------------------------------------------------------------------
#define NROWS   100352            // 32 * 56 * 56 tokens
#define NWIN    2048              // 32 * 64 windows
#define SCALE_Q 0.17677669529663689f   // 32^-0.5

// ---------------------------------------------------------------------------
// Scratch (static __device__ arrays; allocation is forbidden)
// ---------------------------------------------------------------------------
__device__ __align__(16) __nv_bfloat16 g_ywin[100352 * 256];   // LN1 out (win order)
__device__ float                       g_qkv [100352 * 768];   // qkv (fp32 for attn)
__device__ __align__(16) __nv_bfloat16 g_attn[100352 * 256];   // attention out
__device__ float                       g_x1  [100352 * 256];   // shortcut + proj
__device__ __align__(16) __nv_bfloat16 g_h2  [100352 * 256];   // LN2 out
__device__ __align__(16) __nv_bfloat16 g_act [100352 * 1024];  // gelu(mlp1)
__device__ __align__(16) __nv_bfloat16 g_wbf [786432];         // all 4 weights, bf16

#define WOFF_QKV  0
#define WOFF_PROJ 196608
#define WOFF_W1   262144
#define WOFF_W2   524288

// ---------------------------------------------------------------------------
// window-order row <-> x-order row mapping (shift = 3, 8x8 windows of 7x7)
// ---------------------------------------------------------------------------
__device__ __forceinline__ int win_to_x_row(int m) {
    int w  = m / 49;
    int t  = m - w * 49;
    int b  = w >> 6;
    int wi = w & 63;
    int tr = t / 7;
    int tc = t - tr * 7;
    int gr = ((wi >> 3) * 7) + tr;
    int gc = ((wi & 7) * 7) + tc;
    int r = gr + 3; if (r >= 56) r -= 56;
    int c = gc + 3; if (c >= 56) c -= 56;
    return b * 3136 + r * 56 + c;
}

__device__ __forceinline__ float gelu_tanh(float x) {
    float x3 = x * x * x;
    return 0.5f * x * (1.0f + tanhf(0.7978845608028654f * (x + 0.044715f * x3)));
}

__device__ __forceinline__ uint2 pack4_bf16(float4 v) {
    __nv_bfloat162 lo = __floats2bfloat162_rn(v.x, v.y);
    __nv_bfloat162 hi = __floats2bfloat162_rn(v.z, v.w);
    uint2 r;
    r.x = *(uint32_t*)&lo;
    r.y = *(uint32_t*)&hi;
    return r;
}

// ---------------------------------------------------------------------------
// PTX helpers
// ---------------------------------------------------------------------------
__device__ __forceinline__ void ldsm4(uint32_t r[4], const void* p) {
    uint32_t a = (uint32_t)__cvta_generic_to_shared(p);
    asm volatile("ldmatrix.sync.aligned.m8n8.x4.shared.b16 {%0,%1,%2,%3}, [%4];"
                 : "=r"(r[0]), "=r"(r[1]), "=r"(r[2]), "=r"(r[3]) : "r"(a));
}
__device__ __forceinline__ void ldsm4t(uint32_t r[4], const void* p) {
    uint32_t a = (uint32_t)__cvta_generic_to_shared(p);
    asm volatile("ldmatrix.sync.aligned.m8n8.x4.trans.shared.b16 {%0,%1,%2,%3}, [%4];"
                 : "=r"(r[0]), "=r"(r[1]), "=r"(r[2]), "=r"(r[3]) : "r"(a));
}
__device__ __forceinline__ void mma_bf16(float c[4], const uint32_t a[4],
                                         uint32_t b0, uint32_t b1) {
    asm volatile(
        "mma.sync.aligned.m16n8k16.row.col.f32.bf16.bf16.f32 "
        "{%0,%1,%2,%3}, {%4,%5,%6,%7}, {%8,%9}, {%0,%1,%2,%3};"
        : "+f"(c[0]), "+f"(c[1]), "+f"(c[2]), "+f"(c[3])
        : "r"(a[0]), "r"(a[1]), "r"(a[2]), "r"(a[3]), "r"(b0), "r"(b1));
}
__device__ __forceinline__ void cpasync16(void* dst, const void* src) {
    uint32_t d = (uint32_t)__cvta_generic_to_shared(dst);
    asm volatile("cp.async.cg.shared.global [%0], [%1], 16;" :: "r"(d), "l"(src));
}
__device__ __forceinline__ void cp_commit() {
    asm volatile("cp.async.commit_group;");
}
template <int N>
__device__ __forceinline__ void cp_wait() {
    asm volatile("cp.async.wait_group %0;" :: "n"(N));
}

// ---------------------------------------------------------------------------
// Weight conversion: fp32 -> bf16, once per launch (~0.8M elements)
// ---------------------------------------------------------------------------
__global__ void __launch_bounds__(1024) wconv_kernel(const float* __restrict__ qkv_w,
                                                     const float* __restrict__ proj_w,
                                                     const float* __restrict__ w1,
                                                     const float* __restrict__ w2,
                                                     __nv_bfloat16* __restrict__ dst) {
    int i = blockIdx.x * 1024 + threadIdx.x;   // grid = 768
    float v;
    if      (i < WOFF_PROJ) v = qkv_w[i];
    else if (i < WOFF_W1)   v = proj_w[i - WOFF_PROJ];
    else if (i < WOFF_W2)   v = w1[i - WOFF_W1];
    else                    v = w2[i - WOFF_W2];
    dst[i] = __float2bfloat16(v);
}

// ---------------------------------------------------------------------------
// LayerNorm: one warp per 256-wide row, bf16 output.
// GATHER=true : out[m] = LN(in[win_to_x_row(m)])
// ---------------------------------------------------------------------------
template <bool GATHER>
__global__ void __launch_bounds__(256) ln_kernel(const float* __restrict__ in,
                                                 const float* __restrict__ gamma,
                                                 const float* __restrict__ beta,
                                                 __nv_bfloat16* __restrict__ out) {
    int gw   = (blockIdx.x * blockDim.x + threadIdx.x) >> 5;
    int lane = threadIdx.x & 31;
    if (gw >= NROWS) return;
    int src = GATHER ? win_to_x_row(gw) : gw;

    const float4* row = (const float4*)(in + (size_t)src * 256);
    float4 v0 = row[lane];
    float4 v1 = row[lane + 32];

    float s  = v0.x + v0.y + v0.z + v0.w + v1.x + v1.y + v1.z + v1.w;
    float ss = v0.x*v0.x + v0.y*v0.y + v0.z*v0.z + v0.w*v0.w
             + v1.x*v1.x + v1.y*v1.y + v1.z*v1.z + v1.w*v1.w;
#pragma unroll
    for (int o = 16; o; o >>= 1) {
        s  += __shfl_xor_sync(0xffffffffu, s,  o);
        ss += __shfl_xor_sync(0xffffffffu, ss, o);
    }
    float mu  = s * (1.0f / 256.0f);
    float inv = rsqrtf(ss * (1.0f / 256.0f) - mu * mu + 1e-5f);

    float4 g0 = ((const float4*)gamma)[lane];
    float4 g1 = ((const float4*)gamma)[lane + 32];
    float4 b0 = ((const float4*)beta)[lane];
    float4 b1 = ((const float4*)beta)[lane + 32];

    float4 o0, o1;
    o0.x = (v0.x - mu) * inv * g0.x + b0.x;
    o0.y = (v0.y - mu) * inv * g0.y + b0.y;
    o0.z = (v0.z - mu) * inv * g0.z + b0.z;
    o0.w = (v0.w - mu) * inv * g0.w + b0.w;
    o1.x = (v1.x - mu) * inv * g1.x + b1.x;
    o1.y = (v1.y - mu) * inv * g1.y + b1.y;
    o1.z = (v1.z - mu) * inv * g1.z + b1.z;
    o1.w = (v1.w - mu) * inv * g1.w + b1.w;

    uint2* orow = (uint2*)(out + (size_t)gw * 256);
    orow[lane]      = pack4_bf16(o0);
    orow[lane + 32] = pack4_bf16(o1);
}

// ---------------------------------------------------------------------------
// bf16 tensor-core GEMM: C[M,N] = A[M,K] @ B[K,N] (+ epilogues)
// BM=BN=128, BK=32, 256 threads = 8 warps (4m x 2n), warp tile 32x64.
// cp.async double-buffered smem; ldmatrix.x4 fragment loads.
// A smem [m][k] stride 40 bf16, B smem [k][n] stride 136 bf16 (conflict-free).
// All M/N/K exact tile multiples -> no bounds checks.
// ---------------------------------------------------------------------------
#define EPI_BIAS 0
#define EPI_GELU 1
#define EPI_PROJ 2
#define EPI_MLP2 3

#define AS 40
#define BSS 136

template <int EPI, bool OUT_BF16>
__global__ void __launch_bounds__(256) gemm_bf16(const __nv_bfloat16* __restrict__ A,
                                                 const __nv_bfloat16* __restrict__ B,
                                                 const float* __restrict__ bias,
                                                 void* __restrict__ Cout,
                                                 const float* __restrict__ res,
                                                 int N, int K) {
    __shared__ __align__(16) __nv_bfloat16 As[2][128 * AS];
    __shared__ __align__(16) __nv_bfloat16 Bs[2][32 * BSS];

    const int tid  = threadIdx.x;
    const int lane = tid & 31;
    const int wid  = tid >> 5;
    const int bm   = blockIdx.x * 128;
    const int bn   = blockIdx.y * 128;
    const int wm   = (wid & 3) * 32;
    const int wn   = (wid >> 2) * 64;

    const __nv_bfloat16* Ab = A + (size_t)bm * K;
    const __nv_bfloat16* Bb = B + bn;

    float acc[2][8][4] = {};

    // ---- tile loader: 4 x 16B cp.async per thread ----
    auto load_tile = [&](int k0, int buf) {
#pragma unroll
        for (int i = 0; i < 2; i++) {
            int c = tid + i * 256;             // 0..511
            int row = c >> 2, kc = (c & 3) * 8;
            cpasync16(&As[buf][row * AS + kc], Ab + (size_t)row * K + k0 + kc);
        }
#pragma unroll
        for (int i = 0; i < 2; i++) {
            int c = tid + i * 256;
            int k = c >> 4, n = (c & 15) * 8;
            cpasync16(&Bs[buf][k * BSS + n], Bb + (size_t)(k0 + k) * N + n);
        }
        cp_commit();
    };

    load_tile(0, 0);

    int buf = 0;
    for (int k0 = 0; k0 < K; k0 += 32) {
        const bool more = (k0 + 32) < K;
        if (more) { load_tile(k0 + 32, buf ^ 1); cp_wait<1>(); }
        else      { cp_wait<0>(); }
        __syncthreads();

        const __nv_bfloat16* as = As[buf];
        const __nv_bfloat16* bs = Bs[buf];
#pragma unroll
        for (int ks = 0; ks < 32; ks += 16) {
            uint32_t af[2][4];
#pragma unroll
            for (int mi = 0; mi < 2; mi++)
                ldsm4(af[mi], as + (wm + mi * 16 + (lane & 15)) * AS
                                 + ks + (lane >> 4) * 8);
#pragma unroll
            for (int np = 0; np < 4; np++) {
                uint32_t bf[4];
                ldsm4t(bf, bs + (ks + (lane & 7) + ((lane >> 3) & 1) * 8) * BSS
                              + wn + np * 16 + (lane >> 4) * 8);
                mma_bf16(acc[0][np * 2 + 0], af[0], bf[0], bf[1]);
                mma_bf16(acc[1][np * 2 + 0], af[1], bf[0], bf[1]);
                mma_bf16(acc[0][np * 2 + 1], af[0], bf[2], bf[3]);
                mma_bf16(acc[1][np * 2 + 1], af[1], bf[2], bf[3]);
            }
        }
        __syncthreads();   // protect buf before next issue overwrites it
        buf ^= 1;
    }

    // ---------------- epilogue ----------------
    float bv0[8], bv1[8];
#pragma unroll
    for (int ni = 0; ni < 8; ni++) {
        int c = bn + wn + ni * 8 + 2 * (lane & 3);
        bv0[ni] = bias[c];
        bv1[ni] = bias[c + 1];
    }

#pragma unroll
    for (int mi = 0; mi < 2; mi++) {
#pragma unroll
        for (int half = 0; half < 2; half++) {
            int r = bm + wm + mi * 16 + (lane >> 2) + half * 8;
            size_t rowoff;
            if (EPI == EPI_PROJ) rowoff = (size_t)win_to_x_row(r) * N;
            else                 rowoff = (size_t)r * N;
#pragma unroll
            for (int ni = 0; ni < 8; ni++) {
                int c = bn + wn + ni * 8 + 2 * (lane & 3);
                float v0 = acc[mi][ni][half * 2 + 0] + bv0[ni];
                float v1 = acc[mi][ni][half * 2 + 1] + bv1[ni];
                if (EPI == EPI_GELU) { v0 = gelu_tanh(v0); v1 = gelu_tanh(v1); }
                if (EPI == EPI_PROJ || EPI == EPI_MLP2) {
                    float2 rr = *(const float2*)(res + rowoff + c);
                    v0 += rr.x; v1 += rr.y;
                }
                if (OUT_BF16) {
                    __nv_bfloat162 w = __floats2bfloat162_rn(v0, v1);
                    *(__nv_bfloat162*)((__nv_bfloat16*)Cout + rowoff + c) = w;
                } else {
                    float2 w = {v0, v1};
                    *(float2*)((float*)Cout + rowoff + c) = w;
                }
            }
        }
    }
}

// ---------------------------------------------------------------------------
// Windowed attention: one block per (window, head). 64 threads. bf16 output.
// ---------------------------------------------------------------------------
__global__ void __launch_bounds__(64) attn_kernel(const float* __restrict__ qkv,
                                                  const float* __restrict__ bias_table,
                                                  __nv_bfloat16* __restrict__ out) {
    const int w     = blockIdx.x >> 3;
    const int h     = blockIdx.x & 7;
    const int wbase = w * 49;
    const int wi    = w & 63;
    const int wr0   = (wi >> 3) * 7;
    const int wc0   = (wi & 7) * 7;

    __shared__ float ks[49][32];
    __shared__ float vs[49][32];
    __shared__ float qs[49][33];
    __shared__ float bias_s[169];
    __shared__ int   reg_s[49];

    const int tid = threadIdx.x;

    for (int idx = tid; idx < 49 * 32; idx += 64) {
        int j = idx >> 5, d = idx & 31;
        size_t base = (size_t)(wbase + j) * 768 + h * 32 + d;
        qs[j][d] = qkv[base] * SCALE_Q;
        ks[j][d] = qkv[base + 256];
        vs[j][d] = qkv[base + 512];
    }
    for (int idx = tid; idx < 169; idx += 64) bias_s[idx] = bias_table[idx * 8 + h];
    for (int idx = tid; idx < 49; idx += 64) {
        int tr = idx / 7, tc = idx - tr * 7;
        int gr = wr0 + tr, gc = wc0 + tc;
        int rh = (gr < 49) ? 0 : ((gr < 53) ? 1 : 2);
        int rc = (gc < 49) ? 0 : ((gc < 53) ? 1 : 2);
        reg_s[idx] = rh * 3 + rc;
    }
    __syncthreads();

    if (tid < 49) {
        const int i  = tid;
        const int ri = i / 7, ci = i - (i / 7) * 7;
        const int regi = reg_s[i];

        float q[32];
#pragma unroll
        for (int d = 0; d < 32; d++) q[d] = qs[i][d];

        float sarr[49];
        float mx = -1e30f;
#pragma unroll
        for (int j = 0; j < 49; j++) {
            float a = 0.0f;
#pragma unroll
            for (int d = 0; d < 32; d++) a = fmaf(q[d], ks[j][d], a);
            int rj = j / 7, cj = j - (j / 7) * 7;
            a += bias_s[(ri - rj + 6) + 13 * (ci - cj + 6)];
            if (reg_s[j] != regi) a -= 100.0f;
            sarr[j] = a;
            mx = fmaxf(mx, a);
        }
        float denom = 0.0f;
#pragma unroll
        for (int j = 0; j < 49; j++) {
            sarr[j] = __expf(sarr[j] - mx);
            denom += sarr[j];
        }
        float dinv = 1.0f / denom;

        float o[32] = {};
#pragma unroll
        for (int j = 0; j < 49; j++) {
            float p = sarr[j] * dinv;
#pragma unroll
            for (int d = 0; d < 32; d++) o[d] = fmaf(p, vs[j][d], o[d]);
        }

        uint2* op = (uint2*)(out + (size_t)(wbase + i) * 256 + h * 32);
#pragma unroll
        for (int d = 0; d < 32; d += 4) {
            float4 t = {o[d], o[d + 1], o[d + 2], o[d + 3]};
            op[d >> 2] = pack4_bf16(t);
        }
    }
}

// ---------------------------------------------------------------------------
// Host launcher (graph-capturable: kernel launches only)
// ---------------------------------------------------------------------------
extern "C" void kernel_launch(void* const* d_in, const int* in_sizes, int n_in,
                              void* d_out, int out_size) {
    (void)in_sizes; (void)n_in; (void)out_size;

    const float* x          = (const float*)d_in[0];
    const float* n1g        = (const float*)d_in[1];
    const float* n1b        = (const float*)d_in[2];
    const float* qkv_w      = (const float*)d_in[3];
    const float* qkv_b      = (const float*)d_in[4];
    const float* proj_w     = (const float*)d_in[5];
    const float* proj_b     = (const float*)d_in[6];
    const float* bias_table = (const float*)d_in[7];
    const float* n2g        = (const float*)d_in[8];
    const float* n2b        = (const float*)d_in[9];
    const float* w1         = (const float*)d_in[10];
    const float* b1         = (const float*)d_in[11];
    const float* w2         = (const float*)d_in[12];
    const float* b2         = (const float*)d_in[13];
    float* out = (float*)d_out;

    __nv_bfloat16 *ywin, *attnb, *h2, *act, *wbf;
    float *qkvb, *x1;
    cudaGetSymbolAddress((void**)&ywin,  g_ywin);
    cudaGetSymbolAddress((void**)&qkvb,  g_qkv);
    cudaGetSymbolAddress((void**)&attnb, g_attn);
    cudaGetSymbolAddress((void**)&x1,    g_x1);
    cudaGetSymbolAddress((void**)&h2,    g_h2);
    cudaGetSymbolAddress((void**)&act,   g_act);
    cudaGetSymbolAddress((void**)&wbf,   g_wbf);

    const int lnBlocks = NROWS / 8;

    // 0) weights -> bf16
    wconv_kernel<<<768, 1024>>>(qkv_w, proj_w, w1, w2, wbf);
    // 1) LN1 + cyclic shift + window partition -> bf16
    ln_kernel<true><<<lnBlocks, 256>>>(x, n1g, n1b, ywin);
    // 2) QKV: [100352,256] @ [256,768] -> fp32
    gemm_bf16<EPI_BIAS, false><<<dim3(784, 6), 256>>>(ywin, wbf + WOFF_QKV, qkv_b,
                                                      qkvb, nullptr, 768, 256);
    // 3) windowed attention -> bf16
    attn_kernel<<<NWIN * 8, 64>>>(qkvb, bias_table, attnb);
    // 4) proj + window-reverse + un-shift + residual -> x1 (fp32)
    gemm_bf16<EPI_PROJ, false><<<dim3(784, 2), 256>>>(attnb, wbf + WOFF_PROJ, proj_b,
                                                      x1, x, 256, 256);
    // 5) LN2 -> bf16
    ln_kernel<false><<<lnBlocks, 256>>>(x1, n2g, n2b, h2);
    // 6) MLP up + GELU: [100352,256] @ [256,1024] -> bf16
    gemm_bf16<EPI_GELU, true><<<dim3(784, 8), 256>>>(h2, wbf + WOFF_W1, b1,
                                                     act, nullptr, 1024, 256);
    // 7) MLP down + residual -> d_out (fp32): [100352,1024] @ [1024,256]
    gemm_bf16<EPI_MLP2, false><<<dim3(784, 2), 256>>>(act, wbf + WOFF_W2, b2,
                                                      out, x1, 256, 1024);
}

// round 4
// speedup vs baseline: 4.0749x; 1.0170x over previous
#include <cuda_runtime.h>
#include <cuda_bf16.h>
#include <cstddef>
#include <cstdint>

// ---------------------------------------------------------------------------
// Problem constants
// ---------------------------------------------------------------------------
#define NROWS   100352            // 32 * 56 * 56 tokens
#define NWIN    2048              // 32 * 64 windows
#define SCALE_Q 0.17677669529663689f   // 32^-0.5

// ---------------------------------------------------------------------------
// Scratch (static __device__ arrays; allocation is forbidden)
// ---------------------------------------------------------------------------
__device__ __align__(16) __nv_bfloat16 g_ywin[100352 * 256];   // LN1 out (win order)
__device__ __align__(16) __nv_bfloat16 g_qkv [100352 * 768];   // qkv, bf16
__device__ __align__(16) __nv_bfloat16 g_attn[100352 * 256];   // attention out
__device__ float                       g_x1  [100352 * 256];   // shortcut + proj
__device__ __align__(16) __nv_bfloat16 g_h2  [100352 * 256];   // LN2 out
__device__ __align__(16) __nv_bfloat16 g_act [100352 * 1024];  // gelu(mlp1)
__device__ __align__(16) __nv_bfloat16 g_wbf [786432];         // all 4 weights, bf16

#define WOFF_QKV  0
#define WOFF_PROJ 196608
#define WOFF_W1   262144
#define WOFF_W2   524288

// ---------------------------------------------------------------------------
// window-order row <-> x-order row mapping (shift = 3, 8x8 windows of 7x7)
// ---------------------------------------------------------------------------
__device__ __forceinline__ int win_to_x_row(int m) {
    int w  = m / 49;
    int t  = m - w * 49;
    int b  = w >> 6;
    int wi = w & 63;
    int tr = t / 7;
    int tc = t - tr * 7;
    int gr = ((wi >> 3) * 7) + tr;
    int gc = ((wi & 7) * 7) + tc;
    int r = gr + 3; if (r >= 56) r -= 56;
    int c = gc + 3; if (c >= 56) c -= 56;
    return b * 3136 + r * 56 + c;
}

__device__ __forceinline__ float gelu_tanh(float x) {
    float x3 = x * x * x;
    return 0.5f * x * (1.0f + tanhf(0.7978845608028654f * (x + 0.044715f * x3)));
}

__device__ __forceinline__ uint2 pack4_bf16(float4 v) {
    __nv_bfloat162 lo = __floats2bfloat162_rn(v.x, v.y);
    __nv_bfloat162 hi = __floats2bfloat162_rn(v.z, v.w);
    uint2 r;
    r.x = *(uint32_t*)&lo;
    r.y = *(uint32_t*)&hi;
    return r;
}

// unpack 8 bf16 (uint4) -> 8 floats (scaled) into dst
__device__ __forceinline__ void unpack8(float* dst, uint4 v, float scale) {
    float2 a = __bfloat1622float2(*(__nv_bfloat162*)&v.x);
    float2 b = __bfloat1622float2(*(__nv_bfloat162*)&v.y);
    float2 c = __bfloat1622float2(*(__nv_bfloat162*)&v.z);
    float2 d = __bfloat1622float2(*(__nv_bfloat162*)&v.w);
    dst[0] = a.x * scale; dst[1] = a.y * scale;
    dst[2] = b.x * scale; dst[3] = b.y * scale;
    dst[4] = c.x * scale; dst[5] = c.y * scale;
    dst[6] = d.x * scale; dst[7] = d.y * scale;
}

// ---------------------------------------------------------------------------
// PTX helpers
// ---------------------------------------------------------------------------
__device__ __forceinline__ void ldsm4(uint32_t r[4], const void* p) {
    uint32_t a = (uint32_t)__cvta_generic_to_shared(p);
    asm volatile("ldmatrix.sync.aligned.m8n8.x4.shared.b16 {%0,%1,%2,%3}, [%4];"
                 : "=r"(r[0]), "=r"(r[1]), "=r"(r[2]), "=r"(r[3]) : "r"(a));
}
__device__ __forceinline__ void ldsm4t(uint32_t r[4], const void* p) {
    uint32_t a = (uint32_t)__cvta_generic_to_shared(p);
    asm volatile("ldmatrix.sync.aligned.m8n8.x4.trans.shared.b16 {%0,%1,%2,%3}, [%4];"
                 : "=r"(r[0]), "=r"(r[1]), "=r"(r[2]), "=r"(r[3]) : "r"(a));
}
__device__ __forceinline__ void mma_bf16(float c[4], const uint32_t a[4],
                                         uint32_t b0, uint32_t b1) {
    asm volatile(
        "mma.sync.aligned.m16n8k16.row.col.f32.bf16.bf16.f32 "
        "{%0,%1,%2,%3}, {%4,%5,%6,%7}, {%8,%9}, {%0,%1,%2,%3};"
        : "+f"(c[0]), "+f"(c[1]), "+f"(c[2]), "+f"(c[3])
        : "r"(a[0]), "r"(a[1]), "r"(a[2]), "r"(a[3]), "r"(b0), "r"(b1));
}
__device__ __forceinline__ void cpasync16(void* dst, const void* src) {
    uint32_t d = (uint32_t)__cvta_generic_to_shared(dst);
    asm volatile("cp.async.cg.shared.global [%0], [%1], 16;" :: "r"(d), "l"(src));
}
__device__ __forceinline__ void cp_commit() {
    asm volatile("cp.async.commit_group;");
}
template <int N>
__device__ __forceinline__ void cp_wait() {
    asm volatile("cp.async.wait_group %0;" :: "n"(N));
}

// ---------------------------------------------------------------------------
// Weight conversion: fp32 -> bf16, once per launch
// ---------------------------------------------------------------------------
__global__ void __launch_bounds__(1024) wconv_kernel(const float* __restrict__ qkv_w,
                                                     const float* __restrict__ proj_w,
                                                     const float* __restrict__ w1,
                                                     const float* __restrict__ w2,
                                                     __nv_bfloat16* __restrict__ dst) {
    int i = blockIdx.x * 1024 + threadIdx.x;   // grid = 768
    float v;
    if      (i < WOFF_PROJ) v = qkv_w[i];
    else if (i < WOFF_W1)   v = proj_w[i - WOFF_PROJ];
    else if (i < WOFF_W2)   v = w1[i - WOFF_W1];
    else                    v = w2[i - WOFF_W2];
    dst[i] = __float2bfloat16(v);
}

// ---------------------------------------------------------------------------
// LayerNorm: one warp per 256-wide row, bf16 output.
// ---------------------------------------------------------------------------
template <bool GATHER>
__global__ void __launch_bounds__(256) ln_kernel(const float* __restrict__ in,
                                                 const float* __restrict__ gamma,
                                                 const float* __restrict__ beta,
                                                 __nv_bfloat16* __restrict__ out) {
    int gw   = (blockIdx.x * blockDim.x + threadIdx.x) >> 5;
    int lane = threadIdx.x & 31;
    if (gw >= NROWS) return;
    int src = GATHER ? win_to_x_row(gw) : gw;

    const float4* row = (const float4*)(in + (size_t)src * 256);
    float4 v0 = row[lane];
    float4 v1 = row[lane + 32];

    float s  = v0.x + v0.y + v0.z + v0.w + v1.x + v1.y + v1.z + v1.w;
    float ss = v0.x*v0.x + v0.y*v0.y + v0.z*v0.z + v0.w*v0.w
             + v1.x*v1.x + v1.y*v1.y + v1.z*v1.z + v1.w*v1.w;
#pragma unroll
    for (int o = 16; o; o >>= 1) {
        s  += __shfl_xor_sync(0xffffffffu, s,  o);
        ss += __shfl_xor_sync(0xffffffffu, ss, o);
    }
    float mu  = s * (1.0f / 256.0f);
    float inv = rsqrtf(ss * (1.0f / 256.0f) - mu * mu + 1e-5f);

    float4 g0 = ((const float4*)gamma)[lane];
    float4 g1 = ((const float4*)gamma)[lane + 32];
    float4 b0 = ((const float4*)beta)[lane];
    float4 b1 = ((const float4*)beta)[lane + 32];

    float4 o0, o1;
    o0.x = (v0.x - mu) * inv * g0.x + b0.x;
    o0.y = (v0.y - mu) * inv * g0.y + b0.y;
    o0.z = (v0.z - mu) * inv * g0.z + b0.z;
    o0.w = (v0.w - mu) * inv * g0.w + b0.w;
    o1.x = (v1.x - mu) * inv * g1.x + b1.x;
    o1.y = (v1.y - mu) * inv * g1.y + b1.y;
    o1.z = (v1.z - mu) * inv * g1.z + b1.z;
    o1.w = (v1.w - mu) * inv * g1.w + b1.w;

    uint2* orow = (uint2*)(out + (size_t)gw * 256);
    orow[lane]      = pack4_bf16(o0);
    orow[lane + 32] = pack4_bf16(o1);
}

// ---------------------------------------------------------------------------
// bf16 tensor-core GEMM (unchanged math; single __syncthreads per K-iter)
// ---------------------------------------------------------------------------
#define EPI_BIAS 0
#define EPI_GELU 1
#define EPI_PROJ 2
#define EPI_MLP2 3

#define AS 40
#define BSS 136

template <int EPI, bool OUT_BF16>
__global__ void __launch_bounds__(256) gemm_bf16(const __nv_bfloat16* __restrict__ A,
                                                 const __nv_bfloat16* __restrict__ B,
                                                 const float* __restrict__ bias,
                                                 void* __restrict__ Cout,
                                                 const float* __restrict__ res,
                                                 int N, int K) {
    __shared__ __align__(16) __nv_bfloat16 As[2][128 * AS];
    __shared__ __align__(16) __nv_bfloat16 Bs[2][32 * BSS];

    const int tid  = threadIdx.x;
    const int lane = tid & 31;
    const int wid  = tid >> 5;
    const int bm   = blockIdx.x * 128;
    const int bn   = blockIdx.y * 128;
    const int wm   = (wid & 3) * 32;
    const int wn   = (wid >> 2) * 64;

    const __nv_bfloat16* Ab = A + (size_t)bm * K;
    const __nv_bfloat16* Bb = B + bn;

    float acc[2][8][4] = {};

    auto load_tile = [&](int k0, int buf) {
#pragma unroll
        for (int i = 0; i < 2; i++) {
            int c = tid + i * 256;
            int row = c >> 2, kc = (c & 3) * 8;
            cpasync16(&As[buf][row * AS + kc], Ab + (size_t)row * K + k0 + kc);
        }
#pragma unroll
        for (int i = 0; i < 2; i++) {
            int c = tid + i * 256;
            int k = c >> 4, n = (c & 15) * 8;
            cpasync16(&Bs[buf][k * BSS + n], Bb + (size_t)(k0 + k) * N + n);
        }
        cp_commit();
    };

    load_tile(0, 0);

    int buf = 0;
    for (int k0 = 0; k0 < K; k0 += 32) {
        cp_wait<0>();
        __syncthreads();
        if (k0 + 32 < K) load_tile(k0 + 32, buf ^ 1);

        const __nv_bfloat16* as = As[buf];
        const __nv_bfloat16* bs = Bs[buf];
#pragma unroll
        for (int ks = 0; ks < 32; ks += 16) {
            uint32_t af[2][4];
#pragma unroll
            for (int mi = 0; mi < 2; mi++)
                ldsm4(af[mi], as + (wm + mi * 16 + (lane & 15)) * AS
                                 + ks + (lane >> 4) * 8);
#pragma unroll
            for (int np = 0; np < 4; np++) {
                uint32_t bf[4];
                ldsm4t(bf, bs + (ks + (lane & 7) + ((lane >> 3) & 1) * 8) * BSS
                              + wn + np * 16 + (lane >> 4) * 8);
                mma_bf16(acc[0][np * 2 + 0], af[0], bf[0], bf[1]);
                mma_bf16(acc[1][np * 2 + 0], af[1], bf[0], bf[1]);
                mma_bf16(acc[0][np * 2 + 1], af[0], bf[2], bf[3]);
                mma_bf16(acc[1][np * 2 + 1], af[1], bf[2], bf[3]);
            }
        }
        buf ^= 1;
    }

    // ---------------- epilogue ----------------
    float bv0[8], bv1[8];
#pragma unroll
    for (int ni = 0; ni < 8; ni++) {
        int c = bn + wn + ni * 8 + 2 * (lane & 3);
        bv0[ni] = bias[c];
        bv1[ni] = bias[c + 1];
    }

#pragma unroll
    for (int mi = 0; mi < 2; mi++) {
#pragma unroll
        for (int half = 0; half < 2; half++) {
            int r = bm + wm + mi * 16 + (lane >> 2) + half * 8;
            size_t rowoff;
            if (EPI == EPI_PROJ) rowoff = (size_t)win_to_x_row(r) * N;
            else                 rowoff = (size_t)r * N;
#pragma unroll
            for (int ni = 0; ni < 8; ni++) {
                int c = bn + wn + ni * 8 + 2 * (lane & 3);
                float v0 = acc[mi][ni][half * 2 + 0] + bv0[ni];
                float v1 = acc[mi][ni][half * 2 + 1] + bv1[ni];
                if (EPI == EPI_GELU) { v0 = gelu_tanh(v0); v1 = gelu_tanh(v1); }
                if (EPI == EPI_PROJ || EPI == EPI_MLP2) {
                    float2 rr = *(const float2*)(res + rowoff + c);
                    v0 += rr.x; v1 += rr.y;
                }
                if (OUT_BF16) {
                    __nv_bfloat162 w = __floats2bfloat162_rn(v0, v1);
                    *(__nv_bfloat162*)((__nv_bfloat16*)Cout + rowoff + c) = w;
                } else {
                    float2 w = {v0, v1};
                    *(float2*)((float*)Cout + rowoff + c) = w;
                }
            }
        }
    }
}

// ---------------------------------------------------------------------------
// Windowed attention: one block per (window, head-pair). 128 threads.
// Threads [0,64) -> head 2*hp, [64,128) -> head 2*hp+1; thread t&63 = query row.
// bf16 qkv input unpacked to fp32 smem; float4 inner loops; no max pass.
// ---------------------------------------------------------------------------
__global__ void __launch_bounds__(128) attn_kernel(const __nv_bfloat16* __restrict__ qkv,
                                                   const float* __restrict__ bias_table,
                                                   __nv_bfloat16* __restrict__ out) {
    const int w     = blockIdx.x >> 2;
    const int sub   = threadIdx.x >> 6;            // 0/1 within head pair
    const int h     = (blockIdx.x & 3) * 2 + sub;
    const int t     = threadIdx.x & 63;
    const int wbase = w * 49;
    const int wi    = w & 63;
    const int wr0   = (wi >> 3) * 7;
    const int wc0   = (wi & 7) * 7;

    __shared__ float ks[2][49][32];
    __shared__ float vs[2][49][32];
    __shared__ float qs[2][49][36];   // stride 36: float4 reads conflict-free
    __shared__ float bias_s[2][169];
    __shared__ int   reg_s[49];

    // load q/k/v for this head (8 bf16 per uint4)
    for (int idx = t; idx < 49 * 4; idx += 64) {
        int j = idx >> 2, seg = idx & 3;
        const __nv_bfloat16* base = qkv + (size_t)(wbase + j) * 768 + h * 32 + seg * 8;
        uint4 qv = *(const uint4*)base;
        uint4 kv = *(const uint4*)(base + 256);
        uint4 vv = *(const uint4*)(base + 512);
        unpack8(&qs[sub][j][seg * 8], qv, SCALE_Q);
        unpack8(&ks[sub][j][seg * 8], kv, 1.0f);
        unpack8(&vs[sub][j][seg * 8], vv, 1.0f);
    }
    for (int idx = t; idx < 169; idx += 64) bias_s[sub][idx] = bias_table[idx * 8 + h];
    if (sub == 0) {
        for (int idx = t; idx < 49; idx += 64) {
            int tr = idx / 7, tc = idx - tr * 7;
            int gr = wr0 + tr, gc = wc0 + tc;
            int rh = (gr < 49) ? 0 : ((gr < 53) ? 1 : 2);
            int rc = (gc < 49) ? 0 : ((gc < 53) ? 1 : 2);
            reg_s[idx] = rh * 3 + rc;
        }
    }
    __syncthreads();

    if (t < 49) {
        const int i  = t;
        const int ri = i / 7, ci = i - (i / 7) * 7;
        const int regi = reg_s[i];

        float4 q4[8];
#pragma unroll
        for (int d = 0; d < 8; d++) q4[d] = *(const float4*)&qs[sub][i][d * 4];

        float sarr[49];
        float denom = 0.0f;
#pragma unroll
        for (int j = 0; j < 49; j++) {
            const float4* kr = (const float4*)ks[sub][j];
            float a = 0.0f;
#pragma unroll
            for (int d = 0; d < 8; d++) {
                float4 kv = kr[d];
                a = fmaf(q4[d].x, kv.x, a);
                a = fmaf(q4[d].y, kv.y, a);
                a = fmaf(q4[d].z, kv.z, a);
                a = fmaf(q4[d].w, kv.w, a);
            }
            int rj = j / 7, cj = j - (j / 7) * 7;
            a += bias_s[sub][(ri - rj + 6) + 13 * (ci - cj + 6)];
            if (reg_s[j] != regi) a -= 100.0f;
            float p = __expf(a);
            denom += p;
            sarr[j] = p;
        }
        float dinv = 1.0f / denom;

        float4 o4[8] = {};
#pragma unroll
        for (int j = 0; j < 49; j++) {
            float p = sarr[j] * dinv;
            const float4* vr = (const float4*)vs[sub][j];
#pragma unroll
            for (int d = 0; d < 8; d++) {
                float4 vv = vr[d];
                o4[d].x = fmaf(p, vv.x, o4[d].x);
                o4[d].y = fmaf(p, vv.y, o4[d].y);
                o4[d].z = fmaf(p, vv.z, o4[d].z);
                o4[d].w = fmaf(p, vv.w, o4[d].w);
            }
        }

        uint2* op = (uint2*)(out + (size_t)(wbase + i) * 256 + h * 32);
#pragma unroll
        for (int d = 0; d < 8; d++) op[d] = pack4_bf16(o4[d]);
    }
}

// ---------------------------------------------------------------------------
// Host launcher (graph-capturable: kernel launches only)
// ---------------------------------------------------------------------------
extern "C" void kernel_launch(void* const* d_in, const int* in_sizes, int n_in,
                              void* d_out, int out_size) {
    (void)in_sizes; (void)n_in; (void)out_size;

    const float* x          = (const float*)d_in[0];
    const float* n1g        = (const float*)d_in[1];
    const float* n1b        = (const float*)d_in[2];
    const float* qkv_w      = (const float*)d_in[3];
    const float* qkv_b      = (const float*)d_in[4];
    const float* proj_w     = (const float*)d_in[5];
    const float* proj_b     = (const float*)d_in[6];
    const float* bias_table = (const float*)d_in[7];
    const float* n2g        = (const float*)d_in[8];
    const float* n2b        = (const float*)d_in[9];
    const float* w1         = (const float*)d_in[10];
    const float* b1         = (const float*)d_in[11];
    const float* w2         = (const float*)d_in[12];
    const float* b2         = (const float*)d_in[13];
    float* out = (float*)d_out;

    __nv_bfloat16 *ywin, *qkvb, *attnb, *h2, *act, *wbf;
    float *x1;
    cudaGetSymbolAddress((void**)&ywin,  g_ywin);
    cudaGetSymbolAddress((void**)&qkvb,  g_qkv);
    cudaGetSymbolAddress((void**)&attnb, g_attn);
    cudaGetSymbolAddress((void**)&x1,    g_x1);
    cudaGetSymbolAddress((void**)&h2,    g_h2);
    cudaGetSymbolAddress((void**)&act,   g_act);
    cudaGetSymbolAddress((void**)&wbf,   g_wbf);

    const int lnBlocks = NROWS / 8;

    // 0) weights -> bf16
    wconv_kernel<<<768, 1024>>>(qkv_w, proj_w, w1, w2, wbf);
    // 1) LN1 + cyclic shift + window partition -> bf16
    ln_kernel<true><<<lnBlocks, 256>>>(x, n1g, n1b, ywin);
    // 2) QKV: [100352,256] @ [256,768] -> bf16
    gemm_bf16<EPI_BIAS, true><<<dim3(784, 6), 256>>>(ywin, wbf + WOFF_QKV, qkv_b,
                                                     qkvb, nullptr, 768, 256);
    // 3) windowed attention -> bf16
    attn_kernel<<<NWIN * 4, 128>>>(qkvb, bias_table, attnb);
    // 4) proj + window-reverse + un-shift + residual -> x1 (fp32)
    gemm_bf16<EPI_PROJ, false><<<dim3(784, 2), 256>>>(attnb, wbf + WOFF_PROJ, proj_b,
                                                      x1, x, 256, 256);
    // 5) LN2 -> bf16
    ln_kernel<false><<<lnBlocks, 256>>>(x1, n2g, n2b, h2);
    // 6) MLP up + GELU: [100352,256] @ [256,1024] -> bf16
    gemm_bf16<EPI_GELU, true><<<dim3(784, 8), 256>>>(h2, wbf + WOFF_W1, b1,
                                                     act, nullptr, 1024, 256);
    // 7) MLP down + residual -> d_out (fp32): [100352,1024] @ [1024,256]
    gemm_bf16<EPI_MLP2, false><<<dim3(784, 2), 256>>>(act, wbf + WOFF_W2, b2,
                                                      out, x1, 256, 1024);
}

// round 5
// speedup vs baseline: 4.5779x; 1.1234x over previous
#include <cuda_runtime.h>
#include <cuda_bf16.h>
#include <cstddef>
#include <cstdint>

// ---------------------------------------------------------------------------
// Problem constants
// ---------------------------------------------------------------------------
#define NROWS   100352            // 32 * 56 * 56 tokens
#define NWIN    2048              // 32 * 64 windows
#define SCALE_Q 0.17677669529663689f   // 32^-0.5

// ---------------------------------------------------------------------------
// Scratch (static __device__ arrays; allocation is forbidden)
// ---------------------------------------------------------------------------
__device__ __align__(16) __nv_bfloat16 g_ywin[100352 * 256];   // LN1 out (win order)
__device__ __align__(16) __nv_bfloat16 g_qkv [100352 * 768];   // qkv, bf16
__device__ __align__(16) __nv_bfloat16 g_attn[100352 * 256];   // attention out
__device__ float                       g_x1  [100352 * 256];   // shortcut + proj
__device__ __align__(16) __nv_bfloat16 g_h2  [100352 * 256];   // LN2 out
__device__ __align__(16) __nv_bfloat16 g_act [100352 * 1024];  // gelu(mlp1)
__device__ __align__(16) __nv_bfloat16 g_wbf [786432];         // all 4 weights, bf16

#define WOFF_QKV  0
#define WOFF_PROJ 196608
#define WOFF_W1   262144
#define WOFF_W2   524288

// ---------------------------------------------------------------------------
// window-order row <-> x-order row mapping (shift = 3, 8x8 windows of 7x7)
// ---------------------------------------------------------------------------
__device__ __forceinline__ int win_to_x_row(int m) {
    int w  = m / 49;
    int t  = m - w * 49;
    int b  = w >> 6;
    int wi = w & 63;
    int tr = t / 7;
    int tc = t - tr * 7;
    int gr = ((wi >> 3) * 7) + tr;
    int gc = ((wi & 7) * 7) + tc;
    int r = gr + 3; if (r >= 56) r -= 56;
    int c = gc + 3; if (c >= 56) c -= 56;
    return b * 3136 + r * 56 + c;
}

__device__ __forceinline__ float gelu_tanh(float x) {
    float x3 = x * x * x;
    return 0.5f * x * (1.0f + tanhf(0.7978845608028654f * (x + 0.044715f * x3)));
}

__device__ __forceinline__ uint2 pack4_bf16(float4 v) {
    __nv_bfloat162 lo = __floats2bfloat162_rn(v.x, v.y);
    __nv_bfloat162 hi = __floats2bfloat162_rn(v.z, v.w);
    uint2 r;
    r.x = *(uint32_t*)&lo;
    r.y = *(uint32_t*)&hi;
    return r;
}

__device__ __forceinline__ uint32_t pack2_bf16(float a, float b) {
    __nv_bfloat162 t = __floats2bfloat162_rn(a, b);
    return *(uint32_t*)&t;
}

// ---------------------------------------------------------------------------
// PTX helpers
// ---------------------------------------------------------------------------
__device__ __forceinline__ void ldsm4(uint32_t r[4], const void* p) {
    uint32_t a = (uint32_t)__cvta_generic_to_shared(p);
    asm volatile("ldmatrix.sync.aligned.m8n8.x4.shared.b16 {%0,%1,%2,%3}, [%4];"
                 : "=r"(r[0]), "=r"(r[1]), "=r"(r[2]), "=r"(r[3]) : "r"(a));
}
__device__ __forceinline__ void ldsm4t(uint32_t r[4], const void* p) {
    uint32_t a = (uint32_t)__cvta_generic_to_shared(p);
    asm volatile("ldmatrix.sync.aligned.m8n8.x4.trans.shared.b16 {%0,%1,%2,%3}, [%4];"
                 : "=r"(r[0]), "=r"(r[1]), "=r"(r[2]), "=r"(r[3]) : "r"(a));
}
__device__ __forceinline__ void mma_bf16(float c[4], const uint32_t a[4],
                                         uint32_t b0, uint32_t b1) {
    asm volatile(
        "mma.sync.aligned.m16n8k16.row.col.f32.bf16.bf16.f32 "
        "{%0,%1,%2,%3}, {%4,%5,%6,%7}, {%8,%9}, {%0,%1,%2,%3};"
        : "+f"(c[0]), "+f"(c[1]), "+f"(c[2]), "+f"(c[3])
        : "r"(a[0]), "r"(a[1]), "r"(a[2]), "r"(a[3]), "r"(b0), "r"(b1));
}
__device__ __forceinline__ void cpasync16(void* dst, const void* src) {
    uint32_t d = (uint32_t)__cvta_generic_to_shared(dst);
    asm volatile("cp.async.cg.shared.global [%0], [%1], 16;" :: "r"(d), "l"(src));
}
__device__ __forceinline__ void cp_commit() {
    asm volatile("cp.async.commit_group;");
}
template <int N>
__device__ __forceinline__ void cp_wait() {
    asm volatile("cp.async.wait_group %0;" :: "n"(N));
}

// ---------------------------------------------------------------------------
// Weight conversion: fp32 -> bf16, once per launch
// ---------------------------------------------------------------------------
__global__ void __launch_bounds__(1024) wconv_kernel(const float* __restrict__ qkv_w,
                                                     const float* __restrict__ proj_w,
                                                     const float* __restrict__ w1,
                                                     const float* __restrict__ w2,
                                                     __nv_bfloat16* __restrict__ dst) {
    int i = blockIdx.x * 1024 + threadIdx.x;   // grid = 768
    float v;
    if      (i < WOFF_PROJ) v = qkv_w[i];
    else if (i < WOFF_W1)   v = proj_w[i - WOFF_PROJ];
    else if (i < WOFF_W2)   v = w1[i - WOFF_W1];
    else                    v = w2[i - WOFF_W2];
    dst[i] = __float2bfloat16(v);
}

// ---------------------------------------------------------------------------
// LayerNorm: one warp per 256-wide row, bf16 output.
// ---------------------------------------------------------------------------
template <bool GATHER>
__global__ void __launch_bounds__(256) ln_kernel(const float* __restrict__ in,
                                                 const float* __restrict__ gamma,
                                                 const float* __restrict__ beta,
                                                 __nv_bfloat16* __restrict__ out) {
    int gw   = (blockIdx.x * blockDim.x + threadIdx.x) >> 5;
    int lane = threadIdx.x & 31;
    if (gw >= NROWS) return;
    int src = GATHER ? win_to_x_row(gw) : gw;

    const float4* row = (const float4*)(in + (size_t)src * 256);
    float4 v0 = row[lane];
    float4 v1 = row[lane + 32];

    float s  = v0.x + v0.y + v0.z + v0.w + v1.x + v1.y + v1.z + v1.w;
    float ss = v0.x*v0.x + v0.y*v0.y + v0.z*v0.z + v0.w*v0.w
             + v1.x*v1.x + v1.y*v1.y + v1.z*v1.z + v1.w*v1.w;
#pragma unroll
    for (int o = 16; o; o >>= 1) {
        s  += __shfl_xor_sync(0xffffffffu, s,  o);
        ss += __shfl_xor_sync(0xffffffffu, ss, o);
    }
    float mu  = s * (1.0f / 256.0f);
    float inv = rsqrtf(ss * (1.0f / 256.0f) - mu * mu + 1e-5f);

    float4 g0 = ((const float4*)gamma)[lane];
    float4 g1 = ((const float4*)gamma)[lane + 32];
    float4 b0 = ((const float4*)beta)[lane];
    float4 b1 = ((const float4*)beta)[lane + 32];

    float4 o0, o1;
    o0.x = (v0.x - mu) * inv * g0.x + b0.x;
    o0.y = (v0.y - mu) * inv * g0.y + b0.y;
    o0.z = (v0.z - mu) * inv * g0.z + b0.z;
    o0.w = (v0.w - mu) * inv * g0.w + b0.w;
    o1.x = (v1.x - mu) * inv * g1.x + b1.x;
    o1.y = (v1.y - mu) * inv * g1.y + b1.y;
    o1.z = (v1.z - mu) * inv * g1.z + b1.z;
    o1.w = (v1.w - mu) * inv * g1.w + b1.w;

    uint2* orow = (uint2*)(out + (size_t)gw * 256);
    orow[lane]      = pack4_bf16(o0);
    orow[lane + 32] = pack4_bf16(o1);
}

// ---------------------------------------------------------------------------
// bf16 tensor-core GEMM (unchanged from R3)
// ---------------------------------------------------------------------------
#define EPI_BIAS 0
#define EPI_GELU 1
#define EPI_PROJ 2
#define EPI_MLP2 3

#define AS 40
#define BSS 136

template <int EPI, bool OUT_BF16>
__global__ void __launch_bounds__(256) gemm_bf16(const __nv_bfloat16* __restrict__ A,
                                                 const __nv_bfloat16* __restrict__ B,
                                                 const float* __restrict__ bias,
                                                 void* __restrict__ Cout,
                                                 const float* __restrict__ res,
                                                 int N, int K) {
    __shared__ __align__(16) __nv_bfloat16 As[2][128 * AS];
    __shared__ __align__(16) __nv_bfloat16 Bs[2][32 * BSS];

    const int tid  = threadIdx.x;
    const int lane = tid & 31;
    const int wid  = tid >> 5;
    const int bm   = blockIdx.x * 128;
    const int bn   = blockIdx.y * 128;
    const int wm   = (wid & 3) * 32;
    const int wn   = (wid >> 2) * 64;

    const __nv_bfloat16* Ab = A + (size_t)bm * K;
    const __nv_bfloat16* Bb = B + bn;

    float acc[2][8][4] = {};

    auto load_tile = [&](int k0, int buf) {
#pragma unroll
        for (int i = 0; i < 2; i++) {
            int c = tid + i * 256;
            int row = c >> 2, kc = (c & 3) * 8;
            cpasync16(&As[buf][row * AS + kc], Ab + (size_t)row * K + k0 + kc);
        }
#pragma unroll
        for (int i = 0; i < 2; i++) {
            int c = tid + i * 256;
            int k = c >> 4, n = (c & 15) * 8;
            cpasync16(&Bs[buf][k * BSS + n], Bb + (size_t)(k0 + k) * N + n);
        }
        cp_commit();
    };

    load_tile(0, 0);

    int buf = 0;
    for (int k0 = 0; k0 < K; k0 += 32) {
        cp_wait<0>();
        __syncthreads();
        if (k0 + 32 < K) load_tile(k0 + 32, buf ^ 1);

        const __nv_bfloat16* as = As[buf];
        const __nv_bfloat16* bs = Bs[buf];
#pragma unroll
        for (int ks = 0; ks < 32; ks += 16) {
            uint32_t af[2][4];
#pragma unroll
            for (int mi = 0; mi < 2; mi++)
                ldsm4(af[mi], as + (wm + mi * 16 + (lane & 15)) * AS
                                 + ks + (lane >> 4) * 8);
#pragma unroll
            for (int np = 0; np < 4; np++) {
                uint32_t bf[4];
                ldsm4t(bf, bs + (ks + (lane & 7) + ((lane >> 3) & 1) * 8) * BSS
                              + wn + np * 16 + (lane >> 4) * 8);
                mma_bf16(acc[0][np * 2 + 0], af[0], bf[0], bf[1]);
                mma_bf16(acc[1][np * 2 + 0], af[1], bf[0], bf[1]);
                mma_bf16(acc[0][np * 2 + 1], af[0], bf[2], bf[3]);
                mma_bf16(acc[1][np * 2 + 1], af[1], bf[2], bf[3]);
            }
        }
        buf ^= 1;
    }

    // ---------------- epilogue ----------------
    float bv0[8], bv1[8];
#pragma unroll
    for (int ni = 0; ni < 8; ni++) {
        int c = bn + wn + ni * 8 + 2 * (lane & 3);
        bv0[ni] = bias[c];
        bv1[ni] = bias[c + 1];
    }

#pragma unroll
    for (int mi = 0; mi < 2; mi++) {
#pragma unroll
        for (int half = 0; half < 2; half++) {
            int r = bm + wm + mi * 16 + (lane >> 2) + half * 8;
            size_t rowoff;
            if (EPI == EPI_PROJ) rowoff = (size_t)win_to_x_row(r) * N;
            else                 rowoff = (size_t)r * N;
#pragma unroll
            for (int ni = 0; ni < 8; ni++) {
                int c = bn + wn + ni * 8 + 2 * (lane & 3);
                float v0 = acc[mi][ni][half * 2 + 0] + bv0[ni];
                float v1 = acc[mi][ni][half * 2 + 1] + bv1[ni];
                if (EPI == EPI_GELU) { v0 = gelu_tanh(v0); v1 = gelu_tanh(v1); }
                if (EPI == EPI_PROJ || EPI == EPI_MLP2) {
                    float2 rr = *(const float2*)(res + rowoff + c);
                    v0 += rr.x; v1 += rr.y;
                }
                if (OUT_BF16) {
                    __nv_bfloat162 w = __floats2bfloat162_rn(v0, v1);
                    *(__nv_bfloat162*)((__nv_bfloat16*)Cout + rowoff + c) = w;
                } else {
                    float2 w = {v0, v1};
                    *(float2*)((float*)Cout + rowoff + c) = w;
                }
            }
        }
    }
}

// ---------------------------------------------------------------------------
// Tensor-core windowed attention.
// One WARP per (window, head); tokens padded 49 -> 64.
// Block = 2 warps (2 heads), grid = NWIN * 4 head-pairs.
//   S[64x64] = Q K^T via mma.m16n8k16 (K frags register-resident)
//   softmax fused with rel-pos bias + shift mask on the accumulator layout
//   P (C-frag -> A-frag register identity) @ V via ldmatrix.trans
// smem rows stride 40 bf16 => conflict-free ldmatrix (same proof as GEMM A).
// ---------------------------------------------------------------------------
#define ATS 40

__global__ void __launch_bounds__(64) attn_tc(const __nv_bfloat16* __restrict__ qkv,
                                              const float* __restrict__ bias_table,
                                              __nv_bfloat16* __restrict__ out) {
    __shared__ __align__(16) __nv_bfloat16 sQ[2][64 * ATS];
    __shared__ __align__(16) __nv_bfloat16 sK[2][64 * ATS];
    __shared__ __align__(16) __nv_bfloat16 sV[2][64 * ATS];
    __shared__ float sB[2][169];
    __shared__ int   sInfo[64];       // key | reg<<8 | valid<<16  (per window)

    const int w     = blockIdx.x >> 2;
    const int wp    = threadIdx.x >> 5;
    const int lane  = threadIdx.x & 31;
    const int h     = (blockIdx.x & 3) * 2 + wp;
    const int wbase = w * 49;
    const int wi    = w & 63;

    // ---- per-window token info table (64 entries, block-shared) ----
    if (threadIdx.x < 64) {
        int j = threadIdx.x;
        int info;
        if (j < 49) {
            int rj = j / 7, cj = j - (j / 7) * 7;
            int gr = (wi >> 3) * 7 + rj;
            int gc = (wi & 7) * 7 + cj;
            int rh = (gr < 49) ? 0 : ((gr < 53) ? 1 : 2);
            int rc = (gc < 49) ? 0 : ((gc < 53) ? 1 : 2);
            int key = rj + 13 * cj;                 // bias idx = key_i - key_j + 84
            info = key | ((rh * 3 + rc) << 8) | (1 << 16);
        } else {
            info = 0 | (255 << 8);                  // invalid, never-matching region
        }
        sInfo[j] = info;
    }

    // ---- per-head bias table ----
    for (int idx = lane; idx < 169; idx += 32) sB[wp][idx] = bias_table[idx * 8 + h];

    // ---- load Q/K/V tiles (49 rows x 32 bf16), zero pad rows 49..63 ----
    for (int tsk = lane; tsk < 256; tsk += 32) {
        int row = tsk >> 2, seg = (tsk & 3) * 8;
        uint4 q4, k4, v4;
        if (row < 49) {
            const __nv_bfloat16* base = qkv + (size_t)(wbase + row) * 768 + h * 32 + seg;
            q4 = *(const uint4*)base;
            k4 = *(const uint4*)(base + 256);
            v4 = *(const uint4*)(base + 512);
        } else {
            q4 = make_uint4(0, 0, 0, 0); k4 = q4; v4 = q4;
        }
        int off = row * ATS + seg;
        *(uint4*)&sQ[wp][off] = q4;
        *(uint4*)&sK[wp][off] = k4;
        *(uint4*)&sV[wp][off] = v4;
    }
    __syncthreads();

    // ---- hoisted K fragments: kf[kstep][ntile16][4] ----
    uint32_t kf[2][4][4];
#pragma unroll
    for (int ks = 0; ks < 2; ks++)
#pragma unroll
        for (int nt = 0; nt < 4; nt++)
            ldsm4(kf[ks][nt], &sK[wp][(nt * 16 + (lane & 7) + ((lane >> 4) & 1) * 8) * ATS
                                      + ks * 16 + ((lane >> 3) & 1) * 8]);

    // ---- per-thread column info (j set is m-tile independent) ----
    const int q2 = 2 * (lane & 3);
    int jinfo[16];
#pragma unroll
    for (int u = 0; u < 8; u++) {
        jinfo[u * 2 + 0] = sInfo[u * 8 + q2 + 0];
        jinfo[u * 2 + 1] = sInfo[u * 8 + q2 + 1];
    }

    const int r = lane >> 2;

#pragma unroll
    for (int mt = 0; mt < 4; mt++) {
        // Q fragments for this m-tile (k = 0..31)
        uint32_t qf[2][4];
#pragma unroll
        for (int ks = 0; ks < 2; ks++)
            ldsm4(qf[ks], &sQ[wp][(mt * 16 + (lane & 15)) * ATS
                                  + ks * 16 + (lane >> 4) * 8]);

        // S = Q K^T  (c[u]: n8-tile u, j = 8u + q2 + {0,1})
        float c[8][4] = {};
#pragma unroll
        for (int nt = 0; nt < 4; nt++) {
#pragma unroll
            for (int ks = 0; ks < 2; ks++) {
                mma_bf16(c[2 * nt + 0], qf[ks], kf[ks][nt][0], kf[ks][nt][1]);
                mma_bf16(c[2 * nt + 1], qf[ks], kf[ks][nt][2], kf[ks][nt][3]);
            }
        }

        // ---- fused bias + mask + softmax ----
        int ilo = mt * 16 + r;
        int infLo = sInfo[ilo], infHi = sInfo[ilo + 8];
        int keyLo = (infLo & 255) + 84, regLo = (infLo >> 8) & 255;
        int keyHi = (infHi & 255) + 84, regHi = (infHi >> 8) & 255;

        float sumLo = 0.0f, sumHi = 0.0f;
#pragma unroll
        for (int u = 0; u < 8; u++) {
#pragma unroll
            for (int e = 0; e < 2; e++) {
                int inf = jinfo[u * 2 + e];
                float pLo, pHi;
                if (inf & 0x10000) {
                    int kj = inf & 255;
                    int rj = (inf >> 8) & 255;
                    float aLo = fmaf(c[u][e], SCALE_Q, sB[wp][keyLo - kj]);
                    float aHi = fmaf(c[u][2 + e], SCALE_Q, sB[wp][keyHi - kj]);
                    if (rj != regLo) aLo -= 100.0f;
                    if (rj != regHi) aHi -= 100.0f;
                    pLo = __expf(aLo);
                    pHi = __expf(aHi);
                } else {
                    pLo = 0.0f; pHi = 0.0f;
                }
                c[u][e]     = pLo;  sumLo += pLo;
                c[u][2 + e] = pHi;  sumHi += pHi;
            }
        }
        sumLo += __shfl_xor_sync(0xffffffffu, sumLo, 1);
        sumLo += __shfl_xor_sync(0xffffffffu, sumLo, 2);
        sumHi += __shfl_xor_sync(0xffffffffu, sumHi, 1);
        sumHi += __shfl_xor_sync(0xffffffffu, sumHi, 2);
        float dLo = 1.0f / sumLo;
        float dHi = 1.0f / sumHi;

        // P: C-fragment -> A-fragment (register identity), normalized, bf16
        uint32_t pa[4][4];
#pragma unroll
        for (int t = 0; t < 4; t++) {
            pa[t][0] = pack2_bf16(c[2 * t][0] * dLo,     c[2 * t][1] * dLo);
            pa[t][1] = pack2_bf16(c[2 * t][2] * dHi,     c[2 * t][3] * dHi);
            pa[t][2] = pack2_bf16(c[2 * t + 1][0] * dLo, c[2 * t + 1][1] * dLo);
            pa[t][3] = pack2_bf16(c[2 * t + 1][2] * dHi, c[2 * t + 1][3] * dHi);
        }

        // O = P V   (k = j = 64, n = d = 32)
        float o[4][4] = {};
#pragma unroll
        for (int ks = 0; ks < 4; ks++) {
            uint32_t vf[2][4];
#pragma unroll
            for (int half = 0; half < 2; half++)
                ldsm4t(vf[half], &sV[wp][(ks * 16 + (lane & 7) + ((lane >> 3) & 1) * 8) * ATS
                                         + half * 16 + (lane >> 4) * 8]);
            mma_bf16(o[0], pa[ks], vf[0][0], vf[0][1]);
            mma_bf16(o[1], pa[ks], vf[0][2], vf[0][3]);
            mma_bf16(o[2], pa[ks], vf[1][0], vf[1][1]);
            mma_bf16(o[3], pa[ks], vf[1][2], vf[1][3]);
        }

        // ---- store (rows < 49 only) ----
        if (ilo < 49) {
            __nv_bfloat16* p = out + (size_t)(wbase + ilo) * 256 + h * 32 + q2;
#pragma unroll
            for (int on = 0; on < 4; on++)
                *(uint32_t*)(p + on * 8) = pack2_bf16(o[on][0], o[on][1]);
        }
        int ihi = ilo + 8;
        if (ihi < 49) {
            __nv_bfloat16* p = out + (size_t)(wbase + ihi) * 256 + h * 32 + q2;
#pragma unroll
            for (int on = 0; on < 4; on++)
                *(uint32_t*)(p + on * 8) = pack2_bf16(o[on][2], o[on][3]);
        }
    }
}

// ---------------------------------------------------------------------------
// Host launcher (graph-capturable: kernel launches only)
// ---------------------------------------------------------------------------
extern "C" void kernel_launch(void* const* d_in, const int* in_sizes, int n_in,
                              void* d_out, int out_size) {
    (void)in_sizes; (void)n_in; (void)out_size;

    const float* x          = (const float*)d_in[0];
    const float* n1g        = (const float*)d_in[1];
    const float* n1b        = (const float*)d_in[2];
    const float* qkv_w      = (const float*)d_in[3];
    const float* qkv_b      = (const float*)d_in[4];
    const float* proj_w     = (const float*)d_in[5];
    const float* proj_b     = (const float*)d_in[6];
    const float* bias_table = (const float*)d_in[7];
    const float* n2g        = (const float*)d_in[8];
    const float* n2b        = (const float*)d_in[9];
    const float* w1         = (const float*)d_in[10];
    const float* b1         = (const float*)d_in[11];
    const float* w2         = (const float*)d_in[12];
    const float* b2         = (const float*)d_in[13];
    float* out = (float*)d_out;

    __nv_bfloat16 *ywin, *qkvb, *attnb, *h2, *act, *wbf;
    float *x1;
    cudaGetSymbolAddress((void**)&ywin,  g_ywin);
    cudaGetSymbolAddress((void**)&qkvb,  g_qkv);
    cudaGetSymbolAddress((void**)&attnb, g_attn);
    cudaGetSymbolAddress((void**)&x1,    g_x1);
    cudaGetSymbolAddress((void**)&h2,    g_h2);
    cudaGetSymbolAddress((void**)&act,   g_act);
    cudaGetSymbolAddress((void**)&wbf,   g_wbf);

    const int lnBlocks = NROWS / 8;

    // 0) weights -> bf16
    wconv_kernel<<<768, 1024>>>(qkv_w, proj_w, w1, w2, wbf);
    // 1) LN1 + cyclic shift + window partition -> bf16
    ln_kernel<true><<<lnBlocks, 256>>>(x, n1g, n1b, ywin);
    // 2) QKV: [100352,256] @ [256,768] -> bf16
    gemm_bf16<EPI_BIAS, true><<<dim3(784, 6), 256>>>(ywin, wbf + WOFF_QKV, qkv_b,
                                                     qkvb, nullptr, 768, 256);
    // 3) windowed attention (tensor cores) -> bf16
    attn_tc<<<NWIN * 4, 64>>>(qkvb, bias_table, attnb);
    // 4) proj + window-reverse + un-shift + residual -> x1 (fp32)
    gemm_bf16<EPI_PROJ, false><<<dim3(784, 2), 256>>>(attnb, wbf + WOFF_PROJ, proj_b,
                                                      x1, x, 256, 256);
    // 5) LN2 -> bf16
    ln_kernel<false><<<lnBlocks, 256>>>(x1, n2g, n2b, h2);
    // 6) MLP up + GELU: [100352,256] @ [256,1024] -> bf16
    gemm_bf16<EPI_GELU, true><<<dim3(784, 8), 256>>>(h2, wbf + WOFF_W1, b1,
                                                     act, nullptr, 1024, 256);
    // 7) MLP down + residual -> d_out (fp32): [100352,1024] @ [1024,256]
    gemm_bf16<EPI_MLP2, false><<<dim3(784, 2), 256>>>(act, wbf + WOFF_W2, b2,
                                                      out, x1, 256, 1024);
}

// round 8
// speedup vs baseline: 4.7506x; 1.0377x over previous
#include <cuda_runtime.h>
#include <cuda_bf16.h>
#include <cstddef>
#include <cstdint>

// ---------------------------------------------------------------------------
// Problem constants
// ---------------------------------------------------------------------------
#define NROWS   100352            // 32 * 56 * 56 tokens
#define NWIN    2048              // 32 * 64 windows
#define SCALE_Q 0.17677669529663689f   // 32^-0.5

// ---------------------------------------------------------------------------
// Scratch (static __device__ arrays; allocation is forbidden)
// ---------------------------------------------------------------------------
__device__ __align__(16) __nv_bfloat16 g_ywin[100352 * 256];   // LN1 out (win order)
__device__ __align__(16) __nv_bfloat16 g_qkv [100352 * 768];   // qkv, bf16
__device__ __align__(16) __nv_bfloat16 g_attn[100352 * 256];   // attention out
__device__ float                       g_x1  [100352 * 256];   // shortcut + proj
__device__ __align__(16) __nv_bfloat16 g_h2  [100352 * 256];   // LN2 out
__device__ __align__(16) __nv_bfloat16 g_act [100352 * 1024];  // gelu(mlp1)
__device__ __align__(16) __nv_bfloat16 g_wbf [786432];         // all 4 weights, bf16

#define WOFF_QKV  0
#define WOFF_PROJ 196608
#define WOFF_W1   262144
#define WOFF_W2   524288

// ---------------------------------------------------------------------------
// window-order row <-> x-order row mapping (shift = 3, 8x8 windows of 7x7)
// ---------------------------------------------------------------------------
__device__ __forceinline__ int win_to_x_row(int m) {
    int w  = m / 49;
    int t  = m - w * 49;
    int b  = w >> 6;
    int wi = w & 63;
    int tr = t / 7;
    int tc = t - tr * 7;
    int gr = ((wi >> 3) * 7) + tr;
    int gc = ((wi & 7) * 7) + tc;
    int r = gr + 3; if (r >= 56) r -= 56;
    int c = gc + 3; if (c >= 56) c -= 56;
    return b * 3136 + r * 56 + c;
}

__device__ __forceinline__ float gelu_tanh(float x) {
    float x3 = x * x * x;
    return 0.5f * x * (1.0f + tanhf(0.7978845608028654f * (x + 0.044715f * x3)));
}

__device__ __forceinline__ uint2 pack4_bf16(float4 v) {
    __nv_bfloat162 lo = __floats2bfloat162_rn(v.x, v.y);
    __nv_bfloat162 hi = __floats2bfloat162_rn(v.z, v.w);
    uint2 r;
    r.x = *(uint32_t*)&lo;
    r.y = *(uint32_t*)&hi;
    return r;
}

__device__ __forceinline__ uint32_t pack2_bf16(float a, float b) {
    __nv_bfloat162 t = __floats2bfloat162_rn(a, b);
    return *(uint32_t*)&t;
}

// ---------------------------------------------------------------------------
// PTX helpers
// ---------------------------------------------------------------------------
__device__ __forceinline__ void ldsm4(uint32_t r[4], const void* p) {
    uint32_t a = (uint32_t)__cvta_generic_to_shared(p);
    asm("ldmatrix.sync.aligned.m8n8.x4.shared.b16 {%0,%1,%2,%3}, [%4];"
        : "=r"(r[0]), "=r"(r[1]), "=r"(r[2]), "=r"(r[3]) : "r"(a) : "memory");
}
__device__ __forceinline__ void ldsm4t(uint32_t r[4], const void* p) {
    uint32_t a = (uint32_t)__cvta_generic_to_shared(p);
    asm("ldmatrix.sync.aligned.m8n8.x4.trans.shared.b16 {%0,%1,%2,%3}, [%4];"
        : "=r"(r[0]), "=r"(r[1]), "=r"(r[2]), "=r"(r[3]) : "r"(a) : "memory");
}
__device__ __forceinline__ void mma_bf16(float c[4], const uint32_t a[4],
                                         uint32_t b0, uint32_t b1) {
    asm("mma.sync.aligned.m16n8k16.row.col.f32.bf16.bf16.f32 "
        "{%0,%1,%2,%3}, {%4,%5,%6,%7}, {%8,%9}, {%0,%1,%2,%3};"
        : "+f"(c[0]), "+f"(c[1]), "+f"(c[2]), "+f"(c[3])
        : "r"(a[0]), "r"(a[1]), "r"(a[2]), "r"(a[3]), "r"(b0), "r"(b1));
}
__device__ __forceinline__ void cpasync16(void* dst, const void* src) {
    uint32_t d = (uint32_t)__cvta_generic_to_shared(dst);
    asm volatile("cp.async.cg.shared.global [%0], [%1], 16;" :: "r"(d), "l"(src));
}
__device__ __forceinline__ void cp_commit() {
    asm volatile("cp.async.commit_group;");
}
template <int N>
__device__ __forceinline__ void cp_wait() {
    asm volatile("cp.async.wait_group %0;" :: "n"(N));
}

// ---------------------------------------------------------------------------
// Weight conversion: fp32 -> bf16, once per launch
// ---------------------------------------------------------------------------
__global__ void __launch_bounds__(1024) wconv_kernel(const float* __restrict__ qkv_w,
                                                     const float* __restrict__ proj_w,
                                                     const float* __restrict__ w1,
                                                     const float* __restrict__ w2,
                                                     __nv_bfloat16* __restrict__ dst) {
    int i = blockIdx.x * 1024 + threadIdx.x;   // grid = 768
    float v;
    if      (i < WOFF_PROJ) v = qkv_w[i];
    else if (i < WOFF_W1)   v = proj_w[i - WOFF_PROJ];
    else if (i < WOFF_W2)   v = w1[i - WOFF_W1];
    else                    v = w2[i - WOFF_W2];
    dst[i] = __float2bfloat16(v);
}

// ---------------------------------------------------------------------------
// LayerNorm: one warp per 256-wide row, bf16 output.
// ---------------------------------------------------------------------------
template <bool GATHER>
__global__ void __launch_bounds__(256) ln_kernel(const float* __restrict__ in,
                                                 const float* __restrict__ gamma,
                                                 const float* __restrict__ beta,
                                                 __nv_bfloat16* __restrict__ out) {
    int gw   = (blockIdx.x * blockDim.x + threadIdx.x) >> 5;
    int lane = threadIdx.x & 31;
    if (gw >= NROWS) return;
    int src = GATHER ? win_to_x_row(gw) : gw;

    const float4* row = (const float4*)(in + (size_t)src * 256);
    float4 v0 = row[lane];
    float4 v1 = row[lane + 32];

    float s  = v0.x + v0.y + v0.z + v0.w + v1.x + v1.y + v1.z + v1.w;
    float ss = v0.x*v0.x + v0.y*v0.y + v0.z*v0.z + v0.w*v0.w
             + v1.x*v1.x + v1.y*v1.y + v1.z*v1.z + v1.w*v1.w;
#pragma unroll
    for (int o = 16; o; o >>= 1) {
        s  += __shfl_xor_sync(0xffffffffu, s,  o);
        ss += __shfl_xor_sync(0xffffffffu, ss, o);
    }
    float mu  = s * (1.0f / 256.0f);
    float inv = rsqrtf(ss * (1.0f / 256.0f) - mu * mu + 1e-5f);

    float4 g0 = ((const float4*)gamma)[lane];
    float4 g1 = ((const float4*)gamma)[lane + 32];
    float4 b0 = ((const float4*)beta)[lane];
    float4 b1 = ((const float4*)beta)[lane + 32];

    float4 o0, o1;
    o0.x = (v0.x - mu) * inv * g0.x + b0.x;
    o0.y = (v0.y - mu) * inv * g0.y + b0.y;
    o0.z = (v0.z - mu) * inv * g0.z + b0.z;
    o0.w = (v0.w - mu) * inv * g0.w + b0.w;
    o1.x = (v1.x - mu) * inv * g1.x + b1.x;
    o1.y = (v1.y - mu) * inv * g1.y + b1.y;
    o1.z = (v1.z - mu) * inv * g1.z + b1.z;
    o1.w = (v1.w - mu) * inv * g1.w + b1.w;

    uint2* orow = (uint2*)(out + (size_t)gw * 256);
    orow[lane]      = pack4_bf16(o0);
    orow[lane + 32] = pack4_bf16(o1);
}

// ---------------------------------------------------------------------------
// bf16 tensor-core GEMM, 4-stage cp.async pipeline.
// BM=BN=128, BK=32, 256 threads = 8 warps (4m x 2n), warp tile 32x64.
// A smem [m][k] stride 40 bf16; B smem [k][n] stride 136 bf16 (conflict-free).
// Per iter: cp.async.wait_group 2 (only blocks if load from 3 iters ago is
// late) + one __syncthreads. Dynamic smem: 4 stages x (10240 + 8704) B = 74 KB.
// ---------------------------------------------------------------------------
#define EPI_BIAS 0
#define EPI_GELU 1
#define EPI_PROJ 2
#define EPI_MLP2 3

#define AS 40
#define BSS 136
#define A_STG (128 * AS)            // 5120 elems / stage
#define B_STG (32 * BSS)            // 4352 elems / stage
#define GEMM_SMEM ((4 * A_STG + 4 * B_STG) * 2)   // 75776 bytes

template <int EPI, bool OUT_BF16>
__global__ void __launch_bounds__(256) gemm_bf16(const __nv_bfloat16* __restrict__ A,
                                                 const __nv_bfloat16* __restrict__ B,
                                                 const float* __restrict__ bias,
                                                 void* __restrict__ Cout,
                                                 const float* __restrict__ res,
                                                 int N, int K) {
    extern __shared__ __align__(16) __nv_bfloat16 smp[];
    __nv_bfloat16* Asm = smp;                 // 4 stages
    __nv_bfloat16* Bsm = smp + 4 * A_STG;     // 4 stages

    const int tid  = threadIdx.x;
    const int lane = tid & 31;
    const int wid  = tid >> 5;
    const int bm   = blockIdx.x * 128;
    const int bn   = blockIdx.y * 128;
    const int wm   = (wid & 3) * 32;
    const int wn   = (wid >> 2) * 64;

    const __nv_bfloat16* Ab = A + (size_t)bm * K;
    const __nv_bfloat16* Bb = B + bn;

    float acc[2][8][4] = {};

    auto load_tile = [&](int k0, int stg) {
        __nv_bfloat16* as = Asm + stg * A_STG;
        __nv_bfloat16* bs = Bsm + stg * B_STG;
#pragma unroll
        for (int i = 0; i < 2; i++) {
            int c = tid + i * 256;
            int row = c >> 2, kc = (c & 3) * 8;
            cpasync16(&as[row * AS + kc], Ab + (size_t)row * K + k0 + kc);
        }
#pragma unroll
        for (int i = 0; i < 2; i++) {
            int c = tid + i * 256;
            int k = c >> 4, n = (c & 15) * 8;
            cpasync16(&bs[k * BSS + n], Bb + (size_t)(k0 + k) * N + n);
        }
        cp_commit();
    };

    const int nIter = K >> 5;
    load_tile(0, 0);
    load_tile(32, 1);
    load_tile(64, 2);

    for (int i = 0; i < nIter; i++) {
        cp_wait<2>();
        __syncthreads();
        if (i + 3 < nIter) load_tile((i + 3) * 32, (i + 3) & 3);

        const __nv_bfloat16* as = Asm + (i & 3) * A_STG;
        const __nv_bfloat16* bs = Bsm + (i & 3) * B_STG;
#pragma unroll
        for (int ks = 0; ks < 32; ks += 16) {
            uint32_t af[2][4];
#pragma unroll
            for (int mi = 0; mi < 2; mi++)
                ldsm4(af[mi], as + (wm + mi * 16 + (lane & 15)) * AS
                                 + ks + (lane >> 4) * 8);
#pragma unroll
            for (int np = 0; np < 4; np++) {
                uint32_t bf[4];
                ldsm4t(bf, bs + (ks + (lane & 7) + ((lane >> 3) & 1) * 8) * BSS
                              + wn + np * 16 + (lane >> 4) * 8);
                mma_bf16(acc[0][np * 2 + 0], af[0], bf[0], bf[1]);
                mma_bf16(acc[1][np * 2 + 0], af[1], bf[0], bf[1]);
                mma_bf16(acc[0][np * 2 + 1], af[0], bf[2], bf[3]);
                mma_bf16(acc[1][np * 2 + 1], af[1], bf[2], bf[3]);
            }
        }
    }

    // ---------------- epilogue ----------------
    float bv0[8], bv1[8];
#pragma unroll
    for (int ni = 0; ni < 8; ni++) {
        int c = bn + wn + ni * 8 + 2 * (lane & 3);
        bv0[ni] = bias[c];
        bv1[ni] = bias[c + 1];
    }

#pragma unroll
    for (int mi = 0; mi < 2; mi++) {
#pragma unroll
        for (int half = 0; half < 2; half++) {
            int r = bm + wm + mi * 16 + (lane >> 2) + half * 8;
            size_t rowoff;
            if (EPI == EPI_PROJ) rowoff = (size_t)win_to_x_row(r) * N;
            else                 rowoff = (size_t)r * N;
#pragma unroll
            for (int ni = 0; ni < 8; ni++) {
                int c = bn + wn + ni * 8 + 2 * (lane & 3);
                float v0 = acc[mi][ni][half * 2 + 0] + bv0[ni];
                float v1 = acc[mi][ni][half * 2 + 1] + bv1[ni];
                if (EPI == EPI_GELU) { v0 = gelu_tanh(v0); v1 = gelu_tanh(v1); }
                if (EPI == EPI_PROJ || EPI == EPI_MLP2) {
                    float2 rr = *(const float2*)(res + rowoff + c);
                    v0 += rr.x; v1 += rr.y;
                }
                if (OUT_BF16) {
                    __nv_bfloat162 w = __floats2bfloat162_rn(v0, v1);
                    *(__nv_bfloat162*)((__nv_bfloat16*)Cout + rowoff + c) = w;
                } else {
                    float2 w = {v0, v1};
                    *(float2*)((float*)Cout + rowoff + c) = w;
                }
            }
        }
    }
}

// ---------------------------------------------------------------------------
// Tensor-core windowed attention (verified in R4).
// One WARP per (window, head); tokens padded 49 -> 64.
// ---------------------------------------------------------------------------
#define ATS 40

__global__ void __launch_bounds__(64) attn_tc(const __nv_bfloat16* __restrict__ qkv,
                                              const float* __restrict__ bias_table,
                                              __nv_bfloat16* __restrict__ out) {
    __shared__ __align__(16) __nv_bfloat16 sQ[2][64 * ATS];
    __shared__ __align__(16) __nv_bfloat16 sK[2][64 * ATS];
    __shared__ __align__(16) __nv_bfloat16 sV[2][64 * ATS];
    __shared__ float sB[2][169];
    __shared__ int   sInfo[64];

    const int w     = blockIdx.x >> 2;
    const int wp    = threadIdx.x >> 5;
    const int lane  = threadIdx.x & 31;
    const int h     = (blockIdx.x & 3) * 2 + wp;
    const int wbase = w * 49;
    const int wi    = w & 63;

    if (threadIdx.x < 64) {
        int j = threadIdx.x;
        int info;
        if (j < 49) {
            int rj = j / 7, cj = j - (j / 7) * 7;
            int gr = (wi >> 3) * 7 + rj;
            int gc = (wi & 7) * 7 + cj;
            int rh = (gr < 49) ? 0 : ((gr < 53) ? 1 : 2);
            int rc = (gc < 49) ? 0 : ((gc < 53) ? 1 : 2);
            int key = rj + 13 * cj;
            info = key | ((rh * 3 + rc) << 8) | (1 << 16);
        } else {
            info = 0 | (255 << 8);
        }
        sInfo[j] = info;
    }

    for (int idx = lane; idx < 169; idx += 32) sB[wp][idx] = bias_table[idx * 8 + h];

    for (int tsk = lane; tsk < 256; tsk += 32) {
        int row = tsk >> 2, seg = (tsk & 3) * 8;
        uint4 q4, k4, v4;
        if (row < 49) {
            const __nv_bfloat16* base = qkv + (size_t)(wbase + row) * 768 + h * 32 + seg;
            q4 = *(const uint4*)base;
            k4 = *(const uint4*)(base + 256);
            v4 = *(const uint4*)(base + 512);
        } else {
            q4 = make_uint4(0, 0, 0, 0); k4 = q4; v4 = q4;
        }
        int off = row * ATS + seg;
        *(uint4*)&sQ[wp][off] = q4;
        *(uint4*)&sK[wp][off] = k4;
        *(uint4*)&sV[wp][off] = v4;
    }
    __syncthreads();

    uint32_t kf[2][4][4];
#pragma unroll
    for (int ks = 0; ks < 2; ks++)
#pragma unroll
        for (int nt = 0; nt < 4; nt++)
            ldsm4(kf[ks][nt], &sK[wp][(nt * 16 + (lane & 7) + ((lane >> 4) & 1) * 8) * ATS
                                      + ks * 16 + ((lane >> 3) & 1) * 8]);

    const int q2 = 2 * (lane & 3);
    int jinfo[16];
#pragma unroll
    for (int u = 0; u < 8; u++) {
        jinfo[u * 2 + 0] = sInfo[u * 8 + q2 + 0];
        jinfo[u * 2 + 1] = sInfo[u * 8 + q2 + 1];
    }

    const int r = lane >> 2;

#pragma unroll
    for (int mt = 0; mt < 4; mt++) {
        uint32_t qf[2][4];
#pragma unroll
        for (int ks = 0; ks < 2; ks++)
            ldsm4(qf[ks], &sQ[wp][(mt * 16 + (lane & 15)) * ATS
                                  + ks * 16 + (lane >> 4) * 8]);

        float c[8][4] = {};
#pragma unroll
        for (int nt = 0; nt < 4; nt++) {
#pragma unroll
            for (int ks = 0; ks < 2; ks++) {
                mma_bf16(c[2 * nt + 0], qf[ks], kf[ks][nt][0], kf[ks][nt][1]);
                mma_bf16(c[2 * nt + 1], qf[ks], kf[ks][nt][2], kf[ks][nt][3]);
            }
        }

        int ilo = mt * 16 + r;
        int infLo = sInfo[ilo], infHi = sInfo[ilo + 8];
        int keyLo = (infLo & 255) + 84, regLo = (infLo >> 8) & 255;
        int keyHi = (infHi & 255) + 84, regHi = (infHi >> 8) & 255;

        float sumLo = 0.0f, sumHi = 0.0f;
#pragma unroll
        for (int u = 0; u < 8; u++) {
#pragma unroll
            for (int e = 0; e < 2; e++) {
                int inf = jinfo[u * 2 + e];
                float pLo, pHi;
                if (inf & 0x10000) {
                    int kj = inf & 255;
                    int rj = (inf >> 8) & 255;
                    float aLo = fmaf(c[u][e], SCALE_Q, sB[wp][keyLo - kj]);
                    float aHi = fmaf(c[u][2 + e], SCALE_Q, sB[wp][keyHi - kj]);
                    if (rj != regLo) aLo -= 100.0f;
                    if (rj != regHi) aHi -= 100.0f;
                    pLo = __expf(aLo);
                    pHi = __expf(aHi);
                } else {
                    pLo = 0.0f; pHi = 0.0f;
                }
                c[u][e]     = pLo;  sumLo += pLo;
                c[u][2 + e] = pHi;  sumHi += pHi;
            }
        }
        sumLo += __shfl_xor_sync(0xffffffffu, sumLo, 1);
        sumLo += __shfl_xor_sync(0xffffffffu, sumLo, 2);
        sumHi += __shfl_xor_sync(0xffffffffu, sumHi, 1);
        sumHi += __shfl_xor_sync(0xffffffffu, sumHi, 2);
        float dLo = 1.0f / sumLo;
        float dHi = 1.0f / sumHi;

        uint32_t pa[4][4];
#pragma unroll
        for (int t = 0; t < 4; t++) {
            pa[t][0] = pack2_bf16(c[2 * t][0] * dLo,     c[2 * t][1] * dLo);
            pa[t][1] = pack2_bf16(c[2 * t][2] * dHi,     c[2 * t][3] * dHi);
            pa[t][2] = pack2_bf16(c[2 * t + 1][0] * dLo, c[2 * t + 1][1] * dLo);
            pa[t][3] = pack2_bf16(c[2 * t + 1][2] * dHi, c[2 * t + 1][3] * dHi);
        }

        float o[4][4] = {};
#pragma unroll
        for (int ks = 0; ks < 4; ks++) {
            uint32_t vf[2][4];
#pragma unroll
            for (int half = 0; half < 2; half++)
                ldsm4t(vf[half], &sV[wp][(ks * 16 + (lane & 7) + ((lane >> 3) & 1) * 8) * ATS
                                         + half * 16 + (lane >> 4) * 8]);
            mma_bf16(o[0], pa[ks], vf[0][0], vf[0][1]);
            mma_bf16(o[1], pa[ks], vf[0][2], vf[0][3]);
            mma_bf16(o[2], pa[ks], vf[1][0], vf[1][1]);
            mma_bf16(o[3], pa[ks], vf[1][2], vf[1][3]);
        }

        if (ilo < 49) {
            __nv_bfloat16* p = out + (size_t)(wbase + ilo) * 256 + h * 32 + q2;
#pragma unroll
            for (int on = 0; on < 4; on++)
                *(uint32_t*)(p + on * 8) = pack2_bf16(o[on][0], o[on][1]);
        }
        int ihi = ilo + 8;
        if (ihi < 49) {
            __nv_bfloat16* p = out + (size_t)(wbase + ihi) * 256 + h * 32 + q2;
#pragma unroll
            for (int on = 0; on < 4; on++)
                *(uint32_t*)(p + on * 8) = pack2_bf16(o[on][2], o[on][3]);
        }
    }
}

// ---------------------------------------------------------------------------
// Host launcher (graph-capturable: kernel launches only)
// ---------------------------------------------------------------------------
extern "C" void kernel_launch(void* const* d_in, const int* in_sizes, int n_in,
                              void* d_out, int out_size) {
    (void)in_sizes; (void)n_in; (void)out_size;

    const float* x          = (const float*)d_in[0];
    const float* n1g        = (const float*)d_in[1];
    const float* n1b        = (const float*)d_in[2];
    const float* qkv_w      = (const float*)d_in[3];
    const float* qkv_b      = (const float*)d_in[4];
    const float* proj_w     = (const float*)d_in[5];
    const float* proj_b     = (const float*)d_in[6];
    const float* bias_table = (const float*)d_in[7];
    const float* n2g        = (const float*)d_in[8];
    const float* n2b        = (const float*)d_in[9];
    const float* w1         = (const float*)d_in[10];
    const float* b1         = (const float*)d_in[11];
    const float* w2         = (const float*)d_in[12];
    const float* b2         = (const float*)d_in[13];
    float* out = (float*)d_out;

    __nv_bfloat16 *ywin, *qkvb, *attnb, *h2, *act, *wbf;
    float *x1;
    cudaGetSymbolAddress((void**)&ywin,  g_ywin);
    cudaGetSymbolAddress((void**)&qkvb,  g_qkv);
    cudaGetSymbolAddress((void**)&attnb, g_attn);
    cudaGetSymbolAddress((void**)&x1,    g_x1);
    cudaGetSymbolAddress((void**)&h2,    g_h2);
    cudaGetSymbolAddress((void**)&act,   g_act);
    cudaGetSymbolAddress((void**)&wbf,   g_wbf);

    cudaFuncSetAttribute(gemm_bf16<EPI_BIAS, true>,
                         cudaFuncAttributeMaxDynamicSharedMemorySize, GEMM_SMEM);
    cudaFuncSetAttribute(gemm_bf16<EPI_PROJ, false>,
                         cudaFuncAttributeMaxDynamicSharedMemorySize, GEMM_SMEM);
    cudaFuncSetAttribute(gemm_bf16<EPI_GELU, true>,
                         cudaFuncAttributeMaxDynamicSharedMemorySize, GEMM_SMEM);
    cudaFuncSetAttribute(gemm_bf16<EPI_MLP2, false>,
                         cudaFuncAttributeMaxDynamicSharedMemorySize, GEMM_SMEM);

    const int lnBlocks = NROWS / 8;

    // 0) weights -> bf16
    wconv_kernel<<<768, 1024>>>(qkv_w, proj_w, w1, w2, wbf);
    // 1) LN1 + cyclic shift + window partition -> bf16
    ln_kernel<true><<<lnBlocks, 256>>>(x, n1g, n1b, ywin);
    // 2) QKV: [100352,256] @ [256,768] -> bf16
    gemm_bf16<EPI_BIAS, true><<<dim3(784, 6), 256, GEMM_SMEM>>>(ywin, wbf + WOFF_QKV,
                                                                qkv_b, qkvb, nullptr, 768, 256);
    // 3) windowed attention (tensor cores) -> bf16
    attn_tc<<<NWIN * 4, 64>>>(qkvb, bias_table, attnb);
    // 4) proj + window-reverse + un-shift + residual -> x1 (fp32)
    gemm_bf16<EPI_PROJ, false><<<dim3(784, 2), 256, GEMM_SMEM>>>(attnb, wbf + WOFF_PROJ,
                                                                 proj_b, x1, x, 256, 256);
    // 5) LN2 -> bf16
    ln_kernel<false><<<lnBlocks, 256>>>(x1, n2g, n2b, h2);
    // 6) MLP up + GELU: [100352,256] @ [256,1024] -> bf16
    gemm_bf16<EPI_GELU, true><<<dim3(784, 8), 256, GEMM_SMEM>>>(h2, wbf + WOFF_W1,
                                                                b1, act, nullptr, 1024, 256);
    // 7) MLP down + residual -> d_out (fp32): [100352,1024] @ [1024,256]
    gemm_bf16<EPI_MLP2, false><<<dim3(784, 2), 256, GEMM_SMEM>>>(act, wbf + WOFF_W2,
                                                                 b2, out, x1, 256, 1024);
}

// round 9
// speedup vs baseline: 4.8685x; 1.0248x over previous
#include <cuda_runtime.h>
#include <cuda_bf16.h>
#include <cstddef>
#include <cstdint>

// ---------------------------------------------------------------------------
// Problem constants
// ---------------------------------------------------------------------------
#define NROWS   100352            // 32 * 56 * 56 tokens
#define NWIN    2048              // 32 * 64 windows
#define SCALE_Q 0.17677669529663689f   // 32^-0.5

// ---------------------------------------------------------------------------
// Scratch (static __device__ arrays; allocation is forbidden)
// ---------------------------------------------------------------------------
__device__ __align__(16) __nv_bfloat16 g_ywin[100352 * 256];   // LN1 out (win order)
__device__ __align__(16) __nv_bfloat16 g_qkv [100352 * 768];   // qkv, bf16
__device__ __align__(16) __nv_bfloat16 g_attn[100352 * 256];   // attention out
__device__ float                       g_x1  [100352 * 256];   // shortcut + proj
__device__ __align__(16) __nv_bfloat16 g_h2  [100352 * 256];   // LN2 out
__device__ __align__(16) __nv_bfloat16 g_act [100352 * 1024];  // gelu(mlp1)
__device__ __align__(16) __nv_bfloat16 g_wbf [786432];         // all 4 weights, bf16

#define WOFF_QKV  0
#define WOFF_PROJ 196608
#define WOFF_W1   262144
#define WOFF_W2   524288

// ---------------------------------------------------------------------------
// window-order row <-> x-order row mapping (shift = 3, 8x8 windows of 7x7)
// ---------------------------------------------------------------------------
__device__ __forceinline__ int win_to_x_row(int m) {
    int w  = m / 49;
    int t  = m - w * 49;
    int b  = w >> 6;
    int wi = w & 63;
    int tr = t / 7;
    int tc = t - tr * 7;
    int gr = ((wi >> 3) * 7) + tr;
    int gc = ((wi & 7) * 7) + tc;
    int r = gr + 3; if (r >= 56) r -= 56;
    int c = gc + 3; if (c >= 56) c -= 56;
    return b * 3136 + r * 56 + c;
}

__device__ __forceinline__ float gelu_tanh(float x) {
    float x3 = x * x * x;
    return 0.5f * x * (1.0f + tanhf(0.7978845608028654f * (x + 0.044715f * x3)));
}

__device__ __forceinline__ uint2 pack4_bf16(float4 v) {
    __nv_bfloat162 lo = __floats2bfloat162_rn(v.x, v.y);
    __nv_bfloat162 hi = __floats2bfloat162_rn(v.z, v.w);
    uint2 r;
    r.x = *(uint32_t*)&lo;
    r.y = *(uint32_t*)&hi;
    return r;
}

__device__ __forceinline__ uint32_t pack2_bf16(float a, float b) {
    __nv_bfloat162 t = __floats2bfloat162_rn(a, b);
    return *(uint32_t*)&t;
}

// ---------------------------------------------------------------------------
// PTX helpers
// ---------------------------------------------------------------------------
__device__ __forceinline__ void ldsm4(uint32_t r[4], const void* p) {
    uint32_t a = (uint32_t)__cvta_generic_to_shared(p);
    asm("ldmatrix.sync.aligned.m8n8.x4.shared.b16 {%0,%1,%2,%3}, [%4];"
        : "=r"(r[0]), "=r"(r[1]), "=r"(r[2]), "=r"(r[3]) : "r"(a) : "memory");
}
__device__ __forceinline__ void ldsm4t(uint32_t r[4], const void* p) {
    uint32_t a = (uint32_t)__cvta_generic_to_shared(p);
    asm("ldmatrix.sync.aligned.m8n8.x4.trans.shared.b16 {%0,%1,%2,%3}, [%4];"
        : "=r"(r[0]), "=r"(r[1]), "=r"(r[2]), "=r"(r[3]) : "r"(a) : "memory");
}
__device__ __forceinline__ void mma_bf16(float c[4], const uint32_t a[4],
                                         uint32_t b0, uint32_t b1) {
    asm("mma.sync.aligned.m16n8k16.row.col.f32.bf16.bf16.f32 "
        "{%0,%1,%2,%3}, {%4,%5,%6,%7}, {%8,%9}, {%0,%1,%2,%3};"
        : "+f"(c[0]), "+f"(c[1]), "+f"(c[2]), "+f"(c[3])
        : "r"(a[0]), "r"(a[1]), "r"(a[2]), "r"(a[3]), "r"(b0), "r"(b1));
}
__device__ __forceinline__ void cpasync16(void* dst, const void* src) {
    uint32_t d = (uint32_t)__cvta_generic_to_shared(dst);
    asm volatile("cp.async.cg.shared.global [%0], [%1], 16;" :: "r"(d), "l"(src));
}
__device__ __forceinline__ void cp_commit() {
    asm volatile("cp.async.commit_group;");
}
template <int N>
__device__ __forceinline__ void cp_wait() {
    asm volatile("cp.async.wait_group %0;" :: "n"(N));
}

// ---------------------------------------------------------------------------
// Weight conversion: fp32 -> bf16, once per launch
// ---------------------------------------------------------------------------
__global__ void __launch_bounds__(1024) wconv_kernel(const float* __restrict__ qkv_w,
                                                     const float* __restrict__ proj_w,
                                                     const float* __restrict__ w1,
                                                     const float* __restrict__ w2,
                                                     __nv_bfloat16* __restrict__ dst) {
    int i = blockIdx.x * 1024 + threadIdx.x;   // grid = 768
    float v;
    if      (i < WOFF_PROJ) v = qkv_w[i];
    else if (i < WOFF_W1)   v = proj_w[i - WOFF_PROJ];
    else if (i < WOFF_W2)   v = w1[i - WOFF_W1];
    else                    v = w2[i - WOFF_W2];
    dst[i] = __float2bfloat16(v);
}

// ---------------------------------------------------------------------------
// LayerNorm: one warp per 256-wide row, bf16 output.
// ---------------------------------------------------------------------------
template <bool GATHER>
__global__ void __launch_bounds__(256) ln_kernel(const float* __restrict__ in,
                                                 const float* __restrict__ gamma,
                                                 const float* __restrict__ beta,
                                                 __nv_bfloat16* __restrict__ out) {
    int gw   = (blockIdx.x * blockDim.x + threadIdx.x) >> 5;
    int lane = threadIdx.x & 31;
    if (gw >= NROWS) return;
    int src = GATHER ? win_to_x_row(gw) : gw;

    const float4* row = (const float4*)(in + (size_t)src * 256);
    float4 v0 = row[lane];
    float4 v1 = row[lane + 32];

    float s  = v0.x + v0.y + v0.z + v0.w + v1.x + v1.y + v1.z + v1.w;
    float ss = v0.x*v0.x + v0.y*v0.y + v0.z*v0.z + v0.w*v0.w
             + v1.x*v1.x + v1.y*v1.y + v1.z*v1.z + v1.w*v1.w;
#pragma unroll
    for (int o = 16; o; o >>= 1) {
        s  += __shfl_xor_sync(0xffffffffu, s,  o);
        ss += __shfl_xor_sync(0xffffffffu, ss, o);
    }
    float mu  = s * (1.0f / 256.0f);
    float inv = rsqrtf(ss * (1.0f / 256.0f) - mu * mu + 1e-5f);

    float4 g0 = ((const float4*)gamma)[lane];
    float4 g1 = ((const float4*)gamma)[lane + 32];
    float4 b0 = ((const float4*)beta)[lane];
    float4 b1 = ((const float4*)beta)[lane + 32];

    float4 o0, o1;
    o0.x = (v0.x - mu) * inv * g0.x + b0.x;
    o0.y = (v0.y - mu) * inv * g0.y + b0.y;
    o0.z = (v0.z - mu) * inv * g0.z + b0.z;
    o0.w = (v0.w - mu) * inv * g0.w + b0.w;
    o1.x = (v1.x - mu) * inv * g1.x + b1.x;
    o1.y = (v1.y - mu) * inv * g1.y + b1.y;
    o1.z = (v1.z - mu) * inv * g1.z + b1.z;
    o1.w = (v1.w - mu) * inv * g1.w + b1.w;

    uint2* orow = (uint2*)(out + (size_t)gw * 256);
    orow[lane]      = pack4_bf16(o0);
    orow[lane + 32] = pack4_bf16(o1);
}

// ---------------------------------------------------------------------------
// bf16 tensor-core GEMM, BK=64, 3-stage cp.async pipeline.
// BM=BN=128, 256 threads = 8 warps (4m x 2n), warp tile 32x64.
// A smem [m][k] stride 72 bf16 (row pitch 144B -> banks 4m mod 32, conflict-
// free); B smem [k][n] stride 136 bf16 (row pitch 272B -> 4k mod 32).
// One __syncthreads per 64-K chunk (64 HMMAs). Exact wait-group bounds:
// at iter i, tiles issued = min(nIter, i+2); tile i complete requires
// pending <= issued-(i+1) = 1 while i+1 < nIter, else 0.
// Dynamic smem: 3 x (18432 + 17408) = 107520 B; 2 blocks/SM = 215 KB.
// ---------------------------------------------------------------------------
#define EPI_BIAS 0
#define EPI_GELU 1
#define EPI_PROJ 2
#define EPI_MLP2 3

#define AS 72
#define BSS 136
#define A_STG (128 * AS)            // 9216 elems / stage
#define B_STG (64 * BSS)            // 8704 elems / stage
#define GEMM_SMEM ((3 * A_STG + 3 * B_STG) * 2)   // 107520 bytes

template <int EPI, bool OUT_BF16>
__global__ void __launch_bounds__(256) gemm_bf16(const __nv_bfloat16* __restrict__ A,
                                                 const __nv_bfloat16* __restrict__ B,
                                                 const float* __restrict__ bias,
                                                 void* __restrict__ Cout,
                                                 const float* __restrict__ res,
                                                 int N, int K) {
    extern __shared__ __align__(16) __nv_bfloat16 smp[];
    __nv_bfloat16* Asm = smp;                 // 3 stages
    __nv_bfloat16* Bsm = smp + 3 * A_STG;     // 3 stages

    const int tid  = threadIdx.x;
    const int lane = tid & 31;
    const int wid  = tid >> 5;
    const int bm   = blockIdx.x * 128;
    const int bn   = blockIdx.y * 128;
    const int wm   = (wid & 3) * 32;
    const int wn   = (wid >> 2) * 64;

    const __nv_bfloat16* Ab = A + (size_t)bm * K;
    const __nv_bfloat16* Bb = B + bn;

    float acc[2][8][4] = {};

    // one 64-wide K chunk: A 128x64, B 64x128; 8 x 16B cp.async per thread
    auto load_tile = [&](int k0, int stg) {
        __nv_bfloat16* as = Asm + stg * A_STG;
        __nv_bfloat16* bs = Bsm + stg * B_STG;
#pragma unroll
        for (int i = 0; i < 4; i++) {
            int c = tid + i * 256;              // 0..1023
            int row = c >> 3, kc = (c & 7) * 8;
            cpasync16(&as[row * AS + kc], Ab + (size_t)row * K + k0 + kc);
        }
#pragma unroll
        for (int i = 0; i < 4; i++) {
            int c = tid + i * 256;              // 0..1023
            int k = c >> 4, n = (c & 15) * 8;
            cpasync16(&bs[k * BSS + n], Bb + (size_t)(k0 + k) * N + n);
        }
        cp_commit();
    };

    const int nIter = K >> 6;                   // K/64 (K in {256,1024})
    load_tile(0, 0);
    load_tile(64, 1);

    for (int i = 0; i < nIter; i++) {
        if (i + 1 < nIter) cp_wait<1>(); else cp_wait<0>();
        __syncthreads();
        if (i + 2 < nIter) load_tile((i + 2) * 64, (i + 2) % 3);

        const __nv_bfloat16* as = Asm + (i % 3) * A_STG;
        const __nv_bfloat16* bs = Bsm + (i % 3) * B_STG;
#pragma unroll
        for (int ks = 0; ks < 64; ks += 16) {
            uint32_t af[2][4];
#pragma unroll
            for (int mi = 0; mi < 2; mi++)
                ldsm4(af[mi], as + (wm + mi * 16 + (lane & 15)) * AS
                                 + ks + (lane >> 4) * 8);
#pragma unroll
            for (int np = 0; np < 4; np++) {
                uint32_t bf[4];
                ldsm4t(bf, bs + (ks + (lane & 7) + ((lane >> 3) & 1) * 8) * BSS
                              + wn + np * 16 + (lane >> 4) * 8);
                mma_bf16(acc[0][np * 2 + 0], af[0], bf[0], bf[1]);
                mma_bf16(acc[1][np * 2 + 0], af[1], bf[0], bf[1]);
                mma_bf16(acc[0][np * 2 + 1], af[0], bf[2], bf[3]);
                mma_bf16(acc[1][np * 2 + 1], af[1], bf[2], bf[3]);
            }
        }
    }

    // ---------------- epilogue ----------------
    float bv0[8], bv1[8];
#pragma unroll
    for (int ni = 0; ni < 8; ni++) {
        int c = bn + wn + ni * 8 + 2 * (lane & 3);
        bv0[ni] = bias[c];
        bv1[ni] = bias[c + 1];
    }

#pragma unroll
    for (int mi = 0; mi < 2; mi++) {
#pragma unroll
        for (int half = 0; half < 2; half++) {
            int r = bm + wm + mi * 16 + (lane >> 2) + half * 8;
            size_t rowoff;
            if (EPI == EPI_PROJ) rowoff = (size_t)win_to_x_row(r) * N;
            else                 rowoff = (size_t)r * N;
#pragma unroll
            for (int ni = 0; ni < 8; ni++) {
                int c = bn + wn + ni * 8 + 2 * (lane & 3);
                float v0 = acc[mi][ni][half * 2 + 0] + bv0[ni];
                float v1 = acc[mi][ni][half * 2 + 1] + bv1[ni];
                if (EPI == EPI_GELU) { v0 = gelu_tanh(v0); v1 = gelu_tanh(v1); }
                if (EPI == EPI_PROJ || EPI == EPI_MLP2) {
                    float2 rr = *(const float2*)(res + rowoff + c);
                    v0 += rr.x; v1 += rr.y;
                }
                if (OUT_BF16) {
                    __nv_bfloat162 w = __floats2bfloat162_rn(v0, v1);
                    *(__nv_bfloat162*)((__nv_bfloat16*)Cout + rowoff + c) = w;
                } else {
                    float2 w = {v0, v1};
                    *(float2*)((float*)Cout + rowoff + c) = w;
                }
            }
        }
    }
}

// ---------------------------------------------------------------------------
// Tensor-core windowed attention (verified in R4; unchanged).
// One WARP per (window, head); tokens padded 49 -> 64.
// ---------------------------------------------------------------------------
#define ATS 40

__global__ void __launch_bounds__(64) attn_tc(const __nv_bfloat16* __restrict__ qkv,
                                              const float* __restrict__ bias_table,
                                              __nv_bfloat16* __restrict__ out) {
    __shared__ __align__(16) __nv_bfloat16 sQ[2][64 * ATS];
    __shared__ __align__(16) __nv_bfloat16 sK[2][64 * ATS];
    __shared__ __align__(16) __nv_bfloat16 sV[2][64 * ATS];
    __shared__ float sB[2][169];
    __shared__ int   sInfo[64];

    const int w     = blockIdx.x >> 2;
    const int wp    = threadIdx.x >> 5;
    const int lane  = threadIdx.x & 31;
    const int h     = (blockIdx.x & 3) * 2 + wp;
    const int wbase = w * 49;
    const int wi    = w & 63;

    if (threadIdx.x < 64) {
        int j = threadIdx.x;
        int info;
        if (j < 49) {
            int rj = j / 7, cj = j - (j / 7) * 7;
            int gr = (wi >> 3) * 7 + rj;
            int gc = (wi & 7) * 7 + cj;
            int rh = (gr < 49) ? 0 : ((gr < 53) ? 1 : 2);
            int rc = (gc < 49) ? 0 : ((gc < 53) ? 1 : 2);
            int key = rj + 13 * cj;
            info = key | ((rh * 3 + rc) << 8) | (1 << 16);
        } else {
            info = 0 | (255 << 8);
        }
        sInfo[j] = info;
    }

    for (int idx = lane; idx < 169; idx += 32) sB[wp][idx] = bias_table[idx * 8 + h];

    for (int tsk = lane; tsk < 256; tsk += 32) {
        int row = tsk >> 2, seg = (tsk & 3) * 8;
        uint4 q4, k4, v4;
        if (row < 49) {
            const __nv_bfloat16* base = qkv + (size_t)(wbase + row) * 768 + h * 32 + seg;
            q4 = *(const uint4*)base;
            k4 = *(const uint4*)(base + 256);
            v4 = *(const uint4*)(base + 512);
        } else {
            q4 = make_uint4(0, 0, 0, 0); k4 = q4; v4 = q4;
        }
        int off = row * ATS + seg;
        *(uint4*)&sQ[wp][off] = q4;
        *(uint4*)&sK[wp][off] = k4;
        *(uint4*)&sV[wp][off] = v4;
    }
    __syncthreads();

    uint32_t kf[2][4][4];
#pragma unroll
    for (int ks = 0; ks < 2; ks++)
#pragma unroll
        for (int nt = 0; nt < 4; nt++)
            ldsm4(kf[ks][nt], &sK[wp][(nt * 16 + (lane & 7) + ((lane >> 4) & 1) * 8) * ATS
                                      + ks * 16 + ((lane >> 3) & 1) * 8]);

    const int q2 = 2 * (lane & 3);
    int jinfo[16];
#pragma unroll
    for (int u = 0; u < 8; u++) {
        jinfo[u * 2 + 0] = sInfo[u * 8 + q2 + 0];
        jinfo[u * 2 + 1] = sInfo[u * 8 + q2 + 1];
    }

    const int r = lane >> 2;

#pragma unroll
    for (int mt = 0; mt < 4; mt++) {
        uint32_t qf[2][4];
#pragma unroll
        for (int ks = 0; ks < 2; ks++)
            ldsm4(qf[ks], &sQ[wp][(mt * 16 + (lane & 15)) * ATS
                                  + ks * 16 + (lane >> 4) * 8]);

        float c[8][4] = {};
#pragma unroll
        for (int nt = 0; nt < 4; nt++) {
#pragma unroll
            for (int ks = 0; ks < 2; ks++) {
                mma_bf16(c[2 * nt + 0], qf[ks], kf[ks][nt][0], kf[ks][nt][1]);
                mma_bf16(c[2 * nt + 1], qf[ks], kf[ks][nt][2], kf[ks][nt][3]);
            }
        }

        int ilo = mt * 16 + r;
        int infLo = sInfo[ilo], infHi = sInfo[ilo + 8];
        int keyLo = (infLo & 255) + 84, regLo = (infLo >> 8) & 255;
        int keyHi = (infHi & 255) + 84, regHi = (infHi >> 8) & 255;

        float sumLo = 0.0f, sumHi = 0.0f;
#pragma unroll
        for (int u = 0; u < 8; u++) {
#pragma unroll
            for (int e = 0; e < 2; e++) {
                int inf = jinfo[u * 2 + e];
                float pLo, pHi;
                if (inf & 0x10000) {
                    int kj = inf & 255;
                    int rj = (inf >> 8) & 255;
                    float aLo = fmaf(c[u][e], SCALE_Q, sB[wp][keyLo - kj]);
                    float aHi = fmaf(c[u][2 + e], SCALE_Q, sB[wp][keyHi - kj]);
                    if (rj != regLo) aLo -= 100.0f;
                    if (rj != regHi) aHi -= 100.0f;
                    pLo = __expf(aLo);
                    pHi = __expf(aHi);
                } else {
                    pLo = 0.0f; pHi = 0.0f;
                }
                c[u][e]     = pLo;  sumLo += pLo;
                c[u][2 + e] = pHi;  sumHi += pHi;
            }
        }
        sumLo += __shfl_xor_sync(0xffffffffu, sumLo, 1);
        sumLo += __shfl_xor_sync(0xffffffffu, sumLo, 2);
        sumHi += __shfl_xor_sync(0xffffffffu, sumHi, 1);
        sumHi += __shfl_xor_sync(0xffffffffu, sumHi, 2);
        float dLo = 1.0f / sumLo;
        float dHi = 1.0f / sumHi;

        uint32_t pa[4][4];
#pragma unroll
        for (int t = 0; t < 4; t++) {
            pa[t][0] = pack2_bf16(c[2 * t][0] * dLo,     c[2 * t][1] * dLo);
            pa[t][1] = pack2_bf16(c[2 * t][2] * dHi,     c[2 * t][3] * dHi);
            pa[t][2] = pack2_bf16(c[2 * t + 1][0] * dLo, c[2 * t + 1][1] * dLo);
            pa[t][3] = pack2_bf16(c[2 * t + 1][2] * dHi, c[2 * t + 1][3] * dHi);
        }

        float o[4][4] = {};
#pragma unroll
        for (int ks = 0; ks < 4; ks++) {
            uint32_t vf[2][4];
#pragma unroll
            for (int half = 0; half < 2; half++)
                ldsm4t(vf[half], &sV[wp][(ks * 16 + (lane & 7) + ((lane >> 3) & 1) * 8) * ATS
                                         + half * 16 + (lane >> 4) * 8]);
            mma_bf16(o[0], pa[ks], vf[0][0], vf[0][1]);
            mma_bf16(o[1], pa[ks], vf[0][2], vf[0][3]);
            mma_bf16(o[2], pa[ks], vf[1][0], vf[1][1]);
            mma_bf16(o[3], pa[ks], vf[1][2], vf[1][3]);
        }

        if (ilo < 49) {
            __nv_bfloat16* p = out + (size_t)(wbase + ilo) * 256 + h * 32 + q2;
#pragma unroll
            for (int on = 0; on < 4; on++)
                *(uint32_t*)(p + on * 8) = pack2_bf16(o[on][0], o[on][1]);
        }
        int ihi = ilo + 8;
        if (ihi < 49) {
            __nv_bfloat16* p = out + (size_t)(wbase + ihi) * 256 + h * 32 + q2;
#pragma unroll
            for (int on = 0; on < 4; on++)
                *(uint32_t*)(p + on * 8) = pack2_bf16(o[on][2], o[on][3]);
        }
    }
}

// ---------------------------------------------------------------------------
// Host launcher (graph-capturable: kernel launches only)
// ---------------------------------------------------------------------------
extern "C" void kernel_launch(void* const* d_in, const int* in_sizes, int n_in,
                              void* d_out, int out_size) {
    (void)in_sizes; (void)n_in; (void)out_size;

    const float* x          = (const float*)d_in[0];
    const float* n1g        = (const float*)d_in[1];
    const float* n1b        = (const float*)d_in[2];
    const float* qkv_w      = (const float*)d_in[3];
    const float* qkv_b      = (const float*)d_in[4];
    const float* proj_w     = (const float*)d_in[5];
    const float* proj_b     = (const float*)d_in[6];
    const float* bias_table = (const float*)d_in[7];
    const float* n2g        = (const float*)d_in[8];
    const float* n2b        = (const float*)d_in[9];
    const float* w1         = (const float*)d_in[10];
    const float* b1         = (const float*)d_in[11];
    const float* w2         = (const float*)d_in[12];
    const float* b2         = (const float*)d_in[13];
    float* out = (float*)d_out;

    __nv_bfloat16 *ywin, *qkvb, *attnb, *h2, *act, *wbf;
    float *x1;
    cudaGetSymbolAddress((void**)&ywin,  g_ywin);
    cudaGetSymbolAddress((void**)&qkvb,  g_qkv);
    cudaGetSymbolAddress((void**)&attnb, g_attn);
    cudaGetSymbolAddress((void**)&x1,    g_x1);
    cudaGetSymbolAddress((void**)&h2,    g_h2);
    cudaGetSymbolAddress((void**)&act,   g_act);
    cudaGetSymbolAddress((void**)&wbf,   g_wbf);

    cudaFuncSetAttribute(gemm_bf16<EPI_BIAS, true>,
                         cudaFuncAttributeMaxDynamicSharedMemorySize, GEMM_SMEM);
    cudaFuncSetAttribute(gemm_bf16<EPI_PROJ, false>,
                         cudaFuncAttributeMaxDynamicSharedMemorySize, GEMM_SMEM);
    cudaFuncSetAttribute(gemm_bf16<EPI_GELU, true>,
                         cudaFuncAttributeMaxDynamicSharedMemorySize, GEMM_SMEM);
    cudaFuncSetAttribute(gemm_bf16<EPI_MLP2, false>,
                         cudaFuncAttributeMaxDynamicSharedMemorySize, GEMM_SMEM);

    const int lnBlocks = NROWS / 8;

    // 0) weights -> bf16
    wconv_kernel<<<768, 1024>>>(qkv_w, proj_w, w1, w2, wbf);
    // 1) LN1 + cyclic shift + window partition -> bf16
    ln_kernel<true><<<lnBlocks, 256>>>(x, n1g, n1b, ywin);
    // 2) QKV: [100352,256] @ [256,768] -> bf16
    gemm_bf16<EPI_BIAS, true><<<dim3(784, 6), 256, GEMM_SMEM>>>(ywin, wbf + WOFF_QKV,
                                                                qkv_b, qkvb, nullptr, 768, 256);
    // 3) windowed attention (tensor cores) -> bf16
    attn_tc<<<NWIN * 4, 64>>>(qkvb, bias_table, attnb);
    // 4) proj + window-reverse + un-shift + residual -> x1 (fp32)
    gemm_bf16<EPI_PROJ, false><<<dim3(784, 2), 256, GEMM_SMEM>>>(attnb, wbf + WOFF_PROJ,
                                                                 proj_b, x1, x, 256, 256);
    // 5) LN2 -> bf16
    ln_kernel<false><<<lnBlocks, 256>>>(x1, n2g, n2b, h2);
    // 6) MLP up + GELU: [100352,256] @ [256,1024] -> bf16
    gemm_bf16<EPI_GELU, true><<<dim3(784, 8), 256, GEMM_SMEM>>>(h2, wbf + WOFF_W1,
                                                                b1, act, nullptr, 1024, 256);
    // 7) MLP down + residual -> d_out (fp32): [100352,1024] @ [1024,256]
    gemm_bf16<EPI_MLP2, false><<<dim3(784, 2), 256, GEMM_SMEM>>>(act, wbf + WOFF_W2,
                                                                 b2, out, x1, 256, 1024);
}

// round 10
// speedup vs baseline: 4.9229x; 1.0112x over previous
#include <cuda_runtime.h>
#include <cuda_bf16.h>
#include <cstddef>
#include <cstdint>

// ---------------------------------------------------------------------------
// Problem constants
// ---------------------------------------------------------------------------
#define NROWS   100352            // 32 * 56 * 56 tokens
#define NWIN    2048              // 32 * 64 windows
#define SCALE_Q 0.17677669529663689f   // 32^-0.5

// ---------------------------------------------------------------------------
// Scratch (static __device__ arrays; allocation is forbidden)
// ---------------------------------------------------------------------------
__device__ __align__(16) __nv_bfloat16 g_ywin[100352 * 256];   // LN1 out (win order)
__device__ __align__(16) __nv_bfloat16 g_qkv [100352 * 768];   // qkv, bf16
__device__ __align__(16) __nv_bfloat16 g_attn[100352 * 256];   // attention out
__device__ float                       g_x1  [100352 * 256];   // shortcut + proj
__device__ __align__(16) __nv_bfloat16 g_h2  [100352 * 256];   // LN2 out
__device__ __align__(16) __nv_bfloat16 g_act [100352 * 1024];  // gelu(mlp1)
__device__ __align__(16) __nv_bfloat16 g_wbf [786432];         // all 4 weights, bf16

#define WOFF_QKV  0
#define WOFF_PROJ 196608
#define WOFF_W1   262144
#define WOFF_W2   524288

// ---------------------------------------------------------------------------
// window-order row <-> x-order row mapping (shift = 3, 8x8 windows of 7x7)
// ---------------------------------------------------------------------------
__device__ __forceinline__ int win_to_x_row(int m) {
    int w  = m / 49;
    int t  = m - w * 49;
    int b  = w >> 6;
    int wi = w & 63;
    int tr = t / 7;
    int tc = t - tr * 7;
    int gr = ((wi >> 3) * 7) + tr;
    int gc = ((wi & 7) * 7) + tc;
    int r = gr + 3; if (r >= 56) r -= 56;
    int c = gc + 3; if (c >= 56) c -= 56;
    return b * 3136 + r * 56 + c;
}

__device__ __forceinline__ float gelu_tanh(float x) {
    float x3 = x * x * x;
    return 0.5f * x * (1.0f + tanhf(0.7978845608028654f * (x + 0.044715f * x3)));
}

__device__ __forceinline__ uint2 pack4_bf16(float4 v) {
    __nv_bfloat162 lo = __floats2bfloat162_rn(v.x, v.y);
    __nv_bfloat162 hi = __floats2bfloat162_rn(v.z, v.w);
    uint2 r;
    r.x = *(uint32_t*)&lo;
    r.y = *(uint32_t*)&hi;
    return r;
}

__device__ __forceinline__ uint32_t pack2_bf16(float a, float b) {
    __nv_bfloat162 t = __floats2bfloat162_rn(a, b);
    return *(uint32_t*)&t;
}

// ---------------------------------------------------------------------------
// PTX helpers
// ---------------------------------------------------------------------------
__device__ __forceinline__ void ldsm4(uint32_t r[4], const void* p) {
    uint32_t a = (uint32_t)__cvta_generic_to_shared(p);
    asm("ldmatrix.sync.aligned.m8n8.x4.shared.b16 {%0,%1,%2,%3}, [%4];"
        : "=r"(r[0]), "=r"(r[1]), "=r"(r[2]), "=r"(r[3]) : "r"(a) : "memory");
}
__device__ __forceinline__ void ldsm4t(uint32_t r[4], const void* p) {
    uint32_t a = (uint32_t)__cvta_generic_to_shared(p);
    asm("ldmatrix.sync.aligned.m8n8.x4.trans.shared.b16 {%0,%1,%2,%3}, [%4];"
        : "=r"(r[0]), "=r"(r[1]), "=r"(r[2]), "=r"(r[3]) : "r"(a) : "memory");
}
__device__ __forceinline__ void mma_bf16(float c[4], const uint32_t a[4],
                                         uint32_t b0, uint32_t b1) {
    asm("mma.sync.aligned.m16n8k16.row.col.f32.bf16.bf16.f32 "
        "{%0,%1,%2,%3}, {%4,%5,%6,%7}, {%8,%9}, {%0,%1,%2,%3};"
        : "+f"(c[0]), "+f"(c[1]), "+f"(c[2]), "+f"(c[3])
        : "r"(a[0]), "r"(a[1]), "r"(a[2]), "r"(a[3]), "r"(b0), "r"(b1));
}
__device__ __forceinline__ void cpasync16(void* dst, const void* src) {
    uint32_t d = (uint32_t)__cvta_generic_to_shared(dst);
    asm volatile("cp.async.cg.shared.global [%0], [%1], 16;" :: "r"(d), "l"(src));
}
__device__ __forceinline__ void cp_commit() {
    asm volatile("cp.async.commit_group;");
}
template <int N>
__device__ __forceinline__ void cp_wait() {
    asm volatile("cp.async.wait_group %0;" :: "n"(N));
}

// ---------------------------------------------------------------------------
// Weight conversion: fp32 -> bf16, once per launch
// ---------------------------------------------------------------------------
__global__ void __launch_bounds__(1024) wconv_kernel(const float* __restrict__ qkv_w,
                                                     const float* __restrict__ proj_w,
                                                     const float* __restrict__ w1,
                                                     const float* __restrict__ w2,
                                                     __nv_bfloat16* __restrict__ dst) {
    int i = blockIdx.x * 1024 + threadIdx.x;   // grid = 768
    float v;
    if      (i < WOFF_PROJ) v = qkv_w[i];
    else if (i < WOFF_W1)   v = proj_w[i - WOFF_PROJ];
    else if (i < WOFF_W2)   v = w1[i - WOFF_W1];
    else                    v = w2[i - WOFF_W2];
    dst[i] = __float2bfloat16(v);
}

// ---------------------------------------------------------------------------
// LayerNorm: one warp per 256-wide row, bf16 output.
// ---------------------------------------------------------------------------
template <bool GATHER>
__global__ void __launch_bounds__(256) ln_kernel(const float* __restrict__ in,
                                                 const float* __restrict__ gamma,
                                                 const float* __restrict__ beta,
                                                 __nv_bfloat16* __restrict__ out) {
    int gw   = (blockIdx.x * blockDim.x + threadIdx.x) >> 5;
    int lane = threadIdx.x & 31;
    if (gw >= NROWS) return;
    int src = GATHER ? win_to_x_row(gw) : gw;

    const float4* row = (const float4*)(in + (size_t)src * 256);
    float4 v0 = row[lane];
    float4 v1 = row[lane + 32];

    float s  = v0.x + v0.y + v0.z + v0.w + v1.x + v1.y + v1.z + v1.w;
    float ss = v0.x*v0.x + v0.y*v0.y + v0.z*v0.z + v0.w*v0.w
             + v1.x*v1.x + v1.y*v1.y + v1.z*v1.z + v1.w*v1.w;
#pragma unroll
    for (int o = 16; o; o >>= 1) {
        s  += __shfl_xor_sync(0xffffffffu, s,  o);
        ss += __shfl_xor_sync(0xffffffffu, ss, o);
    }
    float mu  = s * (1.0f / 256.0f);
    float inv = rsqrtf(ss * (1.0f / 256.0f) - mu * mu + 1e-5f);

    float4 g0 = ((const float4*)gamma)[lane];
    float4 g1 = ((const float4*)gamma)[lane + 32];
    float4 b0 = ((const float4*)beta)[lane];
    float4 b1 = ((const float4*)beta)[lane + 32];

    float4 o0, o1;
    o0.x = (v0.x - mu) * inv * g0.x + b0.x;
    o0.y = (v0.y - mu) * inv * g0.y + b0.y;
    o0.z = (v0.z - mu) * inv * g0.z + b0.z;
    o0.w = (v0.w - mu) * inv * g0.w + b0.w;
    o1.x = (v1.x - mu) * inv * g1.x + b1.x;
    o1.y = (v1.y - mu) * inv * g1.y + b1.y;
    o1.z = (v1.z - mu) * inv * g1.z + b1.z;
    o1.w = (v1.w - mu) * inv * g1.w + b1.w;

    uint2* orow = (uint2*)(out + (size_t)gw * 256);
    orow[lane]      = pack4_bf16(o0);
    orow[lane + 32] = pack4_bf16(o1);
}

// ---------------------------------------------------------------------------
// bf16 tensor-core GEMM, BK=64, 3-stage cp.async pipeline,
// register-level fragment double-buffering (A per-ks, B per-step).
// BM=BN=128, 256 threads = 8 warps (4m x 2n), warp tile 32x64.
// A smem [m][k] stride 72; B smem [k][n] stride 136 (conflict-free).
// __launch_bounds__(256, 2) pins regs <= 128 -> 2 blocks/SM preserved.
// ---------------------------------------------------------------------------
#define EPI_BIAS 0
#define EPI_GELU 1
#define EPI_PROJ 2
#define EPI_MLP2 3

#define AS 72
#define BSS 136
#define A_STG (128 * AS)            // 9216 elems / stage
#define B_STG (64 * BSS)            // 8704 elems / stage
#define GEMM_SMEM ((3 * A_STG + 3 * B_STG) * 2)   // 107520 bytes

template <int EPI, bool OUT_BF16>
__global__ void __launch_bounds__(256, 2) gemm_bf16(const __nv_bfloat16* __restrict__ A,
                                                    const __nv_bfloat16* __restrict__ B,
                                                    const float* __restrict__ bias,
                                                    void* __restrict__ Cout,
                                                    const float* __restrict__ res,
                                                    int N, int K) {
    extern __shared__ __align__(16) __nv_bfloat16 smp[];
    __nv_bfloat16* Asm = smp;                 // 3 stages
    __nv_bfloat16* Bsm = smp + 3 * A_STG;     // 3 stages

    const int tid  = threadIdx.x;
    const int lane = tid & 31;
    const int wid  = tid >> 5;
    const int bm   = blockIdx.x * 128;
    const int bn   = blockIdx.y * 128;
    const int wm   = (wid & 3) * 32;
    const int wn   = (wid >> 2) * 64;

    const __nv_bfloat16* Ab = A + (size_t)bm * K;
    const __nv_bfloat16* Bb = B + bn;

    float acc[2][8][4] = {};

    // one 64-wide K chunk: A 128x64, B 64x128; 8 x 16B cp.async per thread
    auto load_tile = [&](int k0, int stg) {
        __nv_bfloat16* as = Asm + stg * A_STG;
        __nv_bfloat16* bs = Bsm + stg * B_STG;
#pragma unroll
        for (int i = 0; i < 4; i++) {
            int c = tid + i * 256;              // 0..1023
            int row = c >> 3, kc = (c & 7) * 8;
            cpasync16(&as[row * AS + kc], Ab + (size_t)row * K + k0 + kc);
        }
#pragma unroll
        for (int i = 0; i < 4; i++) {
            int c = tid + i * 256;              // 0..1023
            int k = c >> 4, n = (c & 15) * 8;
            cpasync16(&bs[k * BSS + n], Bb + (size_t)(k0 + k) * N + n);
        }
        cp_commit();
    };

    const int nIter = K >> 6;                   // K/64 (K in {256,1024})
    load_tile(0, 0);
    load_tile(64, 1);

    // per-warp fragment base offsets (hoisted)
    const int aoff0 = (wm + (lane & 15)) * AS + (lane >> 4) * 8;       // m-tile 0
    const int aoff1 = aoff0 + 16 * AS;                                  // m-tile 1
    const int boff  = ((lane & 7) + ((lane >> 3) & 1) * 8) * BSS
                      + wn + (lane >> 4) * 8;

    for (int i = 0; i < nIter; i++) {
        if (i + 1 < nIter) cp_wait<1>(); else cp_wait<0>();
        __syncthreads();
        if (i + 2 < nIter) load_tile((i + 2) * 64, (i + 2) % 3);

        const __nv_bfloat16* as = Asm + (i % 3) * A_STG;
        const __nv_bfloat16* bs = Bsm + (i % 3) * B_STG;
        const __nv_bfloat16* a0 = as + aoff0;
        const __nv_bfloat16* a1 = as + aoff1;
        const __nv_bfloat16* bp = bs + boff;

        // software-pipelined 16-step body: step s -> ks = (s>>2)*16, np = s&3
        uint32_t af[2][2][4];     // [buf][m-tile]
        uint32_t bf[2][4];        // [buf]
        ldsm4(af[0][0], a0);
        ldsm4(af[0][1], a1);
        ldsm4t(bf[0], bp);
#pragma unroll
        for (int s = 0; s < 16; s++) {
            const int ks = (s >> 2) * 16;
            const int np = s & 3;
            const int ca = (s >> 2) & 1;
            const int cb = s & 1;
            if (np == 2 && ks < 48) {          // prefetch A frags for next ks
                ldsm4(af[ca ^ 1][0], a0 + ks + 16);
                ldsm4(af[ca ^ 1][1], a1 + ks + 16);
            }
            if (s < 15) {                      // prefetch B frag for next step
                const int ns = s + 1;
                ldsm4t(bf[cb ^ 1], bp + ((ns >> 2) * 16) * BSS + (ns & 3) * 16);
            }
            mma_bf16(acc[0][np * 2 + 0], af[ca][0], bf[cb][0], bf[cb][1]);
            mma_bf16(acc[1][np * 2 + 0], af[ca][1], bf[cb][0], bf[cb][1]);
            mma_bf16(acc[0][np * 2 + 1], af[ca][0], bf[cb][2], bf[cb][3]);
            mma_bf16(acc[1][np * 2 + 1], af[ca][1], bf[cb][2], bf[cb][3]);
        }
    }

    // ---------------- epilogue ----------------
    float bv0[8], bv1[8];
#pragma unroll
    for (int ni = 0; ni < 8; ni++) {
        int c = bn + wn + ni * 8 + 2 * (lane & 3);
        bv0[ni] = bias[c];
        bv1[ni] = bias[c + 1];
    }

#pragma unroll
    for (int mi = 0; mi < 2; mi++) {
#pragma unroll
        for (int half = 0; half < 2; half++) {
            int r = bm + wm + mi * 16 + (lane >> 2) + half * 8;
            size_t rowoff;
            if (EPI == EPI_PROJ) rowoff = (size_t)win_to_x_row(r) * N;
            else                 rowoff = (size_t)r * N;
#pragma unroll
            for (int ni = 0; ni < 8; ni++) {
                int c = bn + wn + ni * 8 + 2 * (lane & 3);
                float v0 = acc[mi][ni][half * 2 + 0] + bv0[ni];
                float v1 = acc[mi][ni][half * 2 + 1] + bv1[ni];
                if (EPI == EPI_GELU) { v0 = gelu_tanh(v0); v1 = gelu_tanh(v1); }
                if (EPI == EPI_PROJ || EPI == EPI_MLP2) {
                    float2 rr = *(const float2*)(res + rowoff + c);
                    v0 += rr.x; v1 += rr.y;
                }
                if (OUT_BF16) {
                    __nv_bfloat162 w = __floats2bfloat162_rn(v0, v1);
                    *(__nv_bfloat162*)((__nv_bfloat16*)Cout + rowoff + c) = w;
                } else {
                    float2 w = {v0, v1};
                    *(float2*)((float*)Cout + rowoff + c) = w;
                }
            }
        }
    }
}

// ---------------------------------------------------------------------------
// Tensor-core windowed attention (verified in R4; unchanged).
// One WARP per (window, head); tokens padded 49 -> 64.
// ---------------------------------------------------------------------------
#define ATS 40

__global__ void __launch_bounds__(64) attn_tc(const __nv_bfloat16* __restrict__ qkv,
                                              const float* __restrict__ bias_table,
                                              __nv_bfloat16* __restrict__ out) {
    __shared__ __align__(16) __nv_bfloat16 sQ[2][64 * ATS];
    __shared__ __align__(16) __nv_bfloat16 sK[2][64 * ATS];
    __shared__ __align__(16) __nv_bfloat16 sV[2][64 * ATS];
    __shared__ float sB[2][169];
    __shared__ int   sInfo[64];

    const int w     = blockIdx.x >> 2;
    const int wp    = threadIdx.x >> 5;
    const int lane  = threadIdx.x & 31;
    const int h     = (blockIdx.x & 3) * 2 + wp;
    const int wbase = w * 49;
    const int wi    = w & 63;

    if (threadIdx.x < 64) {
        int j = threadIdx.x;
        int info;
        if (j < 49) {
            int rj = j / 7, cj = j - (j / 7) * 7;
            int gr = (wi >> 3) * 7 + rj;
            int gc = (wi & 7) * 7 + cj;
            int rh = (gr < 49) ? 0 : ((gr < 53) ? 1 : 2);
            int rc = (gc < 49) ? 0 : ((gc < 53) ? 1 : 2);
            int key = rj + 13 * cj;
            info = key | ((rh * 3 + rc) << 8) | (1 << 16);
        } else {
            info = 0 | (255 << 8);
        }
        sInfo[j] = info;
    }

    for (int idx = lane; idx < 169; idx += 32) sB[wp][idx] = bias_table[idx * 8 + h];

    for (int tsk = lane; tsk < 256; tsk += 32) {
        int row = tsk >> 2, seg = (tsk & 3) * 8;
        uint4 q4, k4, v4;
        if (row < 49) {
            const __nv_bfloat16* base = qkv + (size_t)(wbase + row) * 768 + h * 32 + seg;
            q4 = *(const uint4*)base;
            k4 = *(const uint4*)(base + 256);
            v4 = *(const uint4*)(base + 512);
        } else {
            q4 = make_uint4(0, 0, 0, 0); k4 = q4; v4 = q4;
        }
        int off = row * ATS + seg;
        *(uint4*)&sQ[wp][off] = q4;
        *(uint4*)&sK[wp][off] = k4;
        *(uint4*)&sV[wp][off] = v4;
    }
    __syncthreads();

    uint32_t kf[2][4][4];
#pragma unroll
    for (int ks = 0; ks < 2; ks++)
#pragma unroll
        for (int nt = 0; nt < 4; nt++)
            ldsm4(kf[ks][nt], &sK[wp][(nt * 16 + (lane & 7) + ((lane >> 4) & 1) * 8) * ATS
                                      + ks * 16 + ((lane >> 3) & 1) * 8]);

    const int q2 = 2 * (lane & 3);
    int jinfo[16];
#pragma unroll
    for (int u = 0; u < 8; u++) {
        jinfo[u * 2 + 0] = sInfo[u * 8 + q2 + 0];
        jinfo[u * 2 + 1] = sInfo[u * 8 + q2 + 1];
    }

    const int r = lane >> 2;

#pragma unroll
    for (int mt = 0; mt < 4; mt++) {
        uint32_t qf[2][4];
#pragma unroll
        for (int ks = 0; ks < 2; ks++)
            ldsm4(qf[ks], &sQ[wp][(mt * 16 + (lane & 15)) * ATS
                                  + ks * 16 + (lane >> 4) * 8]);

        float c[8][4] = {};
#pragma unroll
        for (int nt = 0; nt < 4; nt++) {
#pragma unroll
            for (int ks = 0; ks < 2; ks++) {
                mma_bf16(c[2 * nt + 0], qf[ks], kf[ks][nt][0], kf[ks][nt][1]);
                mma_bf16(c[2 * nt + 1], qf[ks], kf[ks][nt][2], kf[ks][nt][3]);
            }
        }

        int ilo = mt * 16 + r;
        int infLo = sInfo[ilo], infHi = sInfo[ilo + 8];
        int keyLo = (infLo & 255) + 84, regLo = (infLo >> 8) & 255;
        int keyHi = (infHi & 255) + 84, regHi = (infHi >> 8) & 255;

        float sumLo = 0.0f, sumHi = 0.0f;
#pragma unroll
        for (int u = 0; u < 8; u++) {
#pragma unroll
            for (int e = 0; e < 2; e++) {
                int inf = jinfo[u * 2 + e];
                float pLo, pHi;
                if (inf & 0x10000) {
                    int kj = inf & 255;
                    int rj = (inf >> 8) & 255;
                    float aLo = fmaf(c[u][e], SCALE_Q, sB[wp][keyLo - kj]);
                    float aHi = fmaf(c[u][2 + e], SCALE_Q, sB[wp][keyHi - kj]);
                    if (rj != regLo) aLo -= 100.0f;
                    if (rj != regHi) aHi -= 100.0f;
                    pLo = __expf(aLo);
                    pHi = __expf(aHi);
                } else {
                    pLo = 0.0f; pHi = 0.0f;
                }
                c[u][e]     = pLo;  sumLo += pLo;
                c[u][2 + e] = pHi;  sumHi += pHi;
            }
        }
        sumLo += __shfl_xor_sync(0xffffffffu, sumLo, 1);
        sumLo += __shfl_xor_sync(0xffffffffu, sumLo, 2);
        sumHi += __shfl_xor_sync(0xffffffffu, sumHi, 1);
        sumHi += __shfl_xor_sync(0xffffffffu, sumHi, 2);
        float dLo = 1.0f / sumLo;
        float dHi = 1.0f / sumHi;

        uint32_t pa[4][4];
#pragma unroll
        for (int t = 0; t < 4; t++) {
            pa[t][0] = pack2_bf16(c[2 * t][0] * dLo,     c[2 * t][1] * dLo);
            pa[t][1] = pack2_bf16(c[2 * t][2] * dHi,     c[2 * t][3] * dHi);
            pa[t][2] = pack2_bf16(c[2 * t + 1][0] * dLo, c[2 * t + 1][1] * dLo);
            pa[t][3] = pack2_bf16(c[2 * t + 1][2] * dHi, c[2 * t + 1][3] * dHi);
        }

        float o[4][4] = {};
#pragma unroll
        for (int ks = 0; ks < 4; ks++) {
            uint32_t vf[2][4];
#pragma unroll
            for (int half = 0; half < 2; half++)
                ldsm4t(vf[half], &sV[wp][(ks * 16 + (lane & 7) + ((lane >> 3) & 1) * 8) * ATS
                                         + half * 16 + (lane >> 4) * 8]);
            mma_bf16(o[0], pa[ks], vf[0][0], vf[0][1]);
            mma_bf16(o[1], pa[ks], vf[0][2], vf[0][3]);
            mma_bf16(o[2], pa[ks], vf[1][0], vf[1][1]);
            mma_bf16(o[3], pa[ks], vf[1][2], vf[1][3]);
        }

        if (ilo < 49) {
            __nv_bfloat16* p = out + (size_t)(wbase + ilo) * 256 + h * 32 + q2;
#pragma unroll
            for (int on = 0; on < 4; on++)
                *(uint32_t*)(p + on * 8) = pack2_bf16(o[on][0], o[on][1]);
        }
        int ihi = ilo + 8;
        if (ihi < 49) {
            __nv_bfloat16* p = out + (size_t)(wbase + ihi) * 256 + h * 32 + q2;
#pragma unroll
            for (int on = 0; on < 4; on++)
                *(uint32_t*)(p + on * 8) = pack2_bf16(o[on][2], o[on][3]);
        }
    }
}

// ---------------------------------------------------------------------------
// Host launcher (graph-capturable: kernel launches only)
// ---------------------------------------------------------------------------
extern "C" void kernel_launch(void* const* d_in, const int* in_sizes, int n_in,
                              void* d_out, int out_size) {
    (void)in_sizes; (void)n_in; (void)out_size;

    const float* x          = (const float*)d_in[0];
    const float* n1g        = (const float*)d_in[1];
    const float* n1b        = (const float*)d_in[2];
    const float* qkv_w      = (const float*)d_in[3];
    const float* qkv_b      = (const float*)d_in[4];
    const float* proj_w     = (const float*)d_in[5];
    const float* proj_b     = (const float*)d_in[6];
    const float* bias_table = (const float*)d_in[7];
    const float* n2g        = (const float*)d_in[8];
    const float* n2b        = (const float*)d_in[9];
    const float* w1         = (const float*)d_in[10];
    const float* b1         = (const float*)d_in[11];
    const float* w2         = (const float*)d_in[12];
    const float* b2         = (const float*)d_in[13];
    float* out = (float*)d_out;

    __nv_bfloat16 *ywin, *qkvb, *attnb, *h2, *act, *wbf;
    float *x1;
    cudaGetSymbolAddress((void**)&ywin,  g_ywin);
    cudaGetSymbolAddress((void**)&qkvb,  g_qkv);
    cudaGetSymbolAddress((void**)&attnb, g_attn);
    cudaGetSymbolAddress((void**)&x1,    g_x1);
    cudaGetSymbolAddress((void**)&h2,    g_h2);
    cudaGetSymbolAddress((void**)&act,   g_act);
    cudaGetSymbolAddress((void**)&wbf,   g_wbf);

    cudaFuncSetAttribute(gemm_bf16<EPI_BIAS, true>,
                         cudaFuncAttributeMaxDynamicSharedMemorySize, GEMM_SMEM);
    cudaFuncSetAttribute(gemm_bf16<EPI_PROJ, false>,
                         cudaFuncAttributeMaxDynamicSharedMemorySize, GEMM_SMEM);
    cudaFuncSetAttribute(gemm_bf16<EPI_GELU, true>,
                         cudaFuncAttributeMaxDynamicSharedMemorySize, GEMM_SMEM);
    cudaFuncSetAttribute(gemm_bf16<EPI_MLP2, false>,
                         cudaFuncAttributeMaxDynamicSharedMemorySize, GEMM_SMEM);

    const int lnBlocks = NROWS / 8;

    // 0) weights -> bf16
    wconv_kernel<<<768, 1024>>>(qkv_w, proj_w, w1, w2, wbf);
    // 1) LN1 + cyclic shift + window partition -> bf16
    ln_kernel<true><<<lnBlocks, 256>>>(x, n1g, n1b, ywin);
    // 2) QKV: [100352,256] @ [256,768] -> bf16
    gemm_bf16<EPI_BIAS, true><<<dim3(784, 6), 256, GEMM_SMEM>>>(ywin, wbf + WOFF_QKV,
                                                                qkv_b, qkvb, nullptr, 768, 256);
    // 3) windowed attention (tensor cores) -> bf16
    attn_tc<<<NWIN * 4, 64>>>(qkvb, bias_table, attnb);
    // 4) proj + window-reverse + un-shift + residual -> x1 (fp32)
    gemm_bf16<EPI_PROJ, false><<<dim3(784, 2), 256, GEMM_SMEM>>>(attnb, wbf + WOFF_PROJ,
                                                                 proj_b, x1, x, 256, 256);
    // 5) LN2 -> bf16
    ln_kernel<false><<<lnBlocks, 256>>>(x1, n2g, n2b, h2);
    // 6) MLP up + GELU: [100352,256] @ [256,1024] -> bf16
    gemm_bf16<EPI_GELU, true><<<dim3(784, 8), 256, GEMM_SMEM>>>(h2, wbf + WOFF_W1,
                                                                b1, act, nullptr, 1024, 256);
    // 7) MLP down + residual -> d_out (fp32): [100352,1024] @ [1024,256]
    gemm_bf16<EPI_MLP2, false><<<dim3(784, 2), 256, GEMM_SMEM>>>(act, wbf + WOFF_W2,
                                                                 b2, out, x1, 256, 1024);
}

// round 11
// speedup vs baseline: 4.9675x; 1.0091x over previous
#include <cuda_runtime.h>
#include <cuda_bf16.h>
#include <cstddef>
#include <cstdint>

// ---------------------------------------------------------------------------
// Problem constants
// ---------------------------------------------------------------------------
#define NROWS   100352            // 32 * 56 * 56 tokens
#define NWIN    2048              // 32 * 64 windows
#define SCALE_Q 0.17677669529663689f   // 32^-0.5

// ---------------------------------------------------------------------------
// Scratch (static __device__ arrays; allocation is forbidden)
// ---------------------------------------------------------------------------
__device__ __align__(16) __nv_bfloat16 g_ywin[100352 * 256];   // LN1 out (win order)
__device__ __align__(16) __nv_bfloat16 g_qkv [100352 * 768];   // qkv, bf16
__device__ __align__(16) __nv_bfloat16 g_attn[100352 * 256];   // attention out
__device__ float                       g_x1  [100352 * 256];   // shortcut + proj
__device__ __align__(16) __nv_bfloat16 g_h2  [100352 * 256];   // LN2 out
__device__ __align__(16) __nv_bfloat16 g_act [100352 * 1024];  // gelu(mlp1)
__device__ __align__(16) __nv_bfloat16 g_wbf [786432];         // all 4 weights, bf16

#define WOFF_QKV  0
#define WOFF_PROJ 196608
#define WOFF_W1   262144
#define WOFF_W2   524288

// ---------------------------------------------------------------------------
// window-order row <-> x-order row mapping (shift = 3, 8x8 windows of 7x7)
// ---------------------------------------------------------------------------
__device__ __forceinline__ int win_to_x_row(int m) {
    int w  = m / 49;
    int t  = m - w * 49;
    int b  = w >> 6;
    int wi = w & 63;
    int tr = t / 7;
    int tc = t - tr * 7;
    int gr = ((wi >> 3) * 7) + tr;
    int gc = ((wi & 7) * 7) + tc;
    int r = gr + 3; if (r >= 56) r -= 56;
    int c = gc + 3; if (c >= 56) c -= 56;
    return b * 3136 + r * 56 + c;
}

__device__ __forceinline__ float gelu_tanh(float x) {
    float x3 = x * x * x;
    return 0.5f * x * (1.0f + tanhf(0.7978845608028654f * (x + 0.044715f * x3)));
}

__device__ __forceinline__ uint2 pack4_bf16(float4 v) {
    __nv_bfloat162 lo = __floats2bfloat162_rn(v.x, v.y);
    __nv_bfloat162 hi = __floats2bfloat162_rn(v.z, v.w);
    uint2 r;
    r.x = *(uint32_t*)&lo;
    r.y = *(uint32_t*)&hi;
    return r;
}

__device__ __forceinline__ uint32_t pack2_bf16(float a, float b) {
    __nv_bfloat162 t = __floats2bfloat162_rn(a, b);
    return *(uint32_t*)&t;
}

// ---------------------------------------------------------------------------
// PTX helpers
// ---------------------------------------------------------------------------
__device__ __forceinline__ void ldsm4(uint32_t r[4], const void* p) {
    uint32_t a = (uint32_t)__cvta_generic_to_shared(p);
    asm("ldmatrix.sync.aligned.m8n8.x4.shared.b16 {%0,%1,%2,%3}, [%4];"
        : "=r"(r[0]), "=r"(r[1]), "=r"(r[2]), "=r"(r[3]) : "r"(a) : "memory");
}
__device__ __forceinline__ void ldsm4t(uint32_t r[4], const void* p) {
    uint32_t a = (uint32_t)__cvta_generic_to_shared(p);
    asm("ldmatrix.sync.aligned.m8n8.x4.trans.shared.b16 {%0,%1,%2,%3}, [%4];"
        : "=r"(r[0]), "=r"(r[1]), "=r"(r[2]), "=r"(r[3]) : "r"(a) : "memory");
}
__device__ __forceinline__ void mma_bf16(float c[4], const uint32_t a[4],
                                         uint32_t b0, uint32_t b1) {
    asm("mma.sync.aligned.m16n8k16.row.col.f32.bf16.bf16.f32 "
        "{%0,%1,%2,%3}, {%4,%5,%6,%7}, {%8,%9}, {%0,%1,%2,%3};"
        : "+f"(c[0]), "+f"(c[1]), "+f"(c[2]), "+f"(c[3])
        : "r"(a[0]), "r"(a[1]), "r"(a[2]), "r"(a[3]), "r"(b0), "r"(b1));
}
__device__ __forceinline__ void cpasync16(void* dst, const void* src) {
    uint32_t d = (uint32_t)__cvta_generic_to_shared(dst);
    asm volatile("cp.async.cg.shared.global [%0], [%1], 16;" :: "r"(d), "l"(src));
}
__device__ __forceinline__ void cp_commit() {
    asm volatile("cp.async.commit_group;");
}
template <int N>
__device__ __forceinline__ void cp_wait() {
    asm volatile("cp.async.wait_group %0;" :: "n"(N));
}

// ---------------------------------------------------------------------------
// Weight conversion: fp32 -> bf16, once per launch
// ---------------------------------------------------------------------------
__global__ void __launch_bounds__(1024) wconv_kernel(const float* __restrict__ qkv_w,
                                                     const float* __restrict__ proj_w,
                                                     const float* __restrict__ w1,
                                                     const float* __restrict__ w2,
                                                     __nv_bfloat16* __restrict__ dst) {
    int i = blockIdx.x * 1024 + threadIdx.x;   // grid = 768
    float v;
    if      (i < WOFF_PROJ) v = qkv_w[i];
    else if (i < WOFF_W1)   v = proj_w[i - WOFF_PROJ];
    else if (i < WOFF_W2)   v = w1[i - WOFF_W1];
    else                    v = w2[i - WOFF_W2];
    dst[i] = __float2bfloat16(v);
}

// ---------------------------------------------------------------------------
// LayerNorm (LN1 only): one warp per 256-wide row, gather + bf16 output.
// ---------------------------------------------------------------------------
__global__ void __launch_bounds__(256) ln_kernel(const float* __restrict__ in,
                                                 const float* __restrict__ gamma,
                                                 const float* __restrict__ beta,
                                                 __nv_bfloat16* __restrict__ out) {
    int gw   = (blockIdx.x * blockDim.x + threadIdx.x) >> 5;
    int lane = threadIdx.x & 31;
    if (gw >= NROWS) return;
    int src = win_to_x_row(gw);

    const float4* row = (const float4*)(in + (size_t)src * 256);
    float4 v0 = row[lane];
    float4 v1 = row[lane + 32];

    float s  = v0.x + v0.y + v0.z + v0.w + v1.x + v1.y + v1.z + v1.w;
    float ss = v0.x*v0.x + v0.y*v0.y + v0.z*v0.z + v0.w*v0.w
             + v1.x*v1.x + v1.y*v1.y + v1.z*v1.z + v1.w*v1.w;
#pragma unroll
    for (int o = 16; o; o >>= 1) {
        s  += __shfl_xor_sync(0xffffffffu, s,  o);
        ss += __shfl_xor_sync(0xffffffffu, ss, o);
    }
    float mu  = s * (1.0f / 256.0f);
    float inv = rsqrtf(ss * (1.0f / 256.0f) - mu * mu + 1e-5f);

    float4 g0 = ((const float4*)gamma)[lane];
    float4 g1 = ((const float4*)gamma)[lane + 32];
    float4 b0 = ((const float4*)beta)[lane];
    float4 b1 = ((const float4*)beta)[lane + 32];

    float4 o0, o1;
    o0.x = (v0.x - mu) * inv * g0.x + b0.x;
    o0.y = (v0.y - mu) * inv * g0.y + b0.y;
    o0.z = (v0.z - mu) * inv * g0.z + b0.z;
    o0.w = (v0.w - mu) * inv * g0.w + b0.w;
    o1.x = (v1.x - mu) * inv * g1.x + b1.x;
    o1.y = (v1.y - mu) * inv * g1.y + b1.y;
    o1.z = (v1.z - mu) * inv * g1.z + b1.z;
    o1.w = (v1.w - mu) * inv * g1.w + b1.w;

    uint2* orow = (uint2*)(out + (size_t)gw * 256);
    orow[lane]      = pack4_bf16(o0);
    orow[lane + 32] = pack4_bf16(o1);
}

// ---------------------------------------------------------------------------
// bf16 tensor-core GEMM, BK=64, 3-stage pipeline + register fragment
// double-buffering (unchanged from R9 -- best verified mainloop).
// ---------------------------------------------------------------------------
#define EPI_BIAS 0
#define EPI_GELU 1
#define EPI_MLP2 3

#define AS 72
#define BSS 136
#define A_STG (128 * AS)
#define B_STG (64 * BSS)
#define GEMM_SMEM ((3 * A_STG + 3 * B_STG) * 2)   // 107520 bytes

template <int EPI, bool OUT_BF16>
__global__ void __launch_bounds__(256, 2) gemm_bf16(const __nv_bfloat16* __restrict__ A,
                                                    const __nv_bfloat16* __restrict__ B,
                                                    const float* __restrict__ bias,
                                                    void* __restrict__ Cout,
                                                    const float* __restrict__ res,
                                                    int N, int K) {
    extern __shared__ __align__(16) __nv_bfloat16 smp[];
    __nv_bfloat16* Asm = smp;
    __nv_bfloat16* Bsm = smp + 3 * A_STG;

    const int tid  = threadIdx.x;
    const int lane = tid & 31;
    const int wid  = tid >> 5;
    const int bm   = blockIdx.x * 128;
    const int bn   = blockIdx.y * 128;
    const int wm   = (wid & 3) * 32;
    const int wn   = (wid >> 2) * 64;

    const __nv_bfloat16* Ab = A + (size_t)bm * K;
    const __nv_bfloat16* Bb = B + bn;

    float acc[2][8][4] = {};

    auto load_tile = [&](int k0, int stg) {
        __nv_bfloat16* as = Asm + stg * A_STG;
        __nv_bfloat16* bs = Bsm + stg * B_STG;
#pragma unroll
        for (int i = 0; i < 4; i++) {
            int c = tid + i * 256;
            int row = c >> 3, kc = (c & 7) * 8;
            cpasync16(&as[row * AS + kc], Ab + (size_t)row * K + k0 + kc);
        }
#pragma unroll
        for (int i = 0; i < 4; i++) {
            int c = tid + i * 256;
            int k = c >> 4, n = (c & 15) * 8;
            cpasync16(&bs[k * BSS + n], Bb + (size_t)(k0 + k) * N + n);
        }
        cp_commit();
    };

    const int nIter = K >> 6;
    load_tile(0, 0);
    load_tile(64, 1);

    const int aoff0 = (wm + (lane & 15)) * AS + (lane >> 4) * 8;
    const int aoff1 = aoff0 + 16 * AS;
    const int boff  = ((lane & 7) + ((lane >> 3) & 1) * 8) * BSS
                      + wn + (lane >> 4) * 8;

    for (int i = 0; i < nIter; i++) {
        if (i + 1 < nIter) cp_wait<1>(); else cp_wait<0>();
        __syncthreads();
        if (i + 2 < nIter) load_tile((i + 2) * 64, (i + 2) % 3);

        const __nv_bfloat16* as = Asm + (i % 3) * A_STG;
        const __nv_bfloat16* bs = Bsm + (i % 3) * B_STG;
        const __nv_bfloat16* a0 = as + aoff0;
        const __nv_bfloat16* a1 = as + aoff1;
        const __nv_bfloat16* bp = bs + boff;

        uint32_t af[2][2][4];
        uint32_t bf[2][4];
        ldsm4(af[0][0], a0);
        ldsm4(af[0][1], a1);
        ldsm4t(bf[0], bp);
#pragma unroll
        for (int s = 0; s < 16; s++) {
            const int ks = (s >> 2) * 16;
            const int np = s & 3;
            const int ca = (s >> 2) & 1;
            const int cb = s & 1;
            if (np == 2 && ks < 48) {
                ldsm4(af[ca ^ 1][0], a0 + ks + 16);
                ldsm4(af[ca ^ 1][1], a1 + ks + 16);
            }
            if (s < 15) {
                const int ns = s + 1;
                ldsm4t(bf[cb ^ 1], bp + ((ns >> 2) * 16) * BSS + (ns & 3) * 16);
            }
            mma_bf16(acc[0][np * 2 + 0], af[ca][0], bf[cb][0], bf[cb][1]);
            mma_bf16(acc[1][np * 2 + 0], af[ca][1], bf[cb][0], bf[cb][1]);
            mma_bf16(acc[0][np * 2 + 1], af[ca][0], bf[cb][2], bf[cb][3]);
            mma_bf16(acc[1][np * 2 + 1], af[ca][1], bf[cb][2], bf[cb][3]);
        }
    }

    // ---------------- epilogue ----------------
    float bv0[8], bv1[8];
#pragma unroll
    for (int ni = 0; ni < 8; ni++) {
        int c = bn + wn + ni * 8 + 2 * (lane & 3);
        bv0[ni] = bias[c];
        bv1[ni] = bias[c + 1];
    }

#pragma unroll
    for (int mi = 0; mi < 2; mi++) {
#pragma unroll
        for (int half = 0; half < 2; half++) {
            int r = bm + wm + mi * 16 + (lane >> 2) + half * 8;
            size_t rowoff = (size_t)r * N;
#pragma unroll
            for (int ni = 0; ni < 8; ni++) {
                int c = bn + wn + ni * 8 + 2 * (lane & 3);
                float v0 = acc[mi][ni][half * 2 + 0] + bv0[ni];
                float v1 = acc[mi][ni][half * 2 + 1] + bv1[ni];
                if (EPI == EPI_GELU) { v0 = gelu_tanh(v0); v1 = gelu_tanh(v1); }
                if (EPI == EPI_MLP2) {
                    float2 rr = *(const float2*)(res + rowoff + c);
                    v0 += rr.x; v1 += rr.y;
                }
                if (OUT_BF16) {
                    __nv_bfloat162 w = __floats2bfloat162_rn(v0, v1);
                    *(__nv_bfloat162*)((__nv_bfloat16*)Cout + rowoff + c) = w;
                } else {
                    float2 w = {v0, v1};
                    *(float2*)((float*)Cout + rowoff + c) = w;
                }
            }
        }
    }
}

// ---------------------------------------------------------------------------
// PROJ + residual + LN2 fused GEMM.
// BM=64, BN=256 (= full N), 256 threads = 8 warps (2m x 4n), warp tile 32x64.
// 4-stage BK=32 cp.async pipeline (exact tail waits, load-after-sync).
// Epilogue: x1[xrow] = acc + bias + x[xrow]  (fp32 gmem + smem staging),
// then in-block LN over the staged 64x256 rows -> h2[xrow] bf16.
// Eliminates the standalone LN2 kernel (one full fp32 pass over x1).
// smem: 4*(64*40 + 32*264)*2 = 88064 B >= x1 staging 64*264*4 = 67584 B.
// ---------------------------------------------------------------------------
#define PS_AS 40
#define PS_BS 264
#define PS_A_STG (64 * PS_AS)
#define PS_B_STG (32 * PS_BS)
#define PROJ_SMEM ((4 * PS_A_STG + 4 * PS_B_STG) * 2)   // 88064

__global__ void __launch_bounds__(256, 2) gemm_proj_ln(
    const __nv_bfloat16* __restrict__ A,     // attn out (window order)
    const __nv_bfloat16* __restrict__ B,     // proj_w bf16 [k][n]
    const float* __restrict__ bias,
    const float* __restrict__ xres,          // original input x
    const float* __restrict__ gamma,         // norm2_g
    const float* __restrict__ beta,          // norm2_b
    float* __restrict__ x1,
    __nv_bfloat16* __restrict__ h2) {
    extern __shared__ __align__(16) __nv_bfloat16 smp[];
    __nv_bfloat16* Asm = smp;
    __nv_bfloat16* Bsm = smp + 4 * PS_A_STG;

    const int tid  = threadIdx.x;
    const int lane = tid & 31;
    const int wid  = tid >> 5;
    const int bm   = blockIdx.x * 64;
    const int wm   = (wid & 1) * 32;
    const int wn   = (wid >> 1) * 64;
    const int K = 256, N = 256;

    const __nv_bfloat16* Ab = A + (size_t)bm * K;

    float acc[2][8][4] = {};

    auto load_tile = [&](int k0, int stg) {
        __nv_bfloat16* as = Asm + stg * PS_A_STG;
        __nv_bfloat16* bs = Bsm + stg * PS_B_STG;
        {
            int row = tid >> 2, kc = (tid & 3) * 8;      // A: 64x32
            cpasync16(&as[row * PS_AS + kc], Ab + (size_t)row * K + k0 + kc);
        }
#pragma unroll
        for (int i = 0; i < 4; i++) {                    // B: 32x256
            int c = tid + i * 256;
            int k = c >> 5, n = (c & 31) * 8;
            cpasync16(&bs[k * PS_BS + n], B + (size_t)(k0 + k) * N + n);
        }
        cp_commit();
    };

    const int nIter = 8;                                 // K/32
    load_tile(0, 0);
    load_tile(32, 1);
    load_tile(64, 2);

    for (int i = 0; i < nIter; i++) {
        if      (i + 2 < nIter) cp_wait<2>();
        else if (i + 1 < nIter) cp_wait<1>();
        else                    cp_wait<0>();
        __syncthreads();
        if (i + 3 < nIter) load_tile((i + 3) * 32, (i + 3) & 3);

        const __nv_bfloat16* as = Asm + (i & 3) * PS_A_STG;
        const __nv_bfloat16* bs = Bsm + (i & 3) * PS_B_STG;
#pragma unroll
        for (int ks = 0; ks < 32; ks += 16) {
            uint32_t af[2][4];
#pragma unroll
            for (int mi = 0; mi < 2; mi++)
                ldsm4(af[mi], as + (wm + mi * 16 + (lane & 15)) * PS_AS
                                 + ks + (lane >> 4) * 8);
#pragma unroll
            for (int np = 0; np < 4; np++) {
                uint32_t bf[4];
                ldsm4t(bf, bs + (ks + (lane & 7) + ((lane >> 3) & 1) * 8) * PS_BS
                              + wn + np * 16 + (lane >> 4) * 8);
                mma_bf16(acc[0][np * 2 + 0], af[0], bf[0], bf[1]);
                mma_bf16(acc[1][np * 2 + 0], af[1], bf[0], bf[1]);
                mma_bf16(acc[0][np * 2 + 1], af[0], bf[2], bf[3]);
                mma_bf16(acc[1][np * 2 + 1], af[1], bf[2], bf[3]);
            }
        }
    }
    __syncthreads();   // all warps done with pipeline smem before x1 staging

    // ---------------- epilogue: x1 = acc + bias + x, staged in smem ----------
    float* x1s = (float*)smp;        // 64 rows x stride 264 fp32
    const int S = 264;

    float bv0[8], bv1[8];
#pragma unroll
    for (int ni = 0; ni < 8; ni++) {
        int c = wn + ni * 8 + 2 * (lane & 3);
        bv0[ni] = bias[c];
        bv1[ni] = bias[c + 1];
    }

#pragma unroll
    for (int mi = 0; mi < 2; mi++) {
#pragma unroll
        for (int half = 0; half < 2; half++) {
            int row  = wm + mi * 16 + (lane >> 2) + half * 8;   // 0..63
            int xrow = win_to_x_row(bm + row);
            size_t off = (size_t)xrow * 256;
#pragma unroll
            for (int ni = 0; ni < 8; ni++) {
                int c = wn + ni * 8 + 2 * (lane & 3);
                float v0 = acc[mi][ni][half * 2 + 0] + bv0[ni];
                float v1 = acc[mi][ni][half * 2 + 1] + bv1[ni];
                float2 rr = *(const float2*)(xres + off + c);
                v0 += rr.x; v1 += rr.y;
                float2 w = {v0, v1};
                *(float2*)(x1 + off + c)      = w;
                *(float2*)(&x1s[row * S + c]) = w;
            }
        }
    }
    __syncthreads();

    // ---------------- in-block LN2: 8 rows per warp -> h2 bf16 ---------------
    float4 g0 = *(const float4*)(gamma + lane * 8);
    float4 g1 = *(const float4*)(gamma + lane * 8 + 4);
    float4 be0 = *(const float4*)(beta + lane * 8);
    float4 be1 = *(const float4*)(beta + lane * 8 + 4);

#pragma unroll
    for (int rr = 0; rr < 8; rr++) {
        int row = wid * 8 + rr;
        float4 u0 = *(const float4*)(&x1s[row * S + lane * 8]);
        float4 u1 = *(const float4*)(&x1s[row * S + lane * 8 + 4]);

        float s  = u0.x + u0.y + u0.z + u0.w + u1.x + u1.y + u1.z + u1.w;
        float ss = u0.x*u0.x + u0.y*u0.y + u0.z*u0.z + u0.w*u0.w
                 + u1.x*u1.x + u1.y*u1.y + u1.z*u1.z + u1.w*u1.w;
#pragma unroll
        for (int o = 16; o; o >>= 1) {
            s  += __shfl_xor_sync(0xffffffffu, s,  o);
            ss += __shfl_xor_sync(0xffffffffu, ss, o);
        }
        float mu  = s * (1.0f / 256.0f);
        float inv = rsqrtf(ss * (1.0f / 256.0f) - mu * mu + 1e-5f);

        float4 o0, o1;
        o0.x = (u0.x - mu) * inv * g0.x + be0.x;
        o0.y = (u0.y - mu) * inv * g0.y + be0.y;
        o0.z = (u0.z - mu) * inv * g0.z + be0.z;
        o0.w = (u0.w - mu) * inv * g0.w + be0.w;
        o1.x = (u1.x - mu) * inv * g1.x + be1.x;
        o1.y = (u1.y - mu) * inv * g1.y + be1.y;
        o1.z = (u1.z - mu) * inv * g1.z + be1.z;
        o1.w = (u1.w - mu) * inv * g1.w + be1.w;

        int xrow = win_to_x_row(bm + row);
        uint2 p0 = pack4_bf16(o0);
        uint2 p1 = pack4_bf16(o1);
        uint4 pk = make_uint4(p0.x, p0.y, p1.x, p1.y);
        *(uint4*)(h2 + (size_t)xrow * 256 + lane * 8) = pk;
    }
}

// ---------------------------------------------------------------------------
// Tensor-core windowed attention (verified in R4; unchanged).
// ---------------------------------------------------------------------------
#define ATS 40

__global__ void __launch_bounds__(64) attn_tc(const __nv_bfloat16* __restrict__ qkv,
                                              const float* __restrict__ bias_table,
                                              __nv_bfloat16* __restrict__ out) {
    __shared__ __align__(16) __nv_bfloat16 sQ[2][64 * ATS];
    __shared__ __align__(16) __nv_bfloat16 sK[2][64 * ATS];
    __shared__ __align__(16) __nv_bfloat16 sV[2][64 * ATS];
    __shared__ float sB[2][169];
    __shared__ int   sInfo[64];

    const int w     = blockIdx.x >> 2;
    const int wp    = threadIdx.x >> 5;
    const int lane  = threadIdx.x & 31;
    const int h     = (blockIdx.x & 3) * 2 + wp;
    const int wbase = w * 49;
    const int wi    = w & 63;

    if (threadIdx.x < 64) {
        int j = threadIdx.x;
        int info;
        if (j < 49) {
            int rj = j / 7, cj = j - (j / 7) * 7;
            int gr = (wi >> 3) * 7 + rj;
            int gc = (wi & 7) * 7 + cj;
            int rh = (gr < 49) ? 0 : ((gr < 53) ? 1 : 2);
            int rc = (gc < 49) ? 0 : ((gc < 53) ? 1 : 2);
            int key = rj + 13 * cj;
            info = key | ((rh * 3 + rc) << 8) | (1 << 16);
        } else {
            info = 0 | (255 << 8);
        }
        sInfo[j] = info;
    }

    for (int idx = lane; idx < 169; idx += 32) sB[wp][idx] = bias_table[idx * 8 + h];

    for (int tsk = lane; tsk < 256; tsk += 32) {
        int row = tsk >> 2, seg = (tsk & 3) * 8;
        uint4 q4, k4, v4;
        if (row < 49) {
            const __nv_bfloat16* base = qkv + (size_t)(wbase + row) * 768 + h * 32 + seg;
            q4 = *(const uint4*)base;
            k4 = *(const uint4*)(base + 256);
            v4 = *(const uint4*)(base + 512);
        } else {
            q4 = make_uint4(0, 0, 0, 0); k4 = q4; v4 = q4;
        }
        int off = row * ATS + seg;
        *(uint4*)&sQ[wp][off] = q4;
        *(uint4*)&sK[wp][off] = k4;
        *(uint4*)&sV[wp][off] = v4;
    }
    __syncthreads();

    uint32_t kf[2][4][4];
#pragma unroll
    for (int ks = 0; ks < 2; ks++)
#pragma unroll
        for (int nt = 0; nt < 4; nt++)
            ldsm4(kf[ks][nt], &sK[wp][(nt * 16 + (lane & 7) + ((lane >> 4) & 1) * 8) * ATS
                                      + ks * 16 + ((lane >> 3) & 1) * 8]);

    const int q2 = 2 * (lane & 3);
    int jinfo[16];
#pragma unroll
    for (int u = 0; u < 8; u++) {
        jinfo[u * 2 + 0] = sInfo[u * 8 + q2 + 0];
        jinfo[u * 2 + 1] = sInfo[u * 8 + q2 + 1];
    }

    const int r = lane >> 2;

#pragma unroll
    for (int mt = 0; mt < 4; mt++) {
        uint32_t qf[2][4];
#pragma unroll
        for (int ks = 0; ks < 2; ks++)
            ldsm4(qf[ks], &sQ[wp][(mt * 16 + (lane & 15)) * ATS
                                  + ks * 16 + (lane >> 4) * 8]);

        float c[8][4] = {};
#pragma unroll
        for (int nt = 0; nt < 4; nt++) {
#pragma unroll
            for (int ks = 0; ks < 2; ks++) {
                mma_bf16(c[2 * nt + 0], qf[ks], kf[ks][nt][0], kf[ks][nt][1]);
                mma_bf16(c[2 * nt + 1], qf[ks], kf[ks][nt][2], kf[ks][nt][3]);
            }
        }

        int ilo = mt * 16 + r;
        int infLo = sInfo[ilo], infHi = sInfo[ilo + 8];
        int keyLo = (infLo & 255) + 84, regLo = (infLo >> 8) & 255;
        int keyHi = (infHi & 255) + 84, regHi = (infHi >> 8) & 255;

        float sumLo = 0.0f, sumHi = 0.0f;
#pragma unroll
        for (int u = 0; u < 8; u++) {
#pragma unroll
            for (int e = 0; e < 2; e++) {
                int inf = jinfo[u * 2 + e];
                float pLo, pHi;
                if (inf & 0x10000) {
                    int kj = inf & 255;
                    int rj = (inf >> 8) & 255;
                    float aLo = fmaf(c[u][e], SCALE_Q, sB[wp][keyLo - kj]);
                    float aHi = fmaf(c[u][2 + e], SCALE_Q, sB[wp][keyHi - kj]);
                    if (rj != regLo) aLo -= 100.0f;
                    if (rj != regHi) aHi -= 100.0f;
                    pLo = __expf(aLo);
                    pHi = __expf(aHi);
                } else {
                    pLo = 0.0f; pHi = 0.0f;
                }
                c[u][e]     = pLo;  sumLo += pLo;
                c[u][2 + e] = pHi;  sumHi += pHi;
            }
        }
        sumLo += __shfl_xor_sync(0xffffffffu, sumLo, 1);
        sumLo += __shfl_xor_sync(0xffffffffu, sumLo, 2);
        sumHi += __shfl_xor_sync(0xffffffffu, sumHi, 1);
        sumHi += __shfl_xor_sync(0xffffffffu, sumHi, 2);
        float dLo = 1.0f / sumLo;
        float dHi = 1.0f / sumHi;

        uint32_t pa[4][4];
#pragma unroll
        for (int t = 0; t < 4; t++) {
            pa[t][0] = pack2_bf16(c[2 * t][0] * dLo,     c[2 * t][1] * dLo);
            pa[t][1] = pack2_bf16(c[2 * t][2] * dHi,     c[2 * t][3] * dHi);
            pa[t][2] = pack2_bf16(c[2 * t + 1][0] * dLo, c[2 * t + 1][1] * dLo);
            pa[t][3] = pack2_bf16(c[2 * t + 1][2] * dHi, c[2 * t + 1][3] * dHi);
        }

        float o[4][4] = {};
#pragma unroll
        for (int ks = 0; ks < 4; ks++) {
            uint32_t vf[2][4];
#pragma unroll
            for (int half = 0; half < 2; half++)
                ldsm4t(vf[half], &sV[wp][(ks * 16 + (lane & 7) + ((lane >> 3) & 1) * 8) * ATS
                                         + half * 16 + (lane >> 4) * 8]);
            mma_bf16(o[0], pa[ks], vf[0][0], vf[0][1]);
            mma_bf16(o[1], pa[ks], vf[0][2], vf[0][3]);
            mma_bf16(o[2], pa[ks], vf[1][0], vf[1][1]);
            mma_bf16(o[3], pa[ks], vf[1][2], vf[1][3]);
        }

        if (ilo < 49) {
            __nv_bfloat16* p = out + (size_t)(wbase + ilo) * 256 + h * 32 + q2;
#pragma unroll
            for (int on = 0; on < 4; on++)
                *(uint32_t*)(p + on * 8) = pack2_bf16(o[on][0], o[on][1]);
        }
        int ihi = ilo + 8;
        if (ihi < 49) {
            __nv_bfloat16* p = out + (size_t)(wbase + ihi) * 256 + h * 32 + q2;
#pragma unroll
            for (int on = 0; on < 4; on++)
                *(uint32_t*)(p + on * 8) = pack2_bf16(o[on][2], o[on][3]);
        }
    }
}

// ---------------------------------------------------------------------------
// Host launcher (graph-capturable: kernel launches only)
// ---------------------------------------------------------------------------
extern "C" void kernel_launch(void* const* d_in, const int* in_sizes, int n_in,
                              void* d_out, int out_size) {
    (void)in_sizes; (void)n_in; (void)out_size;

    const float* x          = (const float*)d_in[0];
    const float* n1g        = (const float*)d_in[1];
    const float* n1b        = (const float*)d_in[2];
    const float* qkv_w      = (const float*)d_in[3];
    const float* qkv_b      = (const float*)d_in[4];
    const float* proj_w     = (const float*)d_in[5];
    const float* proj_b     = (const float*)d_in[6];
    const float* bias_table = (const float*)d_in[7];
    const float* n2g        = (const float*)d_in[8];
    const float* n2b        = (const float*)d_in[9];
    const float* w1         = (const float*)d_in[10];
    const float* b1         = (const float*)d_in[11];
    const float* w2         = (const float*)d_in[12];
    const float* b2         = (const float*)d_in[13];
    float* out = (float*)d_out;

    __nv_bfloat16 *ywin, *qkvb, *attnb, *h2, *act, *wbf;
    float *x1;
    cudaGetSymbolAddress((void**)&ywin,  g_ywin);
    cudaGetSymbolAddress((void**)&qkvb,  g_qkv);
    cudaGetSymbolAddress((void**)&attnb, g_attn);
    cudaGetSymbolAddress((void**)&x1,    g_x1);
    cudaGetSymbolAddress((void**)&h2,    g_h2);
    cudaGetSymbolAddress((void**)&act,   g_act);
    cudaGetSymbolAddress((void**)&wbf,   g_wbf);

    cudaFuncSetAttribute(gemm_bf16<EPI_BIAS, true>,
                         cudaFuncAttributeMaxDynamicSharedMemorySize, GEMM_SMEM);
    cudaFuncSetAttribute(gemm_bf16<EPI_GELU, true>,
                         cudaFuncAttributeMaxDynamicSharedMemorySize, GEMM_SMEM);
    cudaFuncSetAttribute(gemm_bf16<EPI_MLP2, false>,
                         cudaFuncAttributeMaxDynamicSharedMemorySize, GEMM_SMEM);
    cudaFuncSetAttribute(gemm_proj_ln,
                         cudaFuncAttributeMaxDynamicSharedMemorySize, PROJ_SMEM);

    const int lnBlocks = NROWS / 8;

    // 0) weights -> bf16
    wconv_kernel<<<768, 1024>>>(qkv_w, proj_w, w1, w2, wbf);
    // 1) LN1 + cyclic shift + window partition -> bf16
    ln_kernel<<<lnBlocks, 256>>>(x, n1g, n1b, ywin);
    // 2) QKV: [100352,256] @ [256,768] -> bf16
    gemm_bf16<EPI_BIAS, true><<<dim3(784, 6), 256, GEMM_SMEM>>>(ywin, wbf + WOFF_QKV,
                                                                qkv_b, qkvb, nullptr, 768, 256);
    // 3) windowed attention (tensor cores) -> bf16
    attn_tc<<<NWIN * 4, 64>>>(qkvb, bias_table, attnb);
    // 4) proj + window-reverse + un-shift + residual + LN2 (fused) -> x1, h2
    gemm_proj_ln<<<1568, 256, PROJ_SMEM>>>(attnb, wbf + WOFF_PROJ, proj_b,
                                           x, n2g, n2b, x1, h2);
    // 5) MLP up + GELU: [100352,256] @ [256,1024] -> bf16
    gemm_bf16<EPI_GELU, true><<<dim3(784, 8), 256, GEMM_SMEM>>>(h2, wbf + WOFF_W1,
                                                                b1, act, nullptr, 1024, 256);
    // 6) MLP down + residual -> d_out (fp32): [100352,1024] @ [1024,256]
    gemm_bf16<EPI_MLP2, false><<<dim3(784, 2), 256, GEMM_SMEM>>>(act, wbf + WOFF_W2,
                                                                 b2, out, x1, 256, 1024);
}

// round 12
// speedup vs baseline: 5.1440x; 1.0355x over previous
#include <cuda_runtime.h>
#include <cuda_bf16.h>
#include <cstddef>
#include <cstdint>

// ---------------------------------------------------------------------------
// Problem constants
// ---------------------------------------------------------------------------
#define NROWS   100352            // 32 * 56 * 56 tokens
#define NWIN    2048              // 32 * 64 windows
#define SCALE_Q 0.17677669529663689f   // 32^-0.5

// ---------------------------------------------------------------------------
// Scratch (static __device__ arrays; allocation is forbidden)
// ---------------------------------------------------------------------------
__device__ __align__(16) __nv_bfloat16 g_ywin[100352 * 256];   // LN1 out (win order)
__device__ __align__(16) __nv_bfloat16 g_qkv [100352 * 768];   // qkv, bf16
__device__ __align__(16) __nv_bfloat16 g_attn[100352 * 256];   // attention out
__device__ float                       g_x1  [100352 * 256];   // shortcut + proj
__device__ __align__(16) __nv_bfloat16 g_h2  [100352 * 256];   // LN2 out
__device__ __align__(16) __nv_bfloat16 g_act [100352 * 1024];  // gelu(mlp1)
__device__ __align__(16) __nv_bfloat16 g_wbf [786432];         // all 4 weights, bf16

#define WOFF_QKV  0
#define WOFF_PROJ 196608
#define WOFF_W1   262144
#define WOFF_W2   524288

// ---------------------------------------------------------------------------
// window-order row <-> x-order row mapping (shift = 3, 8x8 windows of 7x7)
// ---------------------------------------------------------------------------
__device__ __forceinline__ int win_to_x_row(int m) {
    int w  = m / 49;
    int t  = m - w * 49;
    int b  = w >> 6;
    int wi = w & 63;
    int tr = t / 7;
    int tc = t - tr * 7;
    int gr = ((wi >> 3) * 7) + tr;
    int gc = ((wi & 7) * 7) + tc;
    int r = gr + 3; if (r >= 56) r -= 56;
    int c = gc + 3; if (c >= 56) c -= 56;
    return b * 3136 + r * 56 + c;
}

__device__ __forceinline__ float gelu_tanh(float x) {
    float x3 = x * x * x;
    return 0.5f * x * (1.0f + tanhf(0.7978845608028654f * (x + 0.044715f * x3)));
}

__device__ __forceinline__ uint2 pack4_bf16(float4 v) {
    __nv_bfloat162 lo = __floats2bfloat162_rn(v.x, v.y);
    __nv_bfloat162 hi = __floats2bfloat162_rn(v.z, v.w);
    uint2 r;
    r.x = *(uint32_t*)&lo;
    r.y = *(uint32_t*)&hi;
    return r;
}

__device__ __forceinline__ uint32_t pack2_bf16(float a, float b) {
    __nv_bfloat162 t = __floats2bfloat162_rn(a, b);
    return *(uint32_t*)&t;
}

// ---------------------------------------------------------------------------
// PTX helpers
// ---------------------------------------------------------------------------
__device__ __forceinline__ void ldsm4(uint32_t r[4], const void* p) {
    uint32_t a = (uint32_t)__cvta_generic_to_shared(p);
    asm("ldmatrix.sync.aligned.m8n8.x4.shared.b16 {%0,%1,%2,%3}, [%4];"
        : "=r"(r[0]), "=r"(r[1]), "=r"(r[2]), "=r"(r[3]) : "r"(a) : "memory");
}
__device__ __forceinline__ void ldsm4t(uint32_t r[4], const void* p) {
    uint32_t a = (uint32_t)__cvta_generic_to_shared(p);
    asm("ldmatrix.sync.aligned.m8n8.x4.trans.shared.b16 {%0,%1,%2,%3}, [%4];"
        : "=r"(r[0]), "=r"(r[1]), "=r"(r[2]), "=r"(r[3]) : "r"(a) : "memory");
}
__device__ __forceinline__ void mma_bf16(float c[4], const uint32_t a[4],
                                         uint32_t b0, uint32_t b1) {
    asm("mma.sync.aligned.m16n8k16.row.col.f32.bf16.bf16.f32 "
        "{%0,%1,%2,%3}, {%4,%5,%6,%7}, {%8,%9}, {%0,%1,%2,%3};"
        : "+f"(c[0]), "+f"(c[1]), "+f"(c[2]), "+f"(c[3])
        : "r"(a[0]), "r"(a[1]), "r"(a[2]), "r"(a[3]), "r"(b0), "r"(b1));
}
__device__ __forceinline__ void cpasync16(void* dst, const void* src) {
    uint32_t d = (uint32_t)__cvta_generic_to_shared(dst);
    asm volatile("cp.async.cg.shared.global [%0], [%1], 16;" :: "r"(d), "l"(src));
}
__device__ __forceinline__ void cp_commit() {
    asm volatile("cp.async.commit_group;");
}
template <int N>
__device__ __forceinline__ void cp_wait() {
    asm volatile("cp.async.wait_group %0;" :: "n"(N));
}

// ---------------------------------------------------------------------------
// Weight conversion: fp32 -> bf16, once per launch
// ---------------------------------------------------------------------------
__global__ void __launch_bounds__(1024) wconv_kernel(const float* __restrict__ qkv_w,
                                                     const float* __restrict__ proj_w,
                                                     const float* __restrict__ w1,
                                                     const float* __restrict__ w2,
                                                     __nv_bfloat16* __restrict__ dst) {
    int i = blockIdx.x * 1024 + threadIdx.x;   // grid = 768
    float v;
    if      (i < WOFF_PROJ) v = qkv_w[i];
    else if (i < WOFF_W1)   v = proj_w[i - WOFF_PROJ];
    else if (i < WOFF_W2)   v = w1[i - WOFF_W1];
    else                    v = w2[i - WOFF_W2];
    dst[i] = __float2bfloat16(v);
}

// ---------------------------------------------------------------------------
// LayerNorm (LN1 only): one warp per 256-wide row, gather + bf16 output.
// ---------------------------------------------------------------------------
__global__ void __launch_bounds__(256) ln_kernel(const float* __restrict__ in,
                                                 const float* __restrict__ gamma,
                                                 const float* __restrict__ beta,
                                                 __nv_bfloat16* __restrict__ out) {
    int gw   = (blockIdx.x * blockDim.x + threadIdx.x) >> 5;
    int lane = threadIdx.x & 31;
    if (gw >= NROWS) return;
    int src = win_to_x_row(gw);

    const float4* row = (const float4*)(in + (size_t)src * 256);
    float4 v0 = row[lane];
    float4 v1 = row[lane + 32];

    float s  = v0.x + v0.y + v0.z + v0.w + v1.x + v1.y + v1.z + v1.w;
    float ss = v0.x*v0.x + v0.y*v0.y + v0.z*v0.z + v0.w*v0.w
             + v1.x*v1.x + v1.y*v1.y + v1.z*v1.z + v1.w*v1.w;
#pragma unroll
    for (int o = 16; o; o >>= 1) {
        s  += __shfl_xor_sync(0xffffffffu, s,  o);
        ss += __shfl_xor_sync(0xffffffffu, ss, o);
    }
    float mu  = s * (1.0f / 256.0f);
    float inv = rsqrtf(ss * (1.0f / 256.0f) - mu * mu + 1e-5f);

    float4 g0 = ((const float4*)gamma)[lane];
    float4 g1 = ((const float4*)gamma)[lane + 32];
    float4 b0 = ((const float4*)beta)[lane];
    float4 b1 = ((const float4*)beta)[lane + 32];

    float4 o0, o1;
    o0.x = (v0.x - mu) * inv * g0.x + b0.x;
    o0.y = (v0.y - mu) * inv * g0.y + b0.y;
    o0.z = (v0.z - mu) * inv * g0.z + b0.z;
    o0.w = (v0.w - mu) * inv * g0.w + b0.w;
    o1.x = (v1.x - mu) * inv * g1.x + b1.x;
    o1.y = (v1.y - mu) * inv * g1.y + b1.y;
    o1.z = (v1.z - mu) * inv * g1.z + b1.z;
    o1.w = (v1.w - mu) * inv * g1.w + b1.w;

    uint2* orow = (uint2*)(out + (size_t)gw * 256);
    orow[lane]      = pack4_bf16(o0);
    orow[lane + 32] = pack4_bf16(o1);
}

// ---------------------------------------------------------------------------
// bf16 tensor-core GEMM, BK=64, 3-stage pipeline + register fragment
// double-buffering (unchanged from R9 -- best verified mainloop).
// ---------------------------------------------------------------------------
#define EPI_BIAS 0
#define EPI_GELU 1
#define EPI_MLP2 3

#define AS 72
#define BSS 136
#define A_STG (128 * AS)
#define B_STG (64 * BSS)
#define GEMM_SMEM ((3 * A_STG + 3 * B_STG) * 2)   // 107520 bytes

template <int EPI, bool OUT_BF16>
__global__ void __launch_bounds__(256, 2) gemm_bf16(const __nv_bfloat16* __restrict__ A,
                                                    const __nv_bfloat16* __restrict__ B,
                                                    const float* __restrict__ bias,
                                                    void* __restrict__ Cout,
                                                    const float* __restrict__ res,
                                                    int N, int K) {
    extern __shared__ __align__(16) __nv_bfloat16 smp[];
    __nv_bfloat16* Asm = smp;
    __nv_bfloat16* Bsm = smp + 3 * A_STG;

    const int tid  = threadIdx.x;
    const int lane = tid & 31;
    const int wid  = tid >> 5;
    const int bm   = blockIdx.x * 128;
    const int bn   = blockIdx.y * 128;
    const int wm   = (wid & 3) * 32;
    const int wn   = (wid >> 2) * 64;

    const __nv_bfloat16* Ab = A + (size_t)bm * K;
    const __nv_bfloat16* Bb = B + bn;

    float acc[2][8][4] = {};

    auto load_tile = [&](int k0, int stg) {
        __nv_bfloat16* as = Asm + stg * A_STG;
        __nv_bfloat16* bs = Bsm + stg * B_STG;
#pragma unroll
        for (int i = 0; i < 4; i++) {
            int c = tid + i * 256;
            int row = c >> 3, kc = (c & 7) * 8;
            cpasync16(&as[row * AS + kc], Ab + (size_t)row * K + k0 + kc);
        }
#pragma unroll
        for (int i = 0; i < 4; i++) {
            int c = tid + i * 256;
            int k = c >> 4, n = (c & 15) * 8;
            cpasync16(&bs[k * BSS + n], Bb + (size_t)(k0 + k) * N + n);
        }
        cp_commit();
    };

    const int nIter = K >> 6;
    load_tile(0, 0);
    load_tile(64, 1);

    const int aoff0 = (wm + (lane & 15)) * AS + (lane >> 4) * 8;
    const int aoff1 = aoff0 + 16 * AS;
    const int boff  = ((lane & 7) + ((lane >> 3) & 1) * 8) * BSS
                      + wn + (lane >> 4) * 8;

    for (int i = 0; i < nIter; i++) {
        if (i + 1 < nIter) cp_wait<1>(); else cp_wait<0>();
        __syncthreads();
        if (i + 2 < nIter) load_tile((i + 2) * 64, (i + 2) % 3);

        const __nv_bfloat16* as = Asm + (i % 3) * A_STG;
        const __nv_bfloat16* bs = Bsm + (i % 3) * B_STG;
        const __nv_bfloat16* a0 = as + aoff0;
        const __nv_bfloat16* a1 = as + aoff1;
        const __nv_bfloat16* bp = bs + boff;

        uint32_t af[2][2][4];
        uint32_t bf[2][4];
        ldsm4(af[0][0], a0);
        ldsm4(af[0][1], a1);
        ldsm4t(bf[0], bp);
#pragma unroll
        for (int s = 0; s < 16; s++) {
            const int ks = (s >> 2) * 16;
            const int np = s & 3;
            const int ca = (s >> 2) & 1;
            const int cb = s & 1;
            if (np == 2 && ks < 48) {
                ldsm4(af[ca ^ 1][0], a0 + ks + 16);
                ldsm4(af[ca ^ 1][1], a1 + ks + 16);
            }
            if (s < 15) {
                const int ns = s + 1;
                ldsm4t(bf[cb ^ 1], bp + ((ns >> 2) * 16) * BSS + (ns & 3) * 16);
            }
            mma_bf16(acc[0][np * 2 + 0], af[ca][0], bf[cb][0], bf[cb][1]);
            mma_bf16(acc[1][np * 2 + 0], af[ca][1], bf[cb][0], bf[cb][1]);
            mma_bf16(acc[0][np * 2 + 1], af[ca][0], bf[cb][2], bf[cb][3]);
            mma_bf16(acc[1][np * 2 + 1], af[ca][1], bf[cb][2], bf[cb][3]);
        }
    }

    // ---------------- epilogue ----------------
    float bv0[8], bv1[8];
#pragma unroll
    for (int ni = 0; ni < 8; ni++) {
        int c = bn + wn + ni * 8 + 2 * (lane & 3);
        bv0[ni] = bias[c];
        bv1[ni] = bias[c + 1];
    }

#pragma unroll
    for (int mi = 0; mi < 2; mi++) {
#pragma unroll
        for (int half = 0; half < 2; half++) {
            int r = bm + wm + mi * 16 + (lane >> 2) + half * 8;
            size_t rowoff = (size_t)r * N;
#pragma unroll
            for (int ni = 0; ni < 8; ni++) {
                int c = bn + wn + ni * 8 + 2 * (lane & 3);
                float v0 = acc[mi][ni][half * 2 + 0] + bv0[ni];
                float v1 = acc[mi][ni][half * 2 + 1] + bv1[ni];
                if (EPI == EPI_GELU) { v0 = gelu_tanh(v0); v1 = gelu_tanh(v1); }
                if (EPI == EPI_MLP2) {
                    float2 rr = *(const float2*)(res + rowoff + c);
                    v0 += rr.x; v1 += rr.y;
                }
                if (OUT_BF16) {
                    __nv_bfloat162 w = __floats2bfloat162_rn(v0, v1);
                    *(__nv_bfloat162*)((__nv_bfloat16*)Cout + rowoff + c) = w;
                } else {
                    float2 w = {v0, v1};
                    *(float2*)((float*)Cout + rowoff + c) = w;
                }
            }
        }
    }
}

// ---------------------------------------------------------------------------
// PROJ + residual + LN2 fused GEMM (unchanged from R10).
// ---------------------------------------------------------------------------
#define PS_AS 40
#define PS_BS 264
#define PS_A_STG (64 * PS_AS)
#define PS_B_STG (32 * PS_BS)
#define PROJ_SMEM ((4 * PS_A_STG + 4 * PS_B_STG) * 2)   // 88064

__global__ void __launch_bounds__(256, 2) gemm_proj_ln(
    const __nv_bfloat16* __restrict__ A,     // attn out (window order)
    const __nv_bfloat16* __restrict__ B,     // proj_w bf16 [k][n]
    const float* __restrict__ bias,
    const float* __restrict__ xres,          // original input x
    const float* __restrict__ gamma,         // norm2_g
    const float* __restrict__ beta,          // norm2_b
    float* __restrict__ x1,
    __nv_bfloat16* __restrict__ h2) {
    extern __shared__ __align__(16) __nv_bfloat16 smp[];
    __nv_bfloat16* Asm = smp;
    __nv_bfloat16* Bsm = smp + 4 * PS_A_STG;

    const int tid  = threadIdx.x;
    const int lane = tid & 31;
    const int wid  = tid >> 5;
    const int bm   = blockIdx.x * 64;
    const int wm   = (wid & 1) * 32;
    const int wn   = (wid >> 1) * 64;
    const int K = 256, N = 256;

    const __nv_bfloat16* Ab = A + (size_t)bm * K;

    float acc[2][8][4] = {};

    auto load_tile = [&](int k0, int stg) {
        __nv_bfloat16* as = Asm + stg * PS_A_STG;
        __nv_bfloat16* bs = Bsm + stg * PS_B_STG;
        {
            int row = tid >> 2, kc = (tid & 3) * 8;      // A: 64x32
            cpasync16(&as[row * PS_AS + kc], Ab + (size_t)row * K + k0 + kc);
        }
#pragma unroll
        for (int i = 0; i < 4; i++) {                    // B: 32x256
            int c = tid + i * 256;
            int k = c >> 5, n = (c & 31) * 8;
            cpasync16(&bs[k * PS_BS + n], B + (size_t)(k0 + k) * N + n);
        }
        cp_commit();
    };

    const int nIter = 8;                                 // K/32
    load_tile(0, 0);
    load_tile(32, 1);
    load_tile(64, 2);

    for (int i = 0; i < nIter; i++) {
        if      (i + 2 < nIter) cp_wait<2>();
        else if (i + 1 < nIter) cp_wait<1>();
        else                    cp_wait<0>();
        __syncthreads();
        if (i + 3 < nIter) load_tile((i + 3) * 32, (i + 3) & 3);

        const __nv_bfloat16* as = Asm + (i & 3) * PS_A_STG;
        const __nv_bfloat16* bs = Bsm + (i & 3) * PS_B_STG;
#pragma unroll
        for (int ks = 0; ks < 32; ks += 16) {
            uint32_t af[2][4];
#pragma unroll
            for (int mi = 0; mi < 2; mi++)
                ldsm4(af[mi], as + (wm + mi * 16 + (lane & 15)) * PS_AS
                                 + ks + (lane >> 4) * 8);
#pragma unroll
            for (int np = 0; np < 4; np++) {
                uint32_t bf[4];
                ldsm4t(bf, bs + (ks + (lane & 7) + ((lane >> 3) & 1) * 8) * PS_BS
                              + wn + np * 16 + (lane >> 4) * 8);
                mma_bf16(acc[0][np * 2 + 0], af[0], bf[0], bf[1]);
                mma_bf16(acc[1][np * 2 + 0], af[1], bf[0], bf[1]);
                mma_bf16(acc[0][np * 2 + 1], af[0], bf[2], bf[3]);
                mma_bf16(acc[1][np * 2 + 1], af[1], bf[2], bf[3]);
            }
        }
    }
    __syncthreads();   // all warps done with pipeline smem before x1 staging

    // ---------------- epilogue: x1 = acc + bias + x, staged in smem ----------
    float* x1s = (float*)smp;        // 64 rows x stride 264 fp32
    const int S = 264;

    float bv0[8], bv1[8];
#pragma unroll
    for (int ni = 0; ni < 8; ni++) {
        int c = wn + ni * 8 + 2 * (lane & 3);
        bv0[ni] = bias[c];
        bv1[ni] = bias[c + 1];
    }

#pragma unroll
    for (int mi = 0; mi < 2; mi++) {
#pragma unroll
        for (int half = 0; half < 2; half++) {
            int row  = wm + mi * 16 + (lane >> 2) + half * 8;   // 0..63
            int xrow = win_to_x_row(bm + row);
            size_t off = (size_t)xrow * 256;
#pragma unroll
            for (int ni = 0; ni < 8; ni++) {
                int c = wn + ni * 8 + 2 * (lane & 3);
                float v0 = acc[mi][ni][half * 2 + 0] + bv0[ni];
                float v1 = acc[mi][ni][half * 2 + 1] + bv1[ni];
                float2 rr = *(const float2*)(xres + off + c);
                v0 += rr.x; v1 += rr.y;
                float2 w = {v0, v1};
                *(float2*)(x1 + off + c)      = w;
                *(float2*)(&x1s[row * S + c]) = w;
            }
        }
    }
    __syncthreads();

    // ---------------- in-block LN2: 8 rows per warp -> h2 bf16 ---------------
    float4 g0 = *(const float4*)(gamma + lane * 8);
    float4 g1 = *(const float4*)(gamma + lane * 8 + 4);
    float4 be0 = *(const float4*)(beta + lane * 8);
    float4 be1 = *(const float4*)(beta + lane * 8 + 4);

#pragma unroll
    for (int rr = 0; rr < 8; rr++) {
        int row = wid * 8 + rr;
        float4 u0 = *(const float4*)(&x1s[row * S + lane * 8]);
        float4 u1 = *(const float4*)(&x1s[row * S + lane * 8 + 4]);

        float s  = u0.x + u0.y + u0.z + u0.w + u1.x + u1.y + u1.z + u1.w;
        float ss = u0.x*u0.x + u0.y*u0.y + u0.z*u0.z + u0.w*u0.w
                 + u1.x*u1.x + u1.y*u1.y + u1.z*u1.z + u1.w*u1.w;
#pragma unroll
        for (int o = 16; o; o >>= 1) {
            s  += __shfl_xor_sync(0xffffffffu, s,  o);
            ss += __shfl_xor_sync(0xffffffffu, ss, o);
        }
        float mu  = s * (1.0f / 256.0f);
        float inv = rsqrtf(ss * (1.0f / 256.0f) - mu * mu + 1e-5f);

        float4 o0, o1;
        o0.x = (u0.x - mu) * inv * g0.x + be0.x;
        o0.y = (u0.y - mu) * inv * g0.y + be0.y;
        o0.z = (u0.z - mu) * inv * g0.z + be0.z;
        o0.w = (u0.w - mu) * inv * g0.w + be0.w;
        o1.x = (u1.x - mu) * inv * g1.x + be1.x;
        o1.y = (u1.y - mu) * inv * g1.y + be1.y;
        o1.z = (u1.z - mu) * inv * g1.z + be1.z;
        o1.w = (u1.w - mu) * inv * g1.w + be1.w;

        int xrow = win_to_x_row(bm + row);
        uint2 p0 = pack4_bf16(o0);
        uint2 p1 = pack4_bf16(o1);
        uint4 pk = make_uint4(p0.x, p0.y, p1.x, p1.y);
        *(uint4*)(h2 + (size_t)xrow * 256 + lane * 8) = pk;
    }
}

// ---------------------------------------------------------------------------
// Tensor-core windowed attention, occupancy-tuned:
//   - NO sQ: Q fragments loaded directly from gmem (exact ldsm.x4 layout,
//     predicated to 0 for pad rows >= 49)
//   - K fragments reloaded per m-tile (not register-hoisted)
//   - sInfo read directly in the softmax loop (no jinfo register array)
// smem ~22.4 KB/block, target ~9-10 blocks/SM (was 7).
// ---------------------------------------------------------------------------
#define ATS 40

__global__ void __launch_bounds__(64) attn_tc(const __nv_bfloat16* __restrict__ qkv,
                                              const float* __restrict__ bias_table,
                                              __nv_bfloat16* __restrict__ out) {
    __shared__ __align__(16) __nv_bfloat16 sK[2][64 * ATS];
    __shared__ __align__(16) __nv_bfloat16 sV[2][64 * ATS];
    __shared__ float sB[2][169];
    __shared__ int   sInfo[64];

    const int w     = blockIdx.x >> 2;
    const int wp    = threadIdx.x >> 5;
    const int lane  = threadIdx.x & 31;
    const int h     = (blockIdx.x & 3) * 2 + wp;
    const int wbase = w * 49;
    const int wi    = w & 63;

    if (threadIdx.x < 64) {
        int j = threadIdx.x;
        int info;
        if (j < 49) {
            int rj = j / 7, cj = j - (j / 7) * 7;
            int gr = (wi >> 3) * 7 + rj;
            int gc = (wi & 7) * 7 + cj;
            int rh = (gr < 49) ? 0 : ((gr < 53) ? 1 : 2);
            int rc = (gc < 49) ? 0 : ((gc < 53) ? 1 : 2);
            int key = rj + 13 * cj;
            info = key | ((rh * 3 + rc) << 8) | (1 << 16);
        } else {
            info = 0 | (255 << 8);
        }
        sInfo[j] = info;
    }

    for (int idx = lane; idx < 169; idx += 32) sB[wp][idx] = bias_table[idx * 8 + h];

    // K/V rows 0..48 from gmem (coalesced 16B chunks)
    for (int tsk = lane; tsk < 196; tsk += 32) {
        int row = tsk >> 2, seg = (tsk & 3) * 8;
        const __nv_bfloat16* base = qkv + (size_t)(wbase + row) * 768 + h * 32 + seg;
        int off = row * ATS + seg;
        *(uint4*)&sK[wp][off] = *(const uint4*)(base + 256);
        *(uint4*)&sV[wp][off] = *(const uint4*)(base + 512);
    }
    // zero pad rows 49..63 (V mandatory: p=0 x NaN guard; K for hygiene)
    for (int z = lane; z < 60; z += 32) {
        int row = 49 + (z >> 2), seg = (z & 3) * 8;
        int off = row * ATS + seg;
        uint4 zz = make_uint4(0, 0, 0, 0);
        *(uint4*)&sK[wp][off] = zz;
        *(uint4*)&sV[wp][off] = zz;
    }
    __syncthreads();

    const int q2 = 2 * (lane & 3);
    const int r = lane >> 2;
    const __nv_bfloat16* qb = qkv + (size_t)wbase * 768 + h * 32;   // row stride 768

#pragma unroll
    for (int mt = 0; mt < 4; mt++) {
        // ---- Q fragments straight from gmem (matches ldsm.x4 layout) ----
        const int r0 = mt * 16 + r;
        const int r1 = r0 + 8;
        const bool v0 = (r0 < 49), v1 = (r1 < 49);
        uint32_t qf[2][4];
#pragma unroll
        for (int ks = 0; ks < 2; ks++) {
            const int cc = q2 + ks * 16;
            qf[ks][0] = v0 ? *(const uint32_t*)(qb + (size_t)r0 * 768 + cc)     : 0u;
            qf[ks][1] = v1 ? *(const uint32_t*)(qb + (size_t)r1 * 768 + cc)     : 0u;
            qf[ks][2] = v0 ? *(const uint32_t*)(qb + (size_t)r0 * 768 + cc + 8) : 0u;
            qf[ks][3] = v1 ? *(const uint32_t*)(qb + (size_t)r1 * 768 + cc + 8) : 0u;
        }

        // ---- S = Q K^T (K frags reloaded per m-tile) ----
        float c[8][4] = {};
#pragma unroll
        for (int nt = 0; nt < 4; nt++) {
#pragma unroll
            for (int ks = 0; ks < 2; ks++) {
                uint32_t kf[4];
                ldsm4(kf, &sK[wp][(nt * 16 + (lane & 7) + ((lane >> 4) & 1) * 8) * ATS
                                  + ks * 16 + ((lane >> 3) & 1) * 8]);
                mma_bf16(c[2 * nt + 0], qf[ks], kf[0], kf[1]);
                mma_bf16(c[2 * nt + 1], qf[ks], kf[2], kf[3]);
            }
        }

        // ---- fused bias + mask + softmax ----
        int infLo = sInfo[r0 < 64 ? r0 : 0], infHi = sInfo[r1 < 64 ? r1 : 0];
        int keyLo = (infLo & 255) + 84, regLo = (infLo >> 8) & 255;
        int keyHi = (infHi & 255) + 84, regHi = (infHi >> 8) & 255;

        float sumLo = 0.0f, sumHi = 0.0f;
#pragma unroll
        for (int u = 0; u < 8; u++) {
#pragma unroll
            for (int e = 0; e < 2; e++) {
                int inf = sInfo[u * 8 + q2 + e];
                float pLo, pHi;
                if (inf & 0x10000) {
                    int kj = inf & 255;
                    int rj = (inf >> 8) & 255;
                    float aLo = fmaf(c[u][e], SCALE_Q, sB[wp][keyLo - kj]);
                    float aHi = fmaf(c[u][2 + e], SCALE_Q, sB[wp][keyHi - kj]);
                    if (rj != regLo) aLo -= 100.0f;
                    if (rj != regHi) aHi -= 100.0f;
                    pLo = __expf(aLo);
                    pHi = __expf(aHi);
                } else {
                    pLo = 0.0f; pHi = 0.0f;
                }
                c[u][e]     = pLo;  sumLo += pLo;
                c[u][2 + e] = pHi;  sumHi += pHi;
            }
        }
        sumLo += __shfl_xor_sync(0xffffffffu, sumLo, 1);
        sumLo += __shfl_xor_sync(0xffffffffu, sumLo, 2);
        sumHi += __shfl_xor_sync(0xffffffffu, sumHi, 1);
        sumHi += __shfl_xor_sync(0xffffffffu, sumHi, 2);
        float dLo = 1.0f / sumLo;
        float dHi = 1.0f / sumHi;

        uint32_t pa[4][4];
#pragma unroll
        for (int t = 0; t < 4; t++) {
            pa[t][0] = pack2_bf16(c[2 * t][0] * dLo,     c[2 * t][1] * dLo);
            pa[t][1] = pack2_bf16(c[2 * t][2] * dHi,     c[2 * t][3] * dHi);
            pa[t][2] = pack2_bf16(c[2 * t + 1][0] * dLo, c[2 * t + 1][1] * dLo);
            pa[t][3] = pack2_bf16(c[2 * t + 1][2] * dHi, c[2 * t + 1][3] * dHi);
        }

        float o[4][4] = {};
#pragma unroll
        for (int ks = 0; ks < 4; ks++) {
            uint32_t vf[2][4];
#pragma unroll
            for (int half = 0; half < 2; half++)
                ldsm4t(vf[half], &sV[wp][(ks * 16 + (lane & 7) + ((lane >> 3) & 1) * 8) * ATS
                                         + half * 16 + (lane >> 4) * 8]);
            mma_bf16(o[0], pa[ks], vf[0][0], vf[0][1]);
            mma_bf16(o[1], pa[ks], vf[0][2], vf[0][3]);
            mma_bf16(o[2], pa[ks], vf[1][0], vf[1][1]);
            mma_bf16(o[3], pa[ks], vf[1][2], vf[1][3]);
        }

        if (r0 < 49) {
            __nv_bfloat16* p = out + (size_t)(wbase + r0) * 256 + h * 32 + q2;
#pragma unroll
            for (int on = 0; on < 4; on++)
                *(uint32_t*)(p + on * 8) = pack2_bf16(o[on][0], o[on][1]);
        }
        if (r1 < 49) {
            __nv_bfloat16* p = out + (size_t)(wbase + r1) * 256 + h * 32 + q2;
#pragma unroll
            for (int on = 0; on < 4; on++)
                *(uint32_t*)(p + on * 8) = pack2_bf16(o[on][2], o[on][3]);
        }
    }
}

// ---------------------------------------------------------------------------
// Host launcher (graph-capturable: kernel launches only)
// ---------------------------------------------------------------------------
extern "C" void kernel_launch(void* const* d_in, const int* in_sizes, int n_in,
                              void* d_out, int out_size) {
    (void)in_sizes; (void)n_in; (void)out_size;

    const float* x          = (const float*)d_in[0];
    const float* n1g        = (const float*)d_in[1];
    const float* n1b        = (const float*)d_in[2];
    const float* qkv_w      = (const float*)d_in[3];
    const float* qkv_b      = (const float*)d_in[4];
    const float* proj_w     = (const float*)d_in[5];
    const float* proj_b     = (const float*)d_in[6];
    const float* bias_table = (const float*)d_in[7];
    const float* n2g        = (const float*)d_in[8];
    const float* n2b        = (const float*)d_in[9];
    const float* w1         = (const float*)d_in[10];
    const float* b1         = (const float*)d_in[11];
    const float* w2         = (const float*)d_in[12];
    const float* b2         = (const float*)d_in[13];
    float* out = (float*)d_out;

    __nv_bfloat16 *ywin, *qkvb, *attnb, *h2, *act, *wbf;
    float *x1;
    cudaGetSymbolAddress((void**)&ywin,  g_ywin);
    cudaGetSymbolAddress((void**)&qkvb,  g_qkv);
    cudaGetSymbolAddress((void**)&attnb, g_attn);
    cudaGetSymbolAddress((void**)&x1,    g_x1);
    cudaGetSymbolAddress((void**)&h2,    g_h2);
    cudaGetSymbolAddress((void**)&act,   g_act);
    cudaGetSymbolAddress((void**)&wbf,   g_wbf);

    cudaFuncSetAttribute(gemm_bf16<EPI_BIAS, true>,
                         cudaFuncAttributeMaxDynamicSharedMemorySize, GEMM_SMEM);
    cudaFuncSetAttribute(gemm_bf16<EPI_GELU, true>,
                         cudaFuncAttributeMaxDynamicSharedMemorySize, GEMM_SMEM);
    cudaFuncSetAttribute(gemm_bf16<EPI_MLP2, false>,
                         cudaFuncAttributeMaxDynamicSharedMemorySize, GEMM_SMEM);
    cudaFuncSetAttribute(gemm_proj_ln,
                         cudaFuncAttributeMaxDynamicSharedMemorySize, PROJ_SMEM);

    const int lnBlocks = NROWS / 8;

    // 0) weights -> bf16
    wconv_kernel<<<768, 1024>>>(qkv_w, proj_w, w1, w2, wbf);
    // 1) LN1 + cyclic shift + window partition -> bf16
    ln_kernel<<<lnBlocks, 256>>>(x, n1g, n1b, ywin);
    // 2) QKV: [100352,256] @ [256,768] -> bf16
    gemm_bf16<EPI_BIAS, true><<<dim3(784, 6), 256, GEMM_SMEM>>>(ywin, wbf + WOFF_QKV,
                                                                qkv_b, qkvb, nullptr, 768, 256);
    // 3) windowed attention (tensor cores) -> bf16
    attn_tc<<<NWIN * 4, 64>>>(qkvb, bias_table, attnb);
    // 4) proj + window-reverse + un-shift + residual + LN2 (fused) -> x1, h2
    gemm_proj_ln<<<1568, 256, PROJ_SMEM>>>(attnb, wbf + WOFF_PROJ, proj_b,
                                           x, n2g, n2b, x1, h2);
    // 5) MLP up + GELU: [100352,256] @ [256,1024] -> bf16
    gemm_bf16<EPI_GELU, true><<<dim3(784, 8), 256, GEMM_SMEM>>>(h2, wbf + WOFF_W1,
                                                                b1, act, nullptr, 1024, 256);
    // 6) MLP down + residual -> d_out (fp32): [100352,1024] @ [1024,256]
    gemm_bf16<EPI_MLP2, false><<<dim3(784, 2), 256, GEMM_SMEM>>>(act, wbf + WOFF_W2,
                                                                 b2, out, x1, 256, 1024);
}